// round 1
// baseline (speedup 1.0000x reference)
#include <cuda_runtime.h>
#include <math.h>

#define BATCH   2
#define SEQLEN  4096
#define DMODEL  2048
#define DINNER  4096
#define NHEADS  32
#define HEADDIM 128
#define DSTATE  64
#define NCHUNK  16
#define CHUNKT  256
#define CONVDIM 4224
#define DINPROJ 8352
#define NROWS   (BATCH*SEQLEN)
#define LN_EPS  1e-5f

// ---------------- scratch (device globals; no allocations allowed) ----------------
__device__ float g_zxbcdt[(size_t)NROWS * DINPROJ];   // in_proj output: z | xBC | dt_raw
__device__ float g_xdt  [(size_t)NROWS * DINNER];     // conv(x)*silu scaled by dt
__device__ float g_Bv   [NROWS * DSTATE];
__device__ float g_Cv   [NROWS * DSTATE];
__device__ float g_dt   [NROWS * NHEADS];
__device__ float g_dA   [NROWS * NHEADS];
__device__ float g_Acum [BATCH * NHEADS * SEQLEN];    // per-chunk inclusive cumsum of dA
__device__ float g_G    [(size_t)BATCH * NCHUNK * CHUNKT * CHUNKT];   // C·B^T per (b,c)
__device__ float g_states[(size_t)BATCH * NCHUNK * NHEADS * HEADDIM * DSTATE];
__device__ float g_prefix[(size_t)BATCH * NCHUNK * NHEADS * HEADDIM * DSTATE];
__device__ float g_y    [(size_t)NROWS * DINNER];
__device__ float g_yn   [(size_t)NROWS * DINNER];

__device__ __forceinline__ float siluf(float x) { return x / (1.f + __expf(-x)); }

// ---------------- generic NT GEMM: C[m,n] = sum_k A[m,k]*B[n,k] + bias[n] ----------------
// A: lda=K, B: ldb=K, C: ldc=N. BM=BN=128, BK=16, 256 threads, 8x8 per thread.
// z-batched via strides (elements). M must be multiple of 128; N guarded.
__global__ void __launch_bounds__(256)
sgemm_nt(const float* __restrict__ A, const float* __restrict__ B,
         const float* __restrict__ bias, float* __restrict__ C,
         int N, int K, long sA, long sB, long sC)
{
    __shared__ float As[16][128];
    __shared__ float Bs[16][128];
    const int tid  = threadIdx.x;
    const int tcol = tid & 15;
    const int trow = tid >> 4;
    const float* Ab = A + (size_t)blockIdx.z * sA + (size_t)blockIdx.y * 128 * K;
    const float* Bb = B + (size_t)blockIdx.z * sB + (size_t)blockIdx.x * 128 * K;
    const int nbase = blockIdx.x * 128;

    float acc[8][8];
#pragma unroll
    for (int m = 0; m < 8; m++)
#pragma unroll
        for (int n = 0; n < 8; n++) acc[m][n] = 0.f;

    const int lrow = tid >> 2;        // 0..63
    const int lcol = (tid & 3) * 4;   // 0,4,8,12

    for (int kt = 0; kt < K; kt += 16) {
#pragma unroll
        for (int it = 0; it < 2; it++) {
            int r = lrow + it * 64;
            float4 va = *(const float4*)(Ab + (size_t)r * K + kt + lcol);
            As[lcol+0][r] = va.x; As[lcol+1][r] = va.y;
            As[lcol+2][r] = va.z; As[lcol+3][r] = va.w;
            float4 vb;
            if (nbase + r < N) vb = *(const float4*)(Bb + (size_t)r * K + kt + lcol);
            else               vb = make_float4(0.f, 0.f, 0.f, 0.f);
            Bs[lcol+0][r] = vb.x; Bs[lcol+1][r] = vb.y;
            Bs[lcol+2][r] = vb.z; Bs[lcol+3][r] = vb.w;
        }
        __syncthreads();
#pragma unroll
        for (int k = 0; k < 16; k++) {
            float ra[8], rb[8];
#pragma unroll
            for (int m = 0; m < 8; m++) ra[m] = As[k][trow * 8 + m];
#pragma unroll
            for (int n = 0; n < 8; n++) rb[n] = Bs[k][tcol * 8 + n];
#pragma unroll
            for (int m = 0; m < 8; m++)
#pragma unroll
                for (int n = 0; n < 8; n++) acc[m][n] = fmaf(ra[m], rb[n], acc[m][n]);
        }
        __syncthreads();
    }

#pragma unroll
    for (int m = 0; m < 8; m++) {
        int row = blockIdx.y * 128 + trow * 8 + m;
#pragma unroll
        for (int n = 0; n < 8; n++) {
            int col = nbase + tcol * 8 + n;
            if (col < N) {
                float bv = bias ? bias[col] : 0.f;
                C[(size_t)blockIdx.z * sC + (size_t)row * N + col] = acc[m][n] + bv;
            }
        }
    }
}

// ---------------- dt: softplus(dt_raw + bias), dA = -exp(A_log)*dt ----------------
__global__ void dt_kernel(const float* __restrict__ dt_bias, const float* __restrict__ A_log)
{
    int idx = blockIdx.x * blockDim.x + threadIdx.x;   // NROWS*NHEADS
    if (idx >= NROWS * NHEADS) return;
    int h = idx & (NHEADS - 1);
    int r = idx >> 5;
    float v = g_zxbcdt[(size_t)r * DINPROJ + DINNER + CONVDIM + h] + dt_bias[h];
    float dt = (v > 20.f) ? v : log1pf(__expf(v));
    g_dt[idx] = dt;
    g_dA[idx] = -__expf(A_log[h]) * dt;
}

// ---------------- causal depthwise conv (width 4) + SiLU; split x*dt / B / C ----------------
__global__ void conv_kernel(const float* __restrict__ w, const float* __restrict__ cb)
{
    long idx = (long)blockIdx.x * blockDim.x + threadIdx.x;
    if (idx >= (long)NROWS * CONVDIM) return;
    int c = (int)(idx % CONVDIM);
    int r = (int)(idx / CONVDIM);
    int l = r & (SEQLEN - 1);
    float acc = cb[c];
#pragma unroll
    for (int k = 0; k < 4; k++) {
        int lp = l - 3 + k;
        if (lp >= 0)
            acc = fmaf(w[c * 4 + k], g_zxbcdt[(size_t)(r - 3 + k) * DINPROJ + DINNER + c], acc);
    }
    float out = siluf(acc);
    if (c < DINNER) {
        g_xdt[(size_t)r * DINNER + c] = out * g_dt[r * NHEADS + (c >> 7)];
    } else if (c < DINNER + DSTATE) {
        g_Bv[r * DSTATE + (c - DINNER)] = out;
    } else {
        g_Cv[r * DSTATE + (c - DINNER - DSTATE)] = out;
    }
}

// ---------------- per-chunk inclusive cumsum of dA ----------------
__global__ void cumsum_kernel()
{
    int c = blockIdx.x, h = blockIdx.y, b = blockIdx.z;
    int t = threadIdx.x;
    __shared__ float s[CHUNKT];
    int row = b * SEQLEN + c * CHUNKT + t;
    s[t] = g_dA[row * NHEADS + h];
    __syncthreads();
#pragma unroll
    for (int off = 1; off < CHUNKT; off <<= 1) {
        float x = (t >= off) ? s[t - off] : 0.f;
        __syncthreads();
        s[t] += x;
        __syncthreads();
    }
    g_Acum[(b * NHEADS + h) * SEQLEN + c * CHUNKT + t] = s[t];
}

// ---------------- chunk-local states: S[p,n] = sum_l X[l,p]*B[l,n]*exp(Atot-Acum_l) ----------------
__global__ void __launch_bounds__(256) states_kernel()
{
    int h = blockIdx.x, c = blockIdx.y, b = blockIdx.z;
    __shared__ float Xs[16][128];
    __shared__ float Bsc[16][64];
    __shared__ float Ac[CHUNKT];
    int tid = threadIdx.x;
    Ac[tid] = g_Acum[(b * NHEADS + h) * SEQLEN + c * CHUNKT + tid];
    __syncthreads();
    float Atot = Ac[CHUNKT - 1];
    int brow = b * SEQLEN + c * CHUNKT;
    int tp = tid >> 3, tn = tid & 7;
    float acc[4][8];
#pragma unroll
    for (int m = 0; m < 4; m++)
#pragma unroll
        for (int n = 0; n < 8; n++) acc[m][n] = 0.f;

    for (int lt = 0; lt < CHUNKT; lt += 16) {
#pragma unroll
        for (int q = 0; q < 8; q++) {
            int idx = tid + q * 256;
            int ll = idx >> 7, p = idx & 127;
            Xs[ll][p] = g_xdt[(size_t)(brow + lt + ll) * DINNER + h * HEADDIM + p];
        }
#pragma unroll
        for (int q = 0; q < 4; q++) {
            int idx = tid + q * 256;
            int ll = idx >> 6, n = idx & 63;
            Bsc[ll][n] = g_Bv[(brow + lt + ll) * DSTATE + n] * __expf(Atot - Ac[lt + ll]);
        }
        __syncthreads();
#pragma unroll
        for (int l = 0; l < 16; l++) {
            float ra[4], rb[8];
#pragma unroll
            for (int m = 0; m < 4; m++) ra[m] = Xs[l][tp * 4 + m];
#pragma unroll
            for (int n = 0; n < 8; n++) rb[n] = Bsc[l][tn * 8 + n];
#pragma unroll
            for (int m = 0; m < 4; m++)
#pragma unroll
                for (int n = 0; n < 8; n++) acc[m][n] = fmaf(ra[m], rb[n], acc[m][n]);
        }
        __syncthreads();
    }
    size_t base = ((size_t)((b * NCHUNK + c) * NHEADS + h)) * HEADDIM * DSTATE;
#pragma unroll
    for (int m = 0; m < 4; m++)
#pragma unroll
        for (int n = 0; n < 8; n++)
            g_states[base + (size_t)(tp * 4 + m) * DSTATE + tn * 8 + n] = acc[m][n];
}

// ---------------- inter-chunk state scan (sequential over 16 chunks per (b,h)) ----------------
__global__ void scan_kernel()
{
    int bh = blockIdx.x;                 // 0..63
    int b = bh >> 5, h = bh & 31;
    int t = threadIdx.x;                 // 256 threads x 32 elems
    float S[32];
#pragma unroll
    for (int i = 0; i < 32; i++) S[i] = 0.f;
    for (int c = 0; c < NCHUNK; c++) {
        size_t base = ((size_t)((b * NCHUNK + c) * NHEADS + h)) * (HEADDIM * DSTATE) + (size_t)t * 32;
#pragma unroll
        for (int i = 0; i < 32; i++) g_prefix[base + i] = S[i];
        float f = __expf(g_Acum[(b * NHEADS + h) * SEQLEN + c * CHUNKT + CHUNKT - 1]);
#pragma unroll
        for (int i = 0; i < 32; i++) S[i] = S[i] * f + g_states[base + i];
    }
}

// ---------------- Y_diag = (exp(Acum_i - Acum_j) * G[i,j] * [j<=i]) @ X ----------------
__global__ void __launch_bounds__(512) ydiag_kernel()
{
    int h = blockIdx.x, c = blockIdx.y, b = blockIdx.z;
    __shared__ float Ss[16][256];
    __shared__ float Xs[16][128];
    __shared__ float Ac[CHUNKT];
    int tid = threadIdx.x;
    if (tid < CHUNKT) Ac[tid] = g_Acum[(b * NHEADS + h) * SEQLEN + c * CHUNKT + tid];
    __syncthreads();
    int brow = b * SEQLEN + c * CHUNKT;
    size_t gbase = (size_t)(b * NCHUNK + c) * CHUNKT * CHUNKT;
    int ti = tid >> 4, tp = tid & 15;
    float acc[8][8];
#pragma unroll
    for (int m = 0; m < 8; m++)
#pragma unroll
        for (int n = 0; n < 8; n++) acc[m][n] = 0.f;

    for (int jt = 0; jt < CHUNKT; jt += 16) {
#pragma unroll
        for (int q = 0; q < 8; q++) {
            int idx = tid + q * 512;
            int jj = idx >> 8, i = idx & 255;
            int j = jt + jj;
            float v = 0.f;
            if (j <= i) v = __expf(Ac[i] - Ac[j]) * g_G[gbase + (size_t)i * 256 + j];
            Ss[jj][i] = v;
        }
#pragma unroll
        for (int q = 0; q < 4; q++) {
            int idx = tid + q * 512;
            int jj = idx >> 7, p = idx & 127;
            Xs[jj][p] = g_xdt[(size_t)(brow + jt + jj) * DINNER + h * HEADDIM + p];
        }
        __syncthreads();
#pragma unroll
        for (int k = 0; k < 16; k++) {
            float ra[8], rb[8];
#pragma unroll
            for (int m = 0; m < 8; m++) ra[m] = Ss[k][ti * 8 + m];
#pragma unroll
            for (int n = 0; n < 8; n++) rb[n] = Xs[k][tp * 8 + n];
#pragma unroll
            for (int m = 0; m < 8; m++)
#pragma unroll
                for (int n = 0; n < 8; n++) acc[m][n] = fmaf(ra[m], rb[n], acc[m][n]);
        }
        __syncthreads();
    }
#pragma unroll
    for (int m = 0; m < 8; m++) {
        int i = ti * 8 + m;
#pragma unroll
        for (int n = 0; n < 8; n++)
            g_y[(size_t)(brow + i) * DINNER + h * HEADDIM + tp * 8 + n] = acc[m][n];
    }
}

// ---------------- Y_off += exp(Acum_i) * C[i,:] @ prefix_state[:,:]^T ----------------
__global__ void __launch_bounds__(512) yoff_kernel()
{
    int h = blockIdx.x, c = blockIdx.y, b = blockIdx.z;
    __shared__ float Cs[16][256];
    __shared__ float St[16][128];
    __shared__ float Ac[CHUNKT];
    int tid = threadIdx.x;
    if (tid < CHUNKT) Ac[tid] = g_Acum[(b * NHEADS + h) * SEQLEN + c * CHUNKT + tid];
    __syncthreads();
    int brow = b * SEQLEN + c * CHUNKT;
    size_t sbase = ((size_t)((b * NCHUNK + c) * NHEADS + h)) * (HEADDIM * DSTATE);
    int ti = tid >> 4, tp = tid & 15;
    float acc[8][8];
#pragma unroll
    for (int m = 0; m < 8; m++)
#pragma unroll
        for (int n = 0; n < 8; n++) acc[m][n] = 0.f;

    for (int kt = 0; kt < DSTATE; kt += 16) {
#pragma unroll
        for (int q = 0; q < 8; q++) {
            int idx = tid + q * 512;
            int nn = idx >> 8, i = idx & 255;
            Cs[nn][i] = g_Cv[(brow + i) * DSTATE + kt + nn];
        }
#pragma unroll
        for (int q = 0; q < 4; q++) {
            int idx = tid + q * 512;
            int nn = idx >> 7, p = idx & 127;
            St[nn][p] = g_prefix[sbase + (size_t)p * DSTATE + kt + nn];
        }
        __syncthreads();
#pragma unroll
        for (int k = 0; k < 16; k++) {
            float ra[8], rb[8];
#pragma unroll
            for (int m = 0; m < 8; m++) ra[m] = Cs[k][ti * 8 + m];
#pragma unroll
            for (int n = 0; n < 8; n++) rb[n] = St[k][tp * 8 + n];
#pragma unroll
            for (int m = 0; m < 8; m++)
#pragma unroll
                for (int n = 0; n < 8; n++) acc[m][n] = fmaf(ra[m], rb[n], acc[m][n]);
        }
        __syncthreads();
    }
#pragma unroll
    for (int m = 0; m < 8; m++) {
        int i = ti * 8 + m;
        float e = __expf(Ac[i]);
#pragma unroll
        for (int n = 0; n < 8; n++) {
            size_t o = (size_t)(brow + i) * DINNER + h * HEADDIM + tp * 8 + n;
            g_y[o] = fmaf(acc[m][n], e, g_y[o]);
        }
    }
}

// ---------------- gating (y * silu(z)) + LayerNorm ----------------
__global__ void __launch_bounds__(256) ln_kernel(const float* __restrict__ lnw, const float* __restrict__ lnb)
{
    int row = blockIdx.x;
    int tid = threadIdx.x;
    float g[16];
    float s = 0.f, s2 = 0.f;
#pragma unroll
    for (int q = 0; q < 16; q++) {
        int i = tid + q * 256;
        float y = g_y[(size_t)row * DINNER + i];
        float z = g_zxbcdt[(size_t)row * DINPROJ + i];
        float v = y * siluf(z);
        g[q] = v; s += v; s2 = fmaf(v, v, s2);
    }
    __shared__ float red[2][8];
#pragma unroll
    for (int off = 16; off > 0; off >>= 1) {
        s  += __shfl_xor_sync(0xffffffffu, s, off);
        s2 += __shfl_xor_sync(0xffffffffu, s2, off);
    }
    if ((tid & 31) == 0) { red[0][tid >> 5] = s; red[1][tid >> 5] = s2; }
    __syncthreads();
    if (tid == 0) {
        float a = 0.f, a2 = 0.f;
#pragma unroll
        for (int w = 0; w < 8; w++) { a += red[0][w]; a2 += red[1][w]; }
        red[0][0] = a; red[1][0] = a2;
    }
    __syncthreads();
    float mu  = red[0][0] * (1.f / DINNER);
    float var = red[1][0] * (1.f / DINNER) - mu * mu;
    float rstd = rsqrtf(var + LN_EPS);
#pragma unroll
    for (int q = 0; q < 16; q++) {
        int i = tid + q * 256;
        g_yn[(size_t)row * DINNER + i] = (g[q] - mu) * rstd * lnw[i] + lnb[i];
    }
}

// ---------------- launch ----------------
extern "C" void kernel_launch(void* const* d_in, const int* in_sizes, int n_in,
                              void* d_out, int out_size)
{
    const float* u          = (const float*)d_in[0];
    const float* in_proj_w  = (const float*)d_in[1];
    const float* in_proj_b  = (const float*)d_in[2];
    const float* conv_w     = (const float*)d_in[3];
    const float* conv_b     = (const float*)d_in[4];
    const float* dt_bias    = (const float*)d_in[5];
    const float* A_log      = (const float*)d_in[6];
    const float* ln_w       = (const float*)d_in[7];
    const float* ln_b       = (const float*)d_in[8];
    const float* out_proj_w = (const float*)d_in[9];
    const float* out_proj_b = (const float*)d_in[10];
    float* out = (float*)d_out;

    float *zx, *yn, *gB, *gC, *gG;
    cudaGetSymbolAddress((void**)&zx, g_zxbcdt);
    cudaGetSymbolAddress((void**)&yn, g_yn);
    cudaGetSymbolAddress((void**)&gB, g_Bv);
    cudaGetSymbolAddress((void**)&gC, g_Cv);
    cudaGetSymbolAddress((void**)&gG, g_G);

    // 1) in_proj: zxbcdt = u @ W^T + b   (M=8192, N=8352, K=2048)
    sgemm_nt<<<dim3((DINPROJ + 127) / 128, NROWS / 128, 1), 256>>>(
        u, in_proj_w, in_proj_b, zx, DINPROJ, DMODEL, 0, 0, 0);

    // 2) dt softplus + dA
    dt_kernel<<<(NROWS * NHEADS) / 256, 256>>>(dt_bias, A_log);

    // 3) causal conv + silu + split (x*dt, B, C)
    {
        long total = (long)NROWS * CONVDIM;
        conv_kernel<<<(unsigned)((total + 255) / 256), 256>>>(conv_w, conv_b);
    }

    // 4) per-chunk cumsum of dA
    cumsum_kernel<<<dim3(NCHUNK, NHEADS, BATCH), CHUNKT>>>();

    // 5) G = C @ B^T per (b,chunk) — shared across heads (ngroups=1)
    sgemm_nt<<<dim3(2, 2, BATCH * NCHUNK), 256>>>(
        gC, gB, nullptr, gG, CHUNKT, DSTATE,
        (long)CHUNKT * DSTATE, (long)CHUNKT * DSTATE, (long)CHUNKT * CHUNKT);

    // 6) chunk-local states
    states_kernel<<<dim3(NHEADS, NCHUNK, BATCH), 256>>>();

    // 7) inter-chunk scan -> prefix states
    scan_kernel<<<BATCH * NHEADS, 256>>>();

    // 8) Y_diag (write) then Y_off (accumulate)
    ydiag_kernel<<<dim3(NHEADS, NCHUNK, BATCH), 512>>>();
    yoff_kernel<<<dim3(NHEADS, NCHUNK, BATCH), 512>>>();

    // 9) gate + layernorm
    ln_kernel<<<NROWS, 256>>>(ln_w, ln_b);

    // 10) out_proj: out = yn @ W^T + b   (M=8192, N=2048, K=4096)
    sgemm_nt<<<dim3(DMODEL / 128, NROWS / 128, 1), 256>>>(
        yn, out_proj_w, out_proj_b, out, DMODEL, DINNER, 0, 0, 0);
}

// round 3
// speedup vs baseline: 1.5707x; 1.5707x over previous
#include <cuda_runtime.h>
#include <cuda_bf16.h>
#include <cstdint>
#include <math.h>

#define BATCH   2
#define SEQLEN  4096
#define DMODEL  2048
#define DINNER  4096
#define NHEADS  32
#define HEADDIM 128
#define DSTATE  64
#define NCHUNK  16
#define CHUNKT  256
#define CONVDIM 4224
#define DINPROJ 8352
#define NROWS   (BATCH*SEQLEN)
#define LN_EPS  1e-5f

// ---------------- scratch (device globals; no allocations allowed) ----------------
__device__ float g_zxbcdt[(size_t)NROWS * DINPROJ];   // in_proj output: z | xBC | dt_raw
__device__ float g_xdt  [(size_t)NROWS * DINNER];     // conv(x)*silu scaled by dt
__device__ float g_Bv   [NROWS * DSTATE];
__device__ float g_Cv   [NROWS * DSTATE];
__device__ float g_dt   [NROWS * NHEADS];
__device__ float g_dA   [NROWS * NHEADS];
__device__ float g_Acum [BATCH * NHEADS * SEQLEN];
__device__ float g_G    [(size_t)BATCH * NCHUNK * CHUNKT * CHUNKT];
__device__ float g_states[(size_t)BATCH * NCHUNK * NHEADS * HEADDIM * DSTATE];
__device__ float g_prefix[(size_t)BATCH * NCHUNK * NHEADS * HEADDIM * DSTATE];
__device__ float g_y    [(size_t)NROWS * DINNER];

// bf16 split buffers for tensor-core GEMMs
__device__ __nv_bfloat16 g_uh [(size_t)NROWS * DMODEL];
__device__ __nv_bfloat16 g_ul [(size_t)NROWS * DMODEL];
__device__ __nv_bfloat16 g_w1h[(size_t)DINPROJ * DMODEL];
__device__ __nv_bfloat16 g_w1l[(size_t)DINPROJ * DMODEL];
__device__ __nv_bfloat16 g_ynh[(size_t)NROWS * DINNER];
__device__ __nv_bfloat16 g_ynl[(size_t)NROWS * DINNER];
__device__ __nv_bfloat16 g_w2h[(size_t)DMODEL * DINNER];
__device__ __nv_bfloat16 g_w2l[(size_t)DMODEL * DINNER];

__device__ __forceinline__ float siluf(float x) { return x / (1.f + __expf(-x)); }

// ================= split fp32 -> bf16 hi/lo =================
__global__ void split_kernel(const float* __restrict__ src,
                             __nv_bfloat16* __restrict__ hi,
                             __nv_bfloat16* __restrict__ lo, long n)
{
    long i = (long)blockIdx.x * blockDim.x + threadIdx.x;
    if (i >= n) return;
    float x = src[i];
    __nv_bfloat16 h = __float2bfloat16(x);
    hi[i] = h;
    lo[i] = __float2bfloat16(x - __bfloat162float(h));
}

// ================= mma.sync helper =================
__device__ __forceinline__ void mma16816(float* c, const uint32_t* a, uint32_t b0, uint32_t b1)
{
    asm volatile(
        "mma.sync.aligned.m16n8k16.row.col.f32.bf16.bf16.f32 "
        "{%0,%1,%2,%3}, {%4,%5,%6,%7}, {%8,%9}, {%0,%1,%2,%3};"
        : "+f"(c[0]), "+f"(c[1]), "+f"(c[2]), "+f"(c[3])
        : "r"(a[0]), "r"(a[1]), "r"(a[2]), "r"(a[3]), "r"(b0), "r"(b1));
}

// ================= split-bf16 tensor-core GEMM: C = A*B^T + bias =================
// A: M x K bf16 hi/lo (M = gridDim.y*128, no row guard), B: N x K hi/lo (guarded),
// C: M x N fp32. BM=BN=128, BK=16, 8 warps (each 32x64), double-buffered smem,
// per-word XOR swizzle (w ^= r&7) -> conflict-free fragment loads.
__global__ void __launch_bounds__(256, 2)
mma_gemm_nt(const __nv_bfloat16* __restrict__ Ah, const __nv_bfloat16* __restrict__ Al,
            const __nv_bfloat16* __restrict__ Bh, const __nv_bfloat16* __restrict__ Bl,
            const float* __restrict__ bias, float* __restrict__ C, int N, int K)
{
    __shared__ __align__(16) uint32_t sA[2][2][128 * 8];  // [stage][hi/lo][r*8 + w]
    __shared__ __align__(16) uint32_t sB[2][2][128 * 8];

    const int tid  = threadIdx.x;
    const int lane = tid & 31;
    const int wid  = tid >> 5;
    const int wr   = wid >> 1;          // 0..3 -> 32-row slab
    const int wc   = wid & 1;           // 0..1 -> 64-col slab
    const int mbase = blockIdx.y * 128;
    const int nbase = blockIdx.x * 128;

    float acc[2][8][4];
#pragma unroll
    for (int mt = 0; mt < 2; mt++)
#pragma unroll
        for (int nt = 0; nt < 8; nt++)
#pragma unroll
            for (int i = 0; i < 4; i++) acc[mt][nt][i] = 0.f;

    // ---- loader assignment: thread -> (row lr, 16B unit lu) of each 128x16 tile ----
    const int lr = tid >> 1;
    const int lu = tid & 1;
    const bool bvalid = (nbase + lr) < N;
    const __nv_bfloat16* pAh = Ah + (size_t)(mbase + lr) * K + lu * 8;
    const __nv_bfloat16* pAl = Al + (size_t)(mbase + lr) * K + lu * 8;
    const __nv_bfloat16* pBh = bvalid ? Bh + (size_t)(nbase + lr) * K + lu * 8 : Bh;
    const __nv_bfloat16* pBl = bvalid ? Bl + (size_t)(nbase + lr) * K + lu * 8 : Bl;
    // precomputed swizzled store word indices (loop-invariant)
    int sw[4];
#pragma unroll
    for (int j = 0; j < 4; j++) sw[j] = lr * 8 + ((lu * 4 + j) ^ (lr & 7));

    // ---- fragment load indices (loop-invariant) ----
    const int cwd = lane & 3;
    int aidx[2][4], bidx[8][2];
#pragma unroll
    for (int mt = 0; mt < 2; mt++) {
        int r  = wr * 32 + mt * 16 + (lane >> 2);
        int r8 = r + 8;
        aidx[mt][0] = r  * 8 + ( cwd      ^ (r  & 7));
        aidx[mt][1] = r8 * 8 + ( cwd      ^ (r8 & 7));
        aidx[mt][2] = r  * 8 + ((cwd + 4) ^ (r  & 7));
        aidx[mt][3] = r8 * 8 + ((cwd + 4) ^ (r8 & 7));
    }
#pragma unroll
    for (int nt = 0; nt < 8; nt++) {
        int n = wc * 64 + nt * 8 + (lane >> 2);
        bidx[nt][0] = n * 8 + ( cwd      ^ (n & 7));
        bidx[nt][1] = n * 8 + ((cwd + 4) ^ (n & 7));
    }

    const int nk = K >> 4;

    // ---- prefetch + store stage 0 ----
    uint4 vah = *(const uint4*)pAh;
    uint4 val = *(const uint4*)pAl;
    uint4 vbh = bvalid ? *(const uint4*)pBh : make_uint4(0,0,0,0);
    uint4 vbl = bvalid ? *(const uint4*)pBl : make_uint4(0,0,0,0);
    {
        uint32_t ah[4] = {vah.x, vah.y, vah.z, vah.w};
        uint32_t al[4] = {val.x, val.y, val.z, val.w};
        uint32_t bh[4] = {vbh.x, vbh.y, vbh.z, vbh.w};
        uint32_t bl[4] = {vbl.x, vbl.y, vbl.z, vbl.w};
#pragma unroll
        for (int j = 0; j < 4; j++) {
            sA[0][0][sw[j]] = ah[j]; sA[0][1][sw[j]] = al[j];
            sB[0][0][sw[j]] = bh[j]; sB[0][1][sw[j]] = bl[j];
        }
    }
    __syncthreads();

    for (int c = 0; c < nk; c++) {
        const int cur = c & 1;
        // prefetch next k-tile
        if (c + 1 < nk) {
            int off = (c + 1) * 16;
            vah = *(const uint4*)(pAh + off);
            val = *(const uint4*)(pAl + off);
            if (bvalid) {
                vbh = *(const uint4*)(pBh + off);
                vbl = *(const uint4*)(pBl + off);
            }
        }
        // A fragments (hi & lo)
        uint32_t afh[2][4], afl[2][4];
#pragma unroll
        for (int mt = 0; mt < 2; mt++)
#pragma unroll
            for (int i = 0; i < 4; i++) {
                afh[mt][i] = sA[cur][0][aidx[mt][i]];
                afl[mt][i] = sA[cur][1][aidx[mt][i]];
            }
#pragma unroll
        for (int nt = 0; nt < 8; nt++) {
            uint32_t bh0 = sB[cur][0][bidx[nt][0]];
            uint32_t bh1 = sB[cur][0][bidx[nt][1]];
            uint32_t bl0 = sB[cur][1][bidx[nt][0]];
            uint32_t bl1 = sB[cur][1][bidx[nt][1]];
#pragma unroll
            for (int mt = 0; mt < 2; mt++) {
                mma16816(acc[mt][nt], afh[mt], bh0, bh1);  // hi*hi
                mma16816(acc[mt][nt], afh[mt], bl0, bl1);  // hi*lo
                mma16816(acc[mt][nt], afl[mt], bh0, bh1);  // lo*hi
            }
        }
        // store next stage
        if (c + 1 < nk) {
            int nxt = cur ^ 1;
            uint32_t ah[4] = {vah.x, vah.y, vah.z, vah.w};
            uint32_t al[4] = {val.x, val.y, val.z, val.w};
            uint32_t bh[4] = {vbh.x, vbh.y, vbh.z, vbh.w};
            uint32_t bl[4] = {vbl.x, vbl.y, vbl.z, vbl.w};
#pragma unroll
            for (int j = 0; j < 4; j++) {
                sA[nxt][0][sw[j]] = ah[j]; sA[nxt][1][sw[j]] = al[j];
                sB[nxt][0][sw[j]] = bh[j]; sB[nxt][1][sw[j]] = bl[j];
            }
        }
        __syncthreads();
    }

    // ---- epilogue ----
#pragma unroll
    for (int mt = 0; mt < 2; mt++) {
        int r0 = mbase + wr * 32 + mt * 16 + (lane >> 2);
#pragma unroll
        for (int nt = 0; nt < 8; nt++) {
            int col = nbase + wc * 64 + nt * 8 + (lane & 3) * 2;
            if (col < N) {
                float b0 = bias[col], b1 = bias[col + 1];
                float2 v0 = make_float2(acc[mt][nt][0] + b0, acc[mt][nt][1] + b1);
                float2 v1 = make_float2(acc[mt][nt][2] + b0, acc[mt][nt][3] + b1);
                *(float2*)(C + (size_t)r0 * N + col)       = v0;
                *(float2*)(C + (size_t)(r0 + 8) * N + col) = v1;
            }
        }
    }
}

// ---------------- small fp32 NT GEMM (kept for G = C @ B^T) ----------------
__global__ void __launch_bounds__(256)
sgemm_nt(const float* __restrict__ A, const float* __restrict__ B,
         const float* __restrict__ bias, float* __restrict__ C,
         int N, int K, long sA, long sB, long sC)
{
    __shared__ float As[16][128];
    __shared__ float Bs[16][128];
    const int tid  = threadIdx.x;
    const int tcol = tid & 15;
    const int trow = tid >> 4;
    const float* Ab = A + (size_t)blockIdx.z * sA + (size_t)blockIdx.y * 128 * K;
    const float* Bb = B + (size_t)blockIdx.z * sB + (size_t)blockIdx.x * 128 * K;
    const int nbase = blockIdx.x * 128;

    float acc[8][8];
#pragma unroll
    for (int m = 0; m < 8; m++)
#pragma unroll
        for (int n = 0; n < 8; n++) acc[m][n] = 0.f;

    const int lrow = tid >> 2;
    const int lcol = (tid & 3) * 4;

    for (int kt = 0; kt < K; kt += 16) {
#pragma unroll
        for (int it = 0; it < 2; it++) {
            int r = lrow + it * 64;
            float4 va = *(const float4*)(Ab + (size_t)r * K + kt + lcol);
            As[lcol+0][r] = va.x; As[lcol+1][r] = va.y;
            As[lcol+2][r] = va.z; As[lcol+3][r] = va.w;
            float4 vb;
            if (nbase + r < N) vb = *(const float4*)(Bb + (size_t)r * K + kt + lcol);
            else               vb = make_float4(0.f, 0.f, 0.f, 0.f);
            Bs[lcol+0][r] = vb.x; Bs[lcol+1][r] = vb.y;
            Bs[lcol+2][r] = vb.z; Bs[lcol+3][r] = vb.w;
        }
        __syncthreads();
#pragma unroll
        for (int k = 0; k < 16; k++) {
            float ra[8], rb[8];
#pragma unroll
            for (int m = 0; m < 8; m++) ra[m] = As[k][trow * 8 + m];
#pragma unroll
            for (int n = 0; n < 8; n++) rb[n] = Bs[k][tcol * 8 + n];
#pragma unroll
            for (int m = 0; m < 8; m++)
#pragma unroll
                for (int n = 0; n < 8; n++) acc[m][n] = fmaf(ra[m], rb[n], acc[m][n]);
        }
        __syncthreads();
    }
#pragma unroll
    for (int m = 0; m < 8; m++) {
        int row = blockIdx.y * 128 + trow * 8 + m;
#pragma unroll
        for (int n = 0; n < 8; n++) {
            int col = nbase + tcol * 8 + n;
            if (col < N) {
                float bv = bias ? bias[col] : 0.f;
                C[(size_t)blockIdx.z * sC + (size_t)row * N + col] = acc[m][n] + bv;
            }
        }
    }
}

// ---------------- dt: softplus(dt_raw + bias), dA = -exp(A_log)*dt ----------------
__global__ void dt_kernel(const float* __restrict__ dt_bias, const float* __restrict__ A_log)
{
    int idx = blockIdx.x * blockDim.x + threadIdx.x;
    if (idx >= NROWS * NHEADS) return;
    int h = idx & (NHEADS - 1);
    int r = idx >> 5;
    float v = g_zxbcdt[(size_t)r * DINPROJ + DINNER + CONVDIM + h] + dt_bias[h];
    float dt = (v > 20.f) ? v : log1pf(__expf(v));
    g_dt[idx] = dt;
    g_dA[idx] = -__expf(A_log[h]) * dt;
}

// ---------------- causal depthwise conv (width 4) + SiLU; split x*dt / B / C ----------------
__global__ void conv_kernel(const float* __restrict__ w, const float* __restrict__ cb)
{
    long idx = (long)blockIdx.x * blockDim.x + threadIdx.x;
    if (idx >= (long)NROWS * CONVDIM) return;
    int c = (int)(idx % CONVDIM);
    int r = (int)(idx / CONVDIM);
    int l = r & (SEQLEN - 1);
    float acc = cb[c];
#pragma unroll
    for (int k = 0; k < 4; k++) {
        int lp = l - 3 + k;
        if (lp >= 0)
            acc = fmaf(w[c * 4 + k], g_zxbcdt[(size_t)(r - 3 + k) * DINPROJ + DINNER + c], acc);
    }
    float out = siluf(acc);
    if (c < DINNER) {
        g_xdt[(size_t)r * DINNER + c] = out * g_dt[r * NHEADS + (c >> 7)];
    } else if (c < DINNER + DSTATE) {
        g_Bv[r * DSTATE + (c - DINNER)] = out;
    } else {
        g_Cv[r * DSTATE + (c - DINNER - DSTATE)] = out;
    }
}

// ---------------- per-chunk inclusive cumsum of dA ----------------
__global__ void cumsum_kernel()
{
    int c = blockIdx.x, h = blockIdx.y, b = blockIdx.z;
    int t = threadIdx.x;
    __shared__ float s[CHUNKT];
    int row = b * SEQLEN + c * CHUNKT + t;
    s[t] = g_dA[row * NHEADS + h];
    __syncthreads();
#pragma unroll
    for (int off = 1; off < CHUNKT; off <<= 1) {
        float x = (t >= off) ? s[t - off] : 0.f;
        __syncthreads();
        s[t] += x;
        __syncthreads();
    }
    g_Acum[(b * NHEADS + h) * SEQLEN + c * CHUNKT + t] = s[t];
}

// ---------------- chunk-local states ----------------
__global__ void __launch_bounds__(256) states_kernel()
{
    int h = blockIdx.x, c = blockIdx.y, b = blockIdx.z;
    __shared__ float Xs[16][128];
    __shared__ float Bsc[16][64];
    __shared__ float Ac[CHUNKT];
    int tid = threadIdx.x;
    Ac[tid] = g_Acum[(b * NHEADS + h) * SEQLEN + c * CHUNKT + tid];
    __syncthreads();
    float Atot = Ac[CHUNKT - 1];
    int brow = b * SEQLEN + c * CHUNKT;
    int tp = tid >> 3, tn = tid & 7;
    float acc[4][8];
#pragma unroll
    for (int m = 0; m < 4; m++)
#pragma unroll
        for (int n = 0; n < 8; n++) acc[m][n] = 0.f;

    for (int lt = 0; lt < CHUNKT; lt += 16) {
#pragma unroll
        for (int q = 0; q < 8; q++) {
            int idx = tid + q * 256;
            int ll = idx >> 7, p = idx & 127;
            Xs[ll][p] = g_xdt[(size_t)(brow + lt + ll) * DINNER + h * HEADDIM + p];
        }
#pragma unroll
        for (int q = 0; q < 4; q++) {
            int idx = tid + q * 256;
            int ll = idx >> 6, n = idx & 63;
            Bsc[ll][n] = g_Bv[(brow + lt + ll) * DSTATE + n] * __expf(Atot - Ac[lt + ll]);
        }
        __syncthreads();
#pragma unroll
        for (int l = 0; l < 16; l++) {
            float ra[4], rb[8];
#pragma unroll
            for (int m = 0; m < 4; m++) ra[m] = Xs[l][tp * 4 + m];
#pragma unroll
            for (int n = 0; n < 8; n++) rb[n] = Bsc[l][tn * 8 + n];
#pragma unroll
            for (int m = 0; m < 4; m++)
#pragma unroll
                for (int n = 0; n < 8; n++) acc[m][n] = fmaf(ra[m], rb[n], acc[m][n]);
        }
        __syncthreads();
    }
    size_t base = ((size_t)((b * NCHUNK + c) * NHEADS + h)) * HEADDIM * DSTATE;
#pragma unroll
    for (int m = 0; m < 4; m++)
#pragma unroll
        for (int n = 0; n < 8; n++)
            g_states[base + (size_t)(tp * 4 + m) * DSTATE + tn * 8 + n] = acc[m][n];
}

// ---------------- inter-chunk state scan ----------------
__global__ void scan_kernel()
{
    int bh = blockIdx.x;
    int b = bh >> 5, h = bh & 31;
    int t = threadIdx.x;
    float S[32];
#pragma unroll
    for (int i = 0; i < 32; i++) S[i] = 0.f;
    for (int c = 0; c < NCHUNK; c++) {
        size_t base = ((size_t)((b * NCHUNK + c) * NHEADS + h)) * (HEADDIM * DSTATE) + (size_t)t * 32;
#pragma unroll
        for (int i = 0; i < 32; i++) g_prefix[base + i] = S[i];
        float f = __expf(g_Acum[(b * NHEADS + h) * SEQLEN + c * CHUNKT + CHUNKT - 1]);
#pragma unroll
        for (int i = 0; i < 32; i++) S[i] = S[i] * f + g_states[base + i];
    }
}

// ---------------- Y_diag ----------------
__global__ void __launch_bounds__(512) ydiag_kernel()
{
    int h = blockIdx.x, c = blockIdx.y, b = blockIdx.z;
    __shared__ float Ss[16][256];
    __shared__ float Xs[16][128];
    __shared__ float Ac[CHUNKT];
    int tid = threadIdx.x;
    if (tid < CHUNKT) Ac[tid] = g_Acum[(b * NHEADS + h) * SEQLEN + c * CHUNKT + tid];
    __syncthreads();
    int brow = b * SEQLEN + c * CHUNKT;
    size_t gbase = (size_t)(b * NCHUNK + c) * CHUNKT * CHUNKT;
    int ti = tid >> 4, tp = tid & 15;
    float acc[8][8];
#pragma unroll
    for (int m = 0; m < 8; m++)
#pragma unroll
        for (int n = 0; n < 8; n++) acc[m][n] = 0.f;

    for (int jt = 0; jt < CHUNKT; jt += 16) {
#pragma unroll
        for (int q = 0; q < 8; q++) {
            int idx = tid + q * 512;
            int jj = idx >> 8, i = idx & 255;
            int j = jt + jj;
            float v = 0.f;
            if (j <= i) v = __expf(Ac[i] - Ac[j]) * g_G[gbase + (size_t)i * 256 + j];
            Ss[jj][i] = v;
        }
#pragma unroll
        for (int q = 0; q < 4; q++) {
            int idx = tid + q * 512;
            int jj = idx >> 7, p = idx & 127;
            Xs[jj][p] = g_xdt[(size_t)(brow + jt + jj) * DINNER + h * HEADDIM + p];
        }
        __syncthreads();
#pragma unroll
        for (int k = 0; k < 16; k++) {
            float ra[8], rb[8];
#pragma unroll
            for (int m = 0; m < 8; m++) ra[m] = Ss[k][ti * 8 + m];
#pragma unroll
            for (int n = 0; n < 8; n++) rb[n] = Xs[k][tp * 8 + n];
#pragma unroll
            for (int m = 0; m < 8; m++)
#pragma unroll
                for (int n = 0; n < 8; n++) acc[m][n] = fmaf(ra[m], rb[n], acc[m][n]);
        }
        __syncthreads();
    }
#pragma unroll
    for (int m = 0; m < 8; m++) {
        int i = ti * 8 + m;
#pragma unroll
        for (int n = 0; n < 8; n++)
            g_y[(size_t)(brow + i) * DINNER + h * HEADDIM + tp * 8 + n] = acc[m][n];
    }
}

// ---------------- Y_off ----------------
__global__ void __launch_bounds__(512) yoff_kernel()
{
    int h = blockIdx.x, c = blockIdx.y, b = blockIdx.z;
    __shared__ float Cs[16][256];
    __shared__ float St[16][128];
    __shared__ float Ac[CHUNKT];
    int tid = threadIdx.x;
    if (tid < CHUNKT) Ac[tid] = g_Acum[(b * NHEADS + h) * SEQLEN + c * CHUNKT + tid];
    __syncthreads();
    int brow = b * SEQLEN + c * CHUNKT;
    size_t sbase = ((size_t)((b * NCHUNK + c) * NHEADS + h)) * (HEADDIM * DSTATE);
    int ti = tid >> 4, tp = tid & 15;
    float acc[8][8];
#pragma unroll
    for (int m = 0; m < 8; m++)
#pragma unroll
        for (int n = 0; n < 8; n++) acc[m][n] = 0.f;

    for (int kt = 0; kt < DSTATE; kt += 16) {
#pragma unroll
        for (int q = 0; q < 8; q++) {
            int idx = tid + q * 512;
            int nn = idx >> 8, i = idx & 255;
            Cs[nn][i] = g_Cv[(brow + i) * DSTATE + kt + nn];
        }
#pragma unroll
        for (int q = 0; q < 4; q++) {
            int idx = tid + q * 512;
            int nn = idx >> 7, p = idx & 127;
            St[nn][p] = g_prefix[sbase + (size_t)p * DSTATE + kt + nn];
        }
        __syncthreads();
#pragma unroll
        for (int k = 0; k < 16; k++) {
            float ra[8], rb[8];
#pragma unroll
            for (int m = 0; m < 8; m++) ra[m] = Cs[k][ti * 8 + m];
#pragma unroll
            for (int n = 0; n < 8; n++) rb[n] = St[k][tp * 8 + n];
#pragma unroll
            for (int m = 0; m < 8; m++)
#pragma unroll
                for (int n = 0; n < 8; n++) acc[m][n] = fmaf(ra[m], rb[n], acc[m][n]);
        }
        __syncthreads();
    }
#pragma unroll
    for (int m = 0; m < 8; m++) {
        int i = ti * 8 + m;
        float e = __expf(Ac[i]);
#pragma unroll
        for (int n = 0; n < 8; n++) {
            size_t o = (size_t)(brow + i) * DINNER + h * HEADDIM + tp * 8 + n;
            g_y[o] = fmaf(acc[m][n], e, g_y[o]);
        }
    }
}

// ---------------- gating (y * silu(z)) + LayerNorm; emits bf16 hi/lo ----------------
__global__ void __launch_bounds__(256) ln_kernel(const float* __restrict__ lnw, const float* __restrict__ lnb)
{
    int row = blockIdx.x;
    int tid = threadIdx.x;
    float g[16];
    float s = 0.f, s2 = 0.f;
#pragma unroll
    for (int q = 0; q < 16; q++) {
        int i = tid + q * 256;
        float y = g_y[(size_t)row * DINNER + i];
        float z = g_zxbcdt[(size_t)row * DINPROJ + i];
        float v = y * siluf(z);
        g[q] = v; s += v; s2 = fmaf(v, v, s2);
    }
    __shared__ float red[2][8];
#pragma unroll
    for (int off = 16; off > 0; off >>= 1) {
        s  += __shfl_xor_sync(0xffffffffu, s, off);
        s2 += __shfl_xor_sync(0xffffffffu, s2, off);
    }
    if ((tid & 31) == 0) { red[0][tid >> 5] = s; red[1][tid >> 5] = s2; }
    __syncthreads();
    if (tid == 0) {
        float a = 0.f, a2 = 0.f;
#pragma unroll
        for (int w = 0; w < 8; w++) { a += red[0][w]; a2 += red[1][w]; }
        red[0][0] = a; red[1][0] = a2;
    }
    __syncthreads();
    float mu  = red[0][0] * (1.f / DINNER);
    float var = red[1][0] * (1.f / DINNER) - mu * mu;
    float rstd = rsqrtf(var + LN_EPS);
#pragma unroll
    for (int q = 0; q < 16; q++) {
        int i = tid + q * 256;
        float v = (g[q] - mu) * rstd * lnw[i] + lnb[i];
        __nv_bfloat16 h = __float2bfloat16(v);
        g_ynh[(size_t)row * DINNER + i] = h;
        g_ynl[(size_t)row * DINNER + i] = __float2bfloat16(v - __bfloat162float(h));
    }
}

// ---------------- launch ----------------
extern "C" void kernel_launch(void* const* d_in, const int* in_sizes, int n_in,
                              void* d_out, int out_size)
{
    const float* u          = (const float*)d_in[0];
    const float* in_proj_w  = (const float*)d_in[1];
    const float* in_proj_b  = (const float*)d_in[2];
    const float* conv_w     = (const float*)d_in[3];
    const float* conv_b     = (const float*)d_in[4];
    const float* dt_bias    = (const float*)d_in[5];
    const float* A_log      = (const float*)d_in[6];
    const float* ln_w       = (const float*)d_in[7];
    const float* ln_b       = (const float*)d_in[8];
    const float* out_proj_w = (const float*)d_in[9];
    const float* out_proj_b = (const float*)d_in[10];
    float* out = (float*)d_out;

    float *zx, *gB, *gC, *gG;
    __nv_bfloat16 *uh, *ul, *w1h, *w1l, *ynh, *ynl, *w2h, *w2l;
    cudaGetSymbolAddress((void**)&zx,  g_zxbcdt);
    cudaGetSymbolAddress((void**)&gB,  g_Bv);
    cudaGetSymbolAddress((void**)&gC,  g_Cv);
    cudaGetSymbolAddress((void**)&gG,  g_G);
    cudaGetSymbolAddress((void**)&uh,  g_uh);
    cudaGetSymbolAddress((void**)&ul,  g_ul);
    cudaGetSymbolAddress((void**)&w1h, g_w1h);
    cudaGetSymbolAddress((void**)&w1l, g_w1l);
    cudaGetSymbolAddress((void**)&ynh, g_ynh);
    cudaGetSymbolAddress((void**)&ynl, g_ynl);
    cudaGetSymbolAddress((void**)&w2h, g_w2h);
    cudaGetSymbolAddress((void**)&w2l, g_w2l);

    // 0) fp32 -> bf16 hi/lo splits
    {
        long n1 = (long)NROWS * DMODEL;
        split_kernel<<<(unsigned)((n1 + 255) / 256), 256>>>(u, uh, ul, n1);
        long n2 = (long)DINPROJ * DMODEL;
        split_kernel<<<(unsigned)((n2 + 255) / 256), 256>>>(in_proj_w, w1h, w1l, n2);
        long n3 = (long)DMODEL * DINNER;
        split_kernel<<<(unsigned)((n3 + 255) / 256), 256>>>(out_proj_w, w2h, w2l, n3);
    }

    // 1) in_proj on tensor cores: M=8192, N=8352, K=2048
    mma_gemm_nt<<<dim3((DINPROJ + 127) / 128, NROWS / 128), 256>>>(
        uh, ul, w1h, w1l, in_proj_b, zx, DINPROJ, DMODEL);

    // 2) dt softplus + dA
    dt_kernel<<<(NROWS * NHEADS) / 256, 256>>>(dt_bias, A_log);

    // 3) causal conv + silu + split (x*dt, B, C)
    {
        long total = (long)NROWS * CONVDIM;
        conv_kernel<<<(unsigned)((total + 255) / 256), 256>>>(conv_w, conv_b);
    }

    // 4) per-chunk cumsum of dA
    cumsum_kernel<<<dim3(NCHUNK, NHEADS, BATCH), CHUNKT>>>();

    // 5) G = C @ B^T per (b,chunk)
    sgemm_nt<<<dim3(2, 2, BATCH * NCHUNK), 256>>>(
        gC, gB, nullptr, gG, CHUNKT, DSTATE,
        (long)CHUNKT * DSTATE, (long)CHUNKT * DSTATE, (long)CHUNKT * CHUNKT);

    // 6) chunk-local states
    states_kernel<<<dim3(NHEADS, NCHUNK, BATCH), 256>>>();

    // 7) inter-chunk scan
    scan_kernel<<<BATCH * NHEADS, 256>>>();

    // 8) Y_diag then Y_off
    ydiag_kernel<<<dim3(NHEADS, NCHUNK, BATCH), 512>>>();
    yoff_kernel<<<dim3(NHEADS, NCHUNK, BATCH), 512>>>();

    // 9) gate + layernorm (+ bf16 split of yn)
    ln_kernel<<<NROWS, 256>>>(ln_w, ln_b);

    // 10) out_proj on tensor cores: M=8192, N=2048, K=4096
    mma_gemm_nt<<<dim3(DMODEL / 128, NROWS / 128), 256>>>(
        ynh, ynl, w2h, w2l, out_proj_b, out, DMODEL, DINNER);
}

// round 4
// speedup vs baseline: 2.1930x; 1.3962x over previous
#include <cuda_runtime.h>
#include <cuda_bf16.h>
#include <cstdint>
#include <math.h>

#define BATCH   2
#define SEQLEN  4096
#define DMODEL  2048
#define DINNER  4096
#define NHEADS  32
#define HEADDIM 128
#define DSTATE  64
#define NCHUNK  16
#define CHUNKT  256
#define CONVDIM 4224
#define DINPROJ 8352
#define NROWS   (BATCH*SEQLEN)
#define LN_EPS  1e-5f

// ---------------- scratch (device globals; no allocations allowed) ----------------
__device__ float g_zxbcdt[(size_t)NROWS * DINPROJ];   // in_proj output: z | xBC | dt_raw
__device__ float g_xdt  [(size_t)NROWS * DINNER];     // conv(x)*silu scaled by dt
__device__ float g_Bv   [NROWS * DSTATE];
__device__ float g_Cv   [NROWS * DSTATE];
__device__ float g_dt   [NROWS * NHEADS];
__device__ float g_dA   [NROWS * NHEADS];
__device__ float g_Acum [BATCH * NHEADS * SEQLEN];
__device__ float g_G    [(size_t)BATCH * NCHUNK * CHUNKT * CHUNKT];
__device__ float g_states[(size_t)BATCH * NCHUNK * NHEADS * HEADDIM * DSTATE];
__device__ float g_prefix[(size_t)BATCH * NCHUNK * NHEADS * HEADDIM * DSTATE];
__device__ float g_y    [(size_t)NROWS * DINNER];

// bf16 split buffers for tensor-core GEMMs
__device__ __nv_bfloat16 g_uh [(size_t)NROWS * DMODEL];
__device__ __nv_bfloat16 g_ul [(size_t)NROWS * DMODEL];
__device__ __nv_bfloat16 g_w1h[(size_t)DINPROJ * DMODEL];
__device__ __nv_bfloat16 g_w1l[(size_t)DINPROJ * DMODEL];
__device__ __nv_bfloat16 g_ynh[(size_t)NROWS * DINNER];
__device__ __nv_bfloat16 g_ynl[(size_t)NROWS * DINNER];
__device__ __nv_bfloat16 g_w2h[(size_t)DMODEL * DINNER];
__device__ __nv_bfloat16 g_w2l[(size_t)DMODEL * DINNER];

__device__ __forceinline__ float siluf(float x) { return x / (1.f + __expf(-x)); }

__device__ __forceinline__ uint32_t smem_u32(const void* p) {
    uint32_t a;
    asm("{ .reg .u64 t; cvta.to.shared.u64 t, %1; cvt.u32.u64 %0, t; }" : "=r"(a) : "l"(p));
    return a;
}

// ================= split fp32 -> bf16 hi/lo =================
__global__ void split_kernel(const float* __restrict__ src,
                             __nv_bfloat16* __restrict__ hi,
                             __nv_bfloat16* __restrict__ lo, long n)
{
    long i = (long)blockIdx.x * blockDim.x + threadIdx.x;
    if (i >= n) return;
    float x = src[i];
    __nv_bfloat16 h = __float2bfloat16(x);
    hi[i] = h;
    lo[i] = __float2bfloat16(x - __bfloat162float(h));
}

// ================= tensor-core primitives =================
__device__ __forceinline__ void mma16816(float* c, const uint32_t* a, uint32_t b0, uint32_t b1)
{
    asm volatile(
        "mma.sync.aligned.m16n8k16.row.col.f32.bf16.bf16.f32 "
        "{%0,%1,%2,%3}, {%4,%5,%6,%7}, {%8,%9}, {%0,%1,%2,%3};"
        : "+f"(c[0]), "+f"(c[1]), "+f"(c[2]), "+f"(c[3])
        : "r"(a[0]), "r"(a[1]), "r"(a[2]), "r"(a[3]), "r"(b0), "r"(b1));
}
#define LDSM_X4(r0, r1, r2, r3, addr) \
    asm volatile("ldmatrix.sync.aligned.m8n8.x4.shared.b16 {%0,%1,%2,%3}, [%4];" \
                 : "=r"(r0), "=r"(r1), "=r"(r2), "=r"(r3) : "r"(addr))
#define CP16(dst, src, sz) \
    asm volatile("cp.async.cg.shared.global [%0], [%1], 16, %2;" \
                 :: "r"(dst), "l"(src), "r"(sz))
#define CP_COMMIT() asm volatile("cp.async.commit_group;" ::: "memory")
#define CP_WAIT1()  asm volatile("cp.async.wait_group 1;" ::: "memory")
#define CP_WAIT0()  asm volatile("cp.async.wait_group 0;" ::: "memory")

// ================= split-bf16 tensor-core GEMM: C = A*B^T + bias =================
// BM=256, BN=128, BK=64 (128B rows, SW128 swizzle), 512 threads (16 warps, each 64x32).
// 2-stage cp.async pipeline; fragments via ldmatrix.x4; 3-product split accumulation.
// A: M x K hi/lo (M multiple of 256), B: N x K hi/lo (row-guarded), C: M x N fp32.
#define GSTAGE 98304
__global__ void __launch_bounds__(512, 1)
mma_gemm_nt(const __nv_bfloat16* __restrict__ Ah, const __nv_bfloat16* __restrict__ Al,
            const __nv_bfloat16* __restrict__ Bh, const __nv_bfloat16* __restrict__ Bl,
            const float* __restrict__ bias, float* __restrict__ C, int N, int K)
{
    extern __shared__ char smem[];
    const uint32_t sb = smem_u32(smem);
    const int tid = threadIdx.x, lane = tid & 31, wid = tid >> 5;
    const int wr = wid >> 2, wc = wid & 3;            // 4x4 warp grid
    const int mbase = blockIdx.y * 256;
    const int nbase = blockIdx.x * 128;

    // ---- loader assignment ----
    const int rA = tid >> 1, uA0 = (tid & 1) * 4;     // A: 2 thr/row, 4 units each
    const int rB = tid >> 2, uB0 = (tid & 3) * 2;     // B: 4 thr/row, 2 units each
    const bool bval = (nbase + rB) < N;
    const uint32_t bsz = bval ? 16u : 0u;
    const __nv_bfloat16* gAh = Ah + (size_t)(mbase + rA) * K + uA0 * 8;
    const __nv_bfloat16* gAl = Al + (size_t)(mbase + rA) * K + uA0 * 8;
    const __nv_bfloat16* gBh = Bh + (size_t)(bval ? nbase + rB : 0) * K + uB0 * 8;
    const __nv_bfloat16* gBl = Bl + (size_t)(bval ? nbase + rB : 0) * K + uB0 * 8;
    uint32_t dA[4], dB[2];
#pragma unroll
    for (int j = 0; j < 4; j++) dA[j] = rA * 128 + (((uA0 + j) ^ (rA & 7)) * 16);
#pragma unroll
    for (int j = 0; j < 2; j++) dB[j] = rB * 128 + (((uB0 + j) ^ (rB & 7)) * 16);

    auto issue = [&](int st, int kt) {
        uint32_t s0 = sb + st * GSTAGE;
#pragma unroll
        for (int j = 0; j < 4; j++) {
            CP16(s0 + dA[j],         gAh + kt + j * 8, 16);
            CP16(s0 + 32768 + dA[j], gAl + kt + j * 8, 16);
        }
#pragma unroll
        for (int j = 0; j < 2; j++) {
            CP16(s0 + 65536 + dB[j], gBh + kt + j * 8, bsz);
            CP16(s0 + 81920 + dB[j], gBl + kt + j * 8, bsz);
        }
        CP_COMMIT();
    };

    float acc[4][4][4];
#pragma unroll
    for (int mt = 0; mt < 4; mt++)
#pragma unroll
        for (int nt = 0; nt < 4; nt++)
#pragma unroll
            for (int i = 0; i < 4; i++) acc[mt][nt][i] = 0.f;

    const int nk = K >> 6;
    issue(0, 0);
    issue(1, 64);

    // ldmatrix lane decomposition
    const int g = lane >> 3, li = lane & 7;
    const int arow_lo = (g & 1) * 8 + li;   // A: row-within-16 tile
    const int ahalf   = g >> 1;             // A: k-half
    const int brow_lo = (g >> 1) * 8 + li;  // B: row-within-16 (nt pair)
    const int bhalf   = g & 1;              // B: k-half

    for (int c = 0; c < nk; c++) {
        if (c + 1 < nk) CP_WAIT1(); else CP_WAIT0();
        __syncthreads();

        const uint32_t s0 = sb + (c & 1) * GSTAGE;
#pragma unroll
        for (int s = 0; s < 4; s++) {
            uint32_t afh[4][4], afl[4][4];
#pragma unroll
            for (int mt = 0; mt < 4; mt++) {
                int row = wr * 64 + mt * 16 + arow_lo;
                uint32_t off = row * 128 + (((2 * s + ahalf) ^ (row & 7)) * 16);
                LDSM_X4(afh[mt][0], afh[mt][1], afh[mt][2], afh[mt][3], s0 + off);
                LDSM_X4(afl[mt][0], afl[mt][1], afl[mt][2], afl[mt][3], s0 + 32768 + off);
            }
#pragma unroll
            for (int ntp = 0; ntp < 2; ntp++) {
                int row = wc * 32 + ntp * 16 + brow_lo;
                uint32_t off = row * 128 + (((2 * s + bhalf) ^ (row & 7)) * 16);
                uint32_t bh0, bh1, bh2, bh3, bl0, bl1, bl2, bl3;
                LDSM_X4(bh0, bh1, bh2, bh3, s0 + 65536 + off);
                LDSM_X4(bl0, bl1, bl2, bl3, s0 + 81920 + off);
#pragma unroll
                for (int mt = 0; mt < 4; mt++) {
                    mma16816(acc[mt][2*ntp+0], afh[mt], bh0, bh1);
                    mma16816(acc[mt][2*ntp+0], afh[mt], bl0, bl1);
                    mma16816(acc[mt][2*ntp+0], afl[mt], bh0, bh1);
                    mma16816(acc[mt][2*ntp+1], afh[mt], bh2, bh3);
                    mma16816(acc[mt][2*ntp+1], afh[mt], bl2, bl3);
                    mma16816(acc[mt][2*ntp+1], afl[mt], bh2, bh3);
                }
            }
        }
        __syncthreads();
        if (c + 2 < nk) issue(c & 1, (c + 2) * 64);
    }

    // ---- epilogue ----
#pragma unroll
    for (int mt = 0; mt < 4; mt++) {
        int r0 = mbase + wr * 64 + mt * 16 + (lane >> 2);
#pragma unroll
        for (int nt = 0; nt < 4; nt++) {
            int col = nbase + wc * 32 + nt * 8 + (lane & 3) * 2;
            if (col < N) {
                float b0 = bias ? bias[col] : 0.f;
                float b1 = bias ? bias[col + 1] : 0.f;
                float2 v0 = make_float2(acc[mt][nt][0] + b0, acc[mt][nt][1] + b1);
                float2 v1 = make_float2(acc[mt][nt][2] + b0, acc[mt][nt][3] + b1);
                *(float2*)(C + (size_t)r0 * N + col)       = v0;
                *(float2*)(C + (size_t)(r0 + 8) * N + col) = v1;
            }
        }
    }
}

// ---------------- small fp32 NT GEMM (kept for G = C @ B^T) ----------------
__global__ void __launch_bounds__(256)
sgemm_nt(const float* __restrict__ A, const float* __restrict__ B,
         const float* __restrict__ bias, float* __restrict__ C,
         int N, int K, long sA, long sB, long sC)
{
    __shared__ float As[16][128];
    __shared__ float Bs[16][128];
    const int tid  = threadIdx.x;
    const int tcol = tid & 15;
    const int trow = tid >> 4;
    const float* Ab = A + (size_t)blockIdx.z * sA + (size_t)blockIdx.y * 128 * K;
    const float* Bb = B + (size_t)blockIdx.z * sB + (size_t)blockIdx.x * 128 * K;
    const int nbase = blockIdx.x * 128;

    float acc[8][8];
#pragma unroll
    for (int m = 0; m < 8; m++)
#pragma unroll
        for (int n = 0; n < 8; n++) acc[m][n] = 0.f;

    const int lrow = tid >> 2;
    const int lcol = (tid & 3) * 4;

    for (int kt = 0; kt < K; kt += 16) {
#pragma unroll
        for (int it = 0; it < 2; it++) {
            int r = lrow + it * 64;
            float4 va = *(const float4*)(Ab + (size_t)r * K + kt + lcol);
            As[lcol+0][r] = va.x; As[lcol+1][r] = va.y;
            As[lcol+2][r] = va.z; As[lcol+3][r] = va.w;
            float4 vb;
            if (nbase + r < N) vb = *(const float4*)(Bb + (size_t)r * K + kt + lcol);
            else               vb = make_float4(0.f, 0.f, 0.f, 0.f);
            Bs[lcol+0][r] = vb.x; Bs[lcol+1][r] = vb.y;
            Bs[lcol+2][r] = vb.z; Bs[lcol+3][r] = vb.w;
        }
        __syncthreads();
#pragma unroll
        for (int k = 0; k < 16; k++) {
            float ra[8], rb[8];
#pragma unroll
            for (int m = 0; m < 8; m++) ra[m] = As[k][trow * 8 + m];
#pragma unroll
            for (int n = 0; n < 8; n++) rb[n] = Bs[k][tcol * 8 + n];
#pragma unroll
            for (int m = 0; m < 8; m++)
#pragma unroll
                for (int n = 0; n < 8; n++) acc[m][n] = fmaf(ra[m], rb[n], acc[m][n]);
        }
        __syncthreads();
    }
#pragma unroll
    for (int m = 0; m < 8; m++) {
        int row = blockIdx.y * 128 + trow * 8 + m;
#pragma unroll
        for (int n = 0; n < 8; n++) {
            int col = nbase + tcol * 8 + n;
            if (col < N) {
                float bv = bias ? bias[col] : 0.f;
                C[(size_t)blockIdx.z * sC + (size_t)row * N + col] = acc[m][n] + bv;
            }
        }
    }
}

// ---------------- dt: softplus(dt_raw + bias), dA = -exp(A_log)*dt ----------------
__global__ void dt_kernel(const float* __restrict__ dt_bias, const float* __restrict__ A_log)
{
    int idx = blockIdx.x * blockDim.x + threadIdx.x;
    if (idx >= NROWS * NHEADS) return;
    int h = idx & (NHEADS - 1);
    int r = idx >> 5;
    float v = g_zxbcdt[(size_t)r * DINPROJ + DINNER + CONVDIM + h] + dt_bias[h];
    float dt = (v > 20.f) ? v : log1pf(__expf(v));
    g_dt[idx] = dt;
    g_dA[idx] = -__expf(A_log[h]) * dt;
}

// ---------------- causal depthwise conv (width 4) + SiLU; split x*dt / B / C ----------------
__global__ void conv_kernel(const float* __restrict__ w, const float* __restrict__ cb)
{
    long idx = (long)blockIdx.x * blockDim.x + threadIdx.x;
    if (idx >= (long)NROWS * CONVDIM) return;
    int c = (int)(idx % CONVDIM);
    int r = (int)(idx / CONVDIM);
    int l = r & (SEQLEN - 1);
    float acc = cb[c];
#pragma unroll
    for (int k = 0; k < 4; k++) {
        int lp = l - 3 + k;
        if (lp >= 0)
            acc = fmaf(w[c * 4 + k], g_zxbcdt[(size_t)(r - 3 + k) * DINPROJ + DINNER + c], acc);
    }
    float out = siluf(acc);
    if (c < DINNER) {
        g_xdt[(size_t)r * DINNER + c] = out * g_dt[r * NHEADS + (c >> 7)];
    } else if (c < DINNER + DSTATE) {
        g_Bv[r * DSTATE + (c - DINNER)] = out;
    } else {
        g_Cv[r * DSTATE + (c - DINNER - DSTATE)] = out;
    }
}

// ---------------- per-chunk inclusive cumsum of dA ----------------
__global__ void cumsum_kernel()
{
    int c = blockIdx.x, h = blockIdx.y, b = blockIdx.z;
    int t = threadIdx.x;
    __shared__ float s[CHUNKT];
    int row = b * SEQLEN + c * CHUNKT + t;
    s[t] = g_dA[row * NHEADS + h];
    __syncthreads();
#pragma unroll
    for (int off = 1; off < CHUNKT; off <<= 1) {
        float x = (t >= off) ? s[t - off] : 0.f;
        __syncthreads();
        s[t] += x;
        __syncthreads();
    }
    g_Acum[(b * NHEADS + h) * SEQLEN + c * CHUNKT + t] = s[t];
}

// ---------------- chunk-local states ----------------
__global__ void __launch_bounds__(256) states_kernel()
{
    int h = blockIdx.x, c = blockIdx.y, b = blockIdx.z;
    __shared__ float Xs[16][128];
    __shared__ float Bsc[16][64];
    __shared__ float Ac[CHUNKT];
    int tid = threadIdx.x;
    Ac[tid] = g_Acum[(b * NHEADS + h) * SEQLEN + c * CHUNKT + tid];
    __syncthreads();
    float Atot = Ac[CHUNKT - 1];
    int brow = b * SEQLEN + c * CHUNKT;
    int tp = tid >> 3, tn = tid & 7;
    float acc[4][8];
#pragma unroll
    for (int m = 0; m < 4; m++)
#pragma unroll
        for (int n = 0; n < 8; n++) acc[m][n] = 0.f;

    for (int lt = 0; lt < CHUNKT; lt += 16) {
#pragma unroll
        for (int q = 0; q < 8; q++) {
            int idx = tid + q * 256;
            int ll = idx >> 7, p = idx & 127;
            Xs[ll][p] = g_xdt[(size_t)(brow + lt + ll) * DINNER + h * HEADDIM + p];
        }
#pragma unroll
        for (int q = 0; q < 4; q++) {
            int idx = tid + q * 256;
            int ll = idx >> 6, n = idx & 63;
            Bsc[ll][n] = g_Bv[(brow + lt + ll) * DSTATE + n] * __expf(Atot - Ac[lt + ll]);
        }
        __syncthreads();
#pragma unroll
        for (int l = 0; l < 16; l++) {
            float ra[4], rb[8];
#pragma unroll
            for (int m = 0; m < 4; m++) ra[m] = Xs[l][tp * 4 + m];
#pragma unroll
            for (int n = 0; n < 8; n++) rb[n] = Bsc[l][tn * 8 + n];
#pragma unroll
            for (int m = 0; m < 4; m++)
#pragma unroll
                for (int n = 0; n < 8; n++) acc[m][n] = fmaf(ra[m], rb[n], acc[m][n]);
        }
        __syncthreads();
    }
    size_t base = ((size_t)((b * NCHUNK + c) * NHEADS + h)) * HEADDIM * DSTATE;
#pragma unroll
    for (int m = 0; m < 4; m++)
#pragma unroll
        for (int n = 0; n < 8; n++)
            g_states[base + (size_t)(tp * 4 + m) * DSTATE + tn * 8 + n] = acc[m][n];
}

// ---------------- inter-chunk state scan ----------------
__global__ void scan_kernel()
{
    int bh = blockIdx.x;
    int b = bh >> 5, h = bh & 31;
    int t = threadIdx.x;
    float S[32];
#pragma unroll
    for (int i = 0; i < 32; i++) S[i] = 0.f;
    for (int c = 0; c < NCHUNK; c++) {
        size_t base = ((size_t)((b * NCHUNK + c) * NHEADS + h)) * (HEADDIM * DSTATE) + (size_t)t * 32;
#pragma unroll
        for (int i = 0; i < 32; i++) g_prefix[base + i] = S[i];
        float f = __expf(g_Acum[(b * NHEADS + h) * SEQLEN + c * CHUNKT + CHUNKT - 1]);
#pragma unroll
        for (int i = 0; i < 32; i++) S[i] = S[i] * f + g_states[base + i];
    }
}

// ---------------- Y_diag ----------------
__global__ void __launch_bounds__(512) ydiag_kernel()
{
    int h = blockIdx.x, c = blockIdx.y, b = blockIdx.z;
    __shared__ float Ss[16][256];
    __shared__ float Xs[16][128];
    __shared__ float Ac[CHUNKT];
    int tid = threadIdx.x;
    if (tid < CHUNKT) Ac[tid] = g_Acum[(b * NHEADS + h) * SEQLEN + c * CHUNKT + tid];
    __syncthreads();
    int brow = b * SEQLEN + c * CHUNKT;
    size_t gbase = (size_t)(b * NCHUNK + c) * CHUNKT * CHUNKT;
    int ti = tid >> 4, tp = tid & 15;
    float acc[8][8];
#pragma unroll
    for (int m = 0; m < 8; m++)
#pragma unroll
        for (int n = 0; n < 8; n++) acc[m][n] = 0.f;

    for (int jt = 0; jt < CHUNKT; jt += 16) {
#pragma unroll
        for (int q = 0; q < 8; q++) {
            int idx = tid + q * 512;
            int jj = idx >> 8, i = idx & 255;
            int j = jt + jj;
            float v = 0.f;
            if (j <= i) v = __expf(Ac[i] - Ac[j]) * g_G[gbase + (size_t)i * 256 + j];
            Ss[jj][i] = v;
        }
#pragma unroll
        for (int q = 0; q < 4; q++) {
            int idx = tid + q * 512;
            int jj = idx >> 7, p = idx & 127;
            Xs[jj][p] = g_xdt[(size_t)(brow + jt + jj) * DINNER + h * HEADDIM + p];
        }
        __syncthreads();
#pragma unroll
        for (int k = 0; k < 16; k++) {
            float ra[8], rb[8];
#pragma unroll
            for (int m = 0; m < 8; m++) ra[m] = Ss[k][ti * 8 + m];
#pragma unroll
            for (int n = 0; n < 8; n++) rb[n] = Xs[k][tp * 8 + n];
#pragma unroll
            for (int m = 0; m < 8; m++)
#pragma unroll
                for (int n = 0; n < 8; n++) acc[m][n] = fmaf(ra[m], rb[n], acc[m][n]);
        }
        __syncthreads();
    }
#pragma unroll
    for (int m = 0; m < 8; m++) {
        int i = ti * 8 + m;
#pragma unroll
        for (int n = 0; n < 8; n++)
            g_y[(size_t)(brow + i) * DINNER + h * HEADDIM + tp * 8 + n] = acc[m][n];
    }
}

// ---------------- Y_off ----------------
__global__ void __launch_bounds__(512) yoff_kernel()
{
    int h = blockIdx.x, c = blockIdx.y, b = blockIdx.z;
    __shared__ float Cs[16][256];
    __shared__ float St[16][128];
    __shared__ float Ac[CHUNKT];
    int tid = threadIdx.x;
    if (tid < CHUNKT) Ac[tid] = g_Acum[(b * NHEADS + h) * SEQLEN + c * CHUNKT + tid];
    __syncthreads();
    int brow = b * SEQLEN + c * CHUNKT;
    size_t sbase = ((size_t)((b * NCHUNK + c) * NHEADS + h)) * (HEADDIM * DSTATE);
    int ti = tid >> 4, tp = tid & 15;
    float acc[8][8];
#pragma unroll
    for (int m = 0; m < 8; m++)
#pragma unroll
        for (int n = 0; n < 8; n++) acc[m][n] = 0.f;

    for (int kt = 0; kt < DSTATE; kt += 16) {
#pragma unroll
        for (int q = 0; q < 8; q++) {
            int idx = tid + q * 512;
            int nn = idx >> 8, i = idx & 255;
            Cs[nn][i] = g_Cv[(brow + i) * DSTATE + kt + nn];
        }
#pragma unroll
        for (int q = 0; q < 4; q++) {
            int idx = tid + q * 512;
            int nn = idx >> 7, p = idx & 127;
            St[nn][p] = g_prefix[sbase + (size_t)p * DSTATE + kt + nn];
        }
        __syncthreads();
#pragma unroll
        for (int k = 0; k < 16; k++) {
            float ra[8], rb[8];
#pragma unroll
            for (int m = 0; m < 8; m++) ra[m] = Cs[k][ti * 8 + m];
#pragma unroll
            for (int n = 0; n < 8; n++) rb[n] = St[k][tp * 8 + n];
#pragma unroll
            for (int m = 0; m < 8; m++)
#pragma unroll
                for (int n = 0; n < 8; n++) acc[m][n] = fmaf(ra[m], rb[n], acc[m][n]);
        }
        __syncthreads();
    }
#pragma unroll
    for (int m = 0; m < 8; m++) {
        int i = ti * 8 + m;
        float e = __expf(Ac[i]);
#pragma unroll
        for (int n = 0; n < 8; n++) {
            size_t o = (size_t)(brow + i) * DINNER + h * HEADDIM + tp * 8 + n;
            g_y[o] = fmaf(acc[m][n], e, g_y[o]);
        }
    }
}

// ---------------- gating (y * silu(z)) + LayerNorm; emits bf16 hi/lo ----------------
__global__ void __launch_bounds__(256) ln_kernel(const float* __restrict__ lnw, const float* __restrict__ lnb)
{
    int row = blockIdx.x;
    int tid = threadIdx.x;
    float g[16];
    float s = 0.f, s2 = 0.f;
#pragma unroll
    for (int q = 0; q < 16; q++) {
        int i = tid + q * 256;
        float y = g_y[(size_t)row * DINNER + i];
        float z = g_zxbcdt[(size_t)row * DINPROJ + i];
        float v = y * siluf(z);
        g[q] = v; s += v; s2 = fmaf(v, v, s2);
    }
    __shared__ float red[2][8];
#pragma unroll
    for (int off = 16; off > 0; off >>= 1) {
        s  += __shfl_xor_sync(0xffffffffu, s, off);
        s2 += __shfl_xor_sync(0xffffffffu, s2, off);
    }
    if ((tid & 31) == 0) { red[0][tid >> 5] = s; red[1][tid >> 5] = s2; }
    __syncthreads();
    if (tid == 0) {
        float a = 0.f, a2 = 0.f;
#pragma unroll
        for (int w = 0; w < 8; w++) { a += red[0][w]; a2 += red[1][w]; }
        red[0][0] = a; red[1][0] = a2;
    }
    __syncthreads();
    float mu  = red[0][0] * (1.f / DINNER);
    float var = red[1][0] * (1.f / DINNER) - mu * mu;
    float rstd = rsqrtf(var + LN_EPS);
#pragma unroll
    for (int q = 0; q < 16; q++) {
        int i = tid + q * 256;
        float v = (g[q] - mu) * rstd * lnw[i] + lnb[i];
        __nv_bfloat16 h = __float2bfloat16(v);
        g_ynh[(size_t)row * DINNER + i] = h;
        g_ynl[(size_t)row * DINNER + i] = __float2bfloat16(v - __bfloat162float(h));
    }
}

// ---------------- launch ----------------
extern "C" void kernel_launch(void* const* d_in, const int* in_sizes, int n_in,
                              void* d_out, int out_size)
{
    const float* u          = (const float*)d_in[0];
    const float* in_proj_w  = (const float*)d_in[1];
    const float* in_proj_b  = (const float*)d_in[2];
    const float* conv_w     = (const float*)d_in[3];
    const float* conv_b     = (const float*)d_in[4];
    const float* dt_bias    = (const float*)d_in[5];
    const float* A_log      = (const float*)d_in[6];
    const float* ln_w       = (const float*)d_in[7];
    const float* ln_b       = (const float*)d_in[8];
    const float* out_proj_w = (const float*)d_in[9];
    const float* out_proj_b = (const float*)d_in[10];
    float* out = (float*)d_out;

    float *zx, *gB, *gC, *gG;
    __nv_bfloat16 *uh, *ul, *w1h, *w1l, *ynh, *ynl, *w2h, *w2l;
    cudaGetSymbolAddress((void**)&zx,  g_zxbcdt);
    cudaGetSymbolAddress((void**)&gB,  g_Bv);
    cudaGetSymbolAddress((void**)&gC,  g_Cv);
    cudaGetSymbolAddress((void**)&gG,  g_G);
    cudaGetSymbolAddress((void**)&uh,  g_uh);
    cudaGetSymbolAddress((void**)&ul,  g_ul);
    cudaGetSymbolAddress((void**)&w1h, g_w1h);
    cudaGetSymbolAddress((void**)&w1l, g_w1l);
    cudaGetSymbolAddress((void**)&ynh, g_ynh);
    cudaGetSymbolAddress((void**)&ynl, g_ynl);
    cudaGetSymbolAddress((void**)&w2h, g_w2h);
    cudaGetSymbolAddress((void**)&w2l, g_w2l);

    cudaFuncSetAttribute(mma_gemm_nt, cudaFuncAttributeMaxDynamicSharedMemorySize, 2 * GSTAGE);

    // 0) fp32 -> bf16 hi/lo splits
    {
        long n1 = (long)NROWS * DMODEL;
        split_kernel<<<(unsigned)((n1 + 255) / 256), 256>>>(u, uh, ul, n1);
        long n2 = (long)DINPROJ * DMODEL;
        split_kernel<<<(unsigned)((n2 + 255) / 256), 256>>>(in_proj_w, w1h, w1l, n2);
        long n3 = (long)DMODEL * DINNER;
        split_kernel<<<(unsigned)((n3 + 255) / 256), 256>>>(out_proj_w, w2h, w2l, n3);
    }

    // 1) in_proj: M=8192, N=8352, K=2048
    mma_gemm_nt<<<dim3((DINPROJ + 127) / 128, NROWS / 256), 512, 2 * GSTAGE>>>(
        uh, ul, w1h, w1l, in_proj_b, zx, DINPROJ, DMODEL);

    // 2) dt softplus + dA
    dt_kernel<<<(NROWS * NHEADS) / 256, 256>>>(dt_bias, A_log);

    // 3) causal conv + silu + split (x*dt, B, C)
    {
        long total = (long)NROWS * CONVDIM;
        conv_kernel<<<(unsigned)((total + 255) / 256), 256>>>(conv_w, conv_b);
    }

    // 4) per-chunk cumsum of dA
    cumsum_kernel<<<dim3(NCHUNK, NHEADS, BATCH), CHUNKT>>>();

    // 5) G = C @ B^T per (b,chunk)
    sgemm_nt<<<dim3(2, 2, BATCH * NCHUNK), 256>>>(
        gC, gB, nullptr, gG, CHUNKT, DSTATE,
        (long)CHUNKT * DSTATE, (long)CHUNKT * DSTATE, (long)CHUNKT * CHUNKT);

    // 6) chunk-local states
    states_kernel<<<dim3(NHEADS, NCHUNK, BATCH), 256>>>();

    // 7) inter-chunk scan
    scan_kernel<<<BATCH * NHEADS, 256>>>();

    // 8) Y_diag then Y_off
    ydiag_kernel<<<dim3(NHEADS, NCHUNK, BATCH), 512>>>();
    yoff_kernel<<<dim3(NHEADS, NCHUNK, BATCH), 512>>>();

    // 9) gate + layernorm (+ bf16 split of yn)
    ln_kernel<<<NROWS, 256>>>(ln_w, ln_b);

    // 10) out_proj: M=8192, N=2048, K=4096
    mma_gemm_nt<<<dim3(DMODEL / 128, NROWS / 256), 512, 2 * GSTAGE>>>(
        ynh, ynl, w2h, w2l, out_proj_b, out, DMODEL, DINNER);
}

// round 5
// speedup vs baseline: 2.3400x; 1.0670x over previous
#include <cuda_runtime.h>
#include <cuda_bf16.h>
#include <cstdint>
#include <math.h>

#define BATCH   2
#define SEQLEN  4096
#define DMODEL  2048
#define DINNER  4096
#define NHEADS  32
#define HEADDIM 128
#define DSTATE  64
#define NCHUNK  16
#define CHUNKT  256
#define CONVDIM 4224
#define DINPROJ 8352
#define NROWS   (BATCH*SEQLEN)
#define LN_EPS  1e-5f

// ---------------- scratch (device globals; no allocations allowed) ----------------
__device__ float g_zxbcdt[(size_t)NROWS * DINPROJ];   // in_proj output: z | xBC | dt_raw
__device__ float g_xdt  [(size_t)NROWS * DINNER];     // conv(x)*silu scaled by dt
__device__ float g_Bv   [NROWS * DSTATE];
__device__ float g_Cv   [NROWS * DSTATE];
__device__ float g_dt   [NROWS * NHEADS];
__device__ float g_dA   [NROWS * NHEADS];
__device__ float g_Acum [BATCH * NHEADS * SEQLEN];
__device__ float g_G    [(size_t)BATCH * NCHUNK * CHUNKT * CHUNKT];
__device__ float g_states[(size_t)BATCH * NCHUNK * NHEADS * HEADDIM * DSTATE];
__device__ float g_prefix[(size_t)BATCH * NCHUNK * NHEADS * HEADDIM * DSTATE];
__device__ float g_y    [(size_t)NROWS * DINNER];

// bf16 split buffers for tensor-core GEMMs
__device__ __nv_bfloat16 g_uh [(size_t)NROWS * DMODEL];
__device__ __nv_bfloat16 g_ul [(size_t)NROWS * DMODEL];
__device__ __nv_bfloat16 g_w1h[(size_t)DINPROJ * DMODEL];
__device__ __nv_bfloat16 g_w1l[(size_t)DINPROJ * DMODEL];
__device__ __nv_bfloat16 g_ynh[(size_t)NROWS * DINNER];
__device__ __nv_bfloat16 g_ynl[(size_t)NROWS * DINNER];
__device__ __nv_bfloat16 g_w2h[(size_t)DMODEL * DINNER];
__device__ __nv_bfloat16 g_w2l[(size_t)DMODEL * DINNER];

__device__ __forceinline__ float siluf(float x) { return x / (1.f + __expf(-x)); }

__device__ __forceinline__ uint32_t smem_u32(const void* p) {
    uint32_t a;
    asm("{ .reg .u64 t; cvta.to.shared.u64 t, %1; cvt.u32.u64 %0, t; }" : "=r"(a) : "l"(p));
    return a;
}

// ================= split fp32 -> bf16 hi/lo =================
__global__ void split_kernel(const float* __restrict__ src,
                             __nv_bfloat16* __restrict__ hi,
                             __nv_bfloat16* __restrict__ lo, long n)
{
    long i = (long)blockIdx.x * blockDim.x + threadIdx.x;
    if (i >= n) return;
    float x = src[i];
    __nv_bfloat16 h = __float2bfloat16(x);
    hi[i] = h;
    lo[i] = __float2bfloat16(x - __bfloat162float(h));
}

// ================= tensor-core primitives =================
__device__ __forceinline__ void mma16816(float* c, const uint32_t* a, uint32_t b0, uint32_t b1)
{
    asm volatile(
        "mma.sync.aligned.m16n8k16.row.col.f32.bf16.bf16.f32 "
        "{%0,%1,%2,%3}, {%4,%5,%6,%7}, {%8,%9}, {%0,%1,%2,%3};"
        : "+f"(c[0]), "+f"(c[1]), "+f"(c[2]), "+f"(c[3])
        : "r"(a[0]), "r"(a[1]), "r"(a[2]), "r"(a[3]), "r"(b0), "r"(b1));
}
#define LDSM_X4(r0, r1, r2, r3, addr) \
    asm volatile("ldmatrix.sync.aligned.m8n8.x4.shared.b16 {%0,%1,%2,%3}, [%4];" \
                 : "=r"(r0), "=r"(r1), "=r"(r2), "=r"(r3) : "r"(addr))
#define CP16(dst, src, sz) \
    asm volatile("cp.async.cg.shared.global [%0], [%1], 16, %2;" \
                 :: "r"(dst), "l"(src), "r"(sz))
#define CP_COMMIT() asm volatile("cp.async.commit_group;" ::: "memory")
#define CP_WAIT1()  asm volatile("cp.async.wait_group 1;" ::: "memory")
#define CP_WAIT0()  asm volatile("cp.async.wait_group 0;" ::: "memory")

// ================= split-bf16 tensor-core GEMM: C = A*B^T + bias =================
// BM=128, BN=128, BK=64 (128B rows, SW128 swizzle), 512 threads (16 warps, 32x32 tiles).
// 3-stage cp.async pipeline, single __syncthreads per iteration.
// A: M x K hi/lo (M multiple of 128), B: N x K hi/lo (row-guarded), C: M x N fp32.
#define GST 65536
__global__ void __launch_bounds__(512, 1)
mma_gemm_nt(const __nv_bfloat16* __restrict__ Ah, const __nv_bfloat16* __restrict__ Al,
            const __nv_bfloat16* __restrict__ Bh, const __nv_bfloat16* __restrict__ Bl,
            const float* __restrict__ bias, float* __restrict__ C, int N, int K)
{
    extern __shared__ char smem[];
    const uint32_t sb = smem_u32(smem);
    const int tid = threadIdx.x, lane = tid & 31, wid = tid >> 5;
    const int wr = wid >> 2, wc = wid & 3;            // 4x4 warp grid, 32x32 tiles
    const int mbase = blockIdx.y * 128;
    const int nbase = blockIdx.x * 128;

    // ---- loader assignment: 4 thr/row, 2x16B units each ----
    const int r = tid >> 2, u0 = (tid & 3) * 2;
    const bool bval = (nbase + r) < N;
    const uint32_t bsz = bval ? 16u : 0u;
    const __nv_bfloat16* gAh = Ah + (size_t)(mbase + r) * K + u0 * 8;
    const __nv_bfloat16* gAl = Al + (size_t)(mbase + r) * K + u0 * 8;
    const __nv_bfloat16* gBh = Bh + (size_t)(bval ? nbase + r : 0) * K + u0 * 8;
    const __nv_bfloat16* gBl = Bl + (size_t)(bval ? nbase + r : 0) * K + u0 * 8;
    const uint32_t d0 = r * 128 + (( u0      ^ (r & 7)) * 16);
    const uint32_t d1 = r * 128 + (((u0 + 1) ^ (r & 7)) * 16);

    auto issue = [&](int st, int kt) {
        uint32_t s0 = sb + st * GST;
        CP16(s0 + d0,         gAh + kt,     16);
        CP16(s0 + d1,         gAh + kt + 8, 16);
        CP16(s0 + 16384 + d0, gAl + kt,     16);
        CP16(s0 + 16384 + d1, gAl + kt + 8, 16);
        CP16(s0 + 32768 + d0, gBh + kt,     bsz);
        CP16(s0 + 32768 + d1, gBh + kt + 8, bsz);
        CP16(s0 + 49152 + d0, gBl + kt,     bsz);
        CP16(s0 + 49152 + d1, gBl + kt + 8, bsz);
        CP_COMMIT();
    };

    float acc[2][4][4];
#pragma unroll
    for (int mt = 0; mt < 2; mt++)
#pragma unroll
        for (int nt = 0; nt < 4; nt++)
#pragma unroll
            for (int i = 0; i < 4; i++) acc[mt][nt][i] = 0.f;

    const int nk = K >> 6;
    issue(0, 0);
    issue(1, 64);

    // ldmatrix lane decomposition
    const int g = lane >> 3, li = lane & 7;
    const int arow_lo = (g & 1) * 8 + li;   // A: row-within-16 tile
    const int ahalf   = g >> 1;             // A: k-half
    const int brow_lo = (g >> 1) * 8 + li;  // B: row-within-16 (nt pair)
    const int bhalf   = g & 1;              // B: k-half

    int stage = 0;
    for (int c = 0; c < nk; c++) {
        if (c + 1 < nk) CP_WAIT1(); else CP_WAIT0();
        __syncthreads();
        if (c + 2 < nk) {
            int st = stage + 2; if (st >= 3) st -= 3;
            issue(st, (c + 2) * 64);
        }
        const uint32_t s0 = sb + stage * GST;
#pragma unroll
        for (int s = 0; s < 4; s++) {
            uint32_t afh[2][4], afl[2][4];
#pragma unroll
            for (int mt = 0; mt < 2; mt++) {
                int row = wr * 32 + mt * 16 + arow_lo;
                uint32_t off = row * 128 + (((2 * s + ahalf) ^ (row & 7)) * 16);
                LDSM_X4(afh[mt][0], afh[mt][1], afh[mt][2], afh[mt][3], s0 + off);
                LDSM_X4(afl[mt][0], afl[mt][1], afl[mt][2], afl[mt][3], s0 + 16384 + off);
            }
#pragma unroll
            for (int ntp = 0; ntp < 2; ntp++) {
                int row = wc * 32 + ntp * 16 + brow_lo;
                uint32_t off = row * 128 + (((2 * s + bhalf) ^ (row & 7)) * 16);
                uint32_t bh0, bh1, bh2, bh3, bl0, bl1, bl2, bl3;
                LDSM_X4(bh0, bh1, bh2, bh3, s0 + 32768 + off);
                LDSM_X4(bl0, bl1, bl2, bl3, s0 + 49152 + off);
#pragma unroll
                for (int mt = 0; mt < 2; mt++) {
                    mma16816(acc[mt][2*ntp+0], afh[mt], bh0, bh1);
                    mma16816(acc[mt][2*ntp+0], afh[mt], bl0, bl1);
                    mma16816(acc[mt][2*ntp+0], afl[mt], bh0, bh1);
                    mma16816(acc[mt][2*ntp+1], afh[mt], bh2, bh3);
                    mma16816(acc[mt][2*ntp+1], afh[mt], bl2, bl3);
                    mma16816(acc[mt][2*ntp+1], afl[mt], bh2, bh3);
                }
            }
        }
        stage++; if (stage >= 3) stage -= 3;
    }

    // ---- epilogue ----
#pragma unroll
    for (int mt = 0; mt < 2; mt++) {
        int r0 = mbase + wr * 32 + mt * 16 + (lane >> 2);
#pragma unroll
        for (int nt = 0; nt < 4; nt++) {
            int col = nbase + wc * 32 + nt * 8 + (lane & 3) * 2;
            if (col < N) {
                float b0 = bias ? bias[col] : 0.f;
                float b1 = bias ? bias[col + 1] : 0.f;
                float2 v0 = make_float2(acc[mt][nt][0] + b0, acc[mt][nt][1] + b1);
                float2 v1 = make_float2(acc[mt][nt][2] + b0, acc[mt][nt][3] + b1);
                *(float2*)(C + (size_t)r0 * N + col)       = v0;
                *(float2*)(C + (size_t)(r0 + 8) * N + col) = v1;
            }
        }
    }
}

// ---------------- small fp32 NT GEMM (kept for G = C @ B^T) ----------------
__global__ void __launch_bounds__(256)
sgemm_nt(const float* __restrict__ A, const float* __restrict__ B,
         const float* __restrict__ bias, float* __restrict__ C,
         int N, int K, long sA, long sB, long sC)
{
    __shared__ float As[16][128];
    __shared__ float Bs[16][128];
    const int tid  = threadIdx.x;
    const int tcol = tid & 15;
    const int trow = tid >> 4;
    const float* Ab = A + (size_t)blockIdx.z * sA + (size_t)blockIdx.y * 128 * K;
    const float* Bb = B + (size_t)blockIdx.z * sB + (size_t)blockIdx.x * 128 * K;
    const int nbase = blockIdx.x * 128;

    float acc[8][8];
#pragma unroll
    for (int m = 0; m < 8; m++)
#pragma unroll
        for (int n = 0; n < 8; n++) acc[m][n] = 0.f;

    const int lrow = tid >> 2;
    const int lcol = (tid & 3) * 4;

    for (int kt = 0; kt < K; kt += 16) {
#pragma unroll
        for (int it = 0; it < 2; it++) {
            int r = lrow + it * 64;
            float4 va = *(const float4*)(Ab + (size_t)r * K + kt + lcol);
            As[lcol+0][r] = va.x; As[lcol+1][r] = va.y;
            As[lcol+2][r] = va.z; As[lcol+3][r] = va.w;
            float4 vb;
            if (nbase + r < N) vb = *(const float4*)(Bb + (size_t)r * K + kt + lcol);
            else               vb = make_float4(0.f, 0.f, 0.f, 0.f);
            Bs[lcol+0][r] = vb.x; Bs[lcol+1][r] = vb.y;
            Bs[lcol+2][r] = vb.z; Bs[lcol+3][r] = vb.w;
        }
        __syncthreads();
#pragma unroll
        for (int k = 0; k < 16; k++) {
            float ra[8], rb[8];
#pragma unroll
            for (int m = 0; m < 8; m++) ra[m] = As[k][trow * 8 + m];
#pragma unroll
            for (int n = 0; n < 8; n++) rb[n] = Bs[k][tcol * 8 + n];
#pragma unroll
            for (int m = 0; m < 8; m++)
#pragma unroll
                for (int n = 0; n < 8; n++) acc[m][n] = fmaf(ra[m], rb[n], acc[m][n]);
        }
        __syncthreads();
    }
#pragma unroll
    for (int m = 0; m < 8; m++) {
        int row = blockIdx.y * 128 + trow * 8 + m;
#pragma unroll
        for (int n = 0; n < 8; n++) {
            int col = nbase + tcol * 8 + n;
            if (col < N) {
                float bv = bias ? bias[col] : 0.f;
                C[(size_t)blockIdx.z * sC + (size_t)row * N + col] = acc[m][n] + bv;
            }
        }
    }
}

// ---------------- dt: softplus(dt_raw + bias), dA = -exp(A_log)*dt ----------------
__global__ void dt_kernel(const float* __restrict__ dt_bias, const float* __restrict__ A_log)
{
    int idx = blockIdx.x * blockDim.x + threadIdx.x;
    if (idx >= NROWS * NHEADS) return;
    int h = idx & (NHEADS - 1);
    int r = idx >> 5;
    float v = g_zxbcdt[(size_t)r * DINPROJ + DINNER + CONVDIM + h] + dt_bias[h];
    float dt = (v > 20.f) ? v : log1pf(__expf(v));
    g_dt[idx] = dt;
    g_dA[idx] = -__expf(A_log[h]) * dt;
}

// ---------------- causal depthwise conv (width 4) + SiLU; split x*dt / B / C ----------------
__global__ void conv_kernel(const float* __restrict__ w, const float* __restrict__ cb)
{
    long idx = (long)blockIdx.x * blockDim.x + threadIdx.x;
    if (idx >= (long)NROWS * CONVDIM) return;
    int c = (int)(idx % CONVDIM);
    int r = (int)(idx / CONVDIM);
    int l = r & (SEQLEN - 1);
    float acc = cb[c];
#pragma unroll
    for (int k = 0; k < 4; k++) {
        int lp = l - 3 + k;
        if (lp >= 0)
            acc = fmaf(w[c * 4 + k], g_zxbcdt[(size_t)(r - 3 + k) * DINPROJ + DINNER + c], acc);
    }
    float out = siluf(acc);
    if (c < DINNER) {
        g_xdt[(size_t)r * DINNER + c] = out * g_dt[r * NHEADS + (c >> 7)];
    } else if (c < DINNER + DSTATE) {
        g_Bv[r * DSTATE + (c - DINNER)] = out;
    } else {
        g_Cv[r * DSTATE + (c - DINNER - DSTATE)] = out;
    }
}

// ---------------- per-chunk inclusive cumsum of dA ----------------
__global__ void cumsum_kernel()
{
    int c = blockIdx.x, h = blockIdx.y, b = blockIdx.z;
    int t = threadIdx.x;
    __shared__ float s[CHUNKT];
    int row = b * SEQLEN + c * CHUNKT + t;
    s[t] = g_dA[row * NHEADS + h];
    __syncthreads();
#pragma unroll
    for (int off = 1; off < CHUNKT; off <<= 1) {
        float x = (t >= off) ? s[t - off] : 0.f;
        __syncthreads();
        s[t] += x;
        __syncthreads();
    }
    g_Acum[(b * NHEADS + h) * SEQLEN + c * CHUNKT + t] = s[t];
}

// ---------------- chunk-local states ----------------
__global__ void __launch_bounds__(256) states_kernel()
{
    int h = blockIdx.x, c = blockIdx.y, b = blockIdx.z;
    __shared__ float Xs[16][128];
    __shared__ float Bsc[16][64];
    __shared__ float Ac[CHUNKT];
    int tid = threadIdx.x;
    Ac[tid] = g_Acum[(b * NHEADS + h) * SEQLEN + c * CHUNKT + tid];
    __syncthreads();
    float Atot = Ac[CHUNKT - 1];
    int brow = b * SEQLEN + c * CHUNKT;
    int tp = tid >> 3, tn = tid & 7;
    float acc[4][8];
#pragma unroll
    for (int m = 0; m < 4; m++)
#pragma unroll
        for (int n = 0; n < 8; n++) acc[m][n] = 0.f;

    for (int lt = 0; lt < CHUNKT; lt += 16) {
#pragma unroll
        for (int q = 0; q < 8; q++) {
            int idx = tid + q * 256;
            int ll = idx >> 7, p = idx & 127;
            Xs[ll][p] = g_xdt[(size_t)(brow + lt + ll) * DINNER + h * HEADDIM + p];
        }
#pragma unroll
        for (int q = 0; q < 4; q++) {
            int idx = tid + q * 256;
            int ll = idx >> 6, n = idx & 63;
            Bsc[ll][n] = g_Bv[(brow + lt + ll) * DSTATE + n] * __expf(Atot - Ac[lt + ll]);
        }
        __syncthreads();
#pragma unroll
        for (int l = 0; l < 16; l++) {
            float ra[4], rb[8];
#pragma unroll
            for (int m = 0; m < 4; m++) ra[m] = Xs[l][tp * 4 + m];
#pragma unroll
            for (int n = 0; n < 8; n++) rb[n] = Bsc[l][tn * 8 + n];
#pragma unroll
            for (int m = 0; m < 4; m++)
#pragma unroll
                for (int n = 0; n < 8; n++) acc[m][n] = fmaf(ra[m], rb[n], acc[m][n]);
        }
        __syncthreads();
    }
    size_t base = ((size_t)((b * NCHUNK + c) * NHEADS + h)) * HEADDIM * DSTATE;
#pragma unroll
    for (int m = 0; m < 4; m++)
#pragma unroll
        for (int n = 0; n < 8; n++)
            g_states[base + (size_t)(tp * 4 + m) * DSTATE + tn * 8 + n] = acc[m][n];
}

// ---------------- inter-chunk state scan ----------------
__global__ void scan_kernel()
{
    int bh = blockIdx.x;
    int b = bh >> 5, h = bh & 31;
    int t = threadIdx.x;
    float S[32];
#pragma unroll
    for (int i = 0; i < 32; i++) S[i] = 0.f;
    for (int c = 0; c < NCHUNK; c++) {
        size_t base = ((size_t)((b * NCHUNK + c) * NHEADS + h)) * (HEADDIM * DSTATE) + (size_t)t * 32;
#pragma unroll
        for (int i = 0; i < 32; i++) g_prefix[base + i] = S[i];
        float f = __expf(g_Acum[(b * NHEADS + h) * SEQLEN + c * CHUNKT + CHUNKT - 1]);
#pragma unroll
        for (int i = 0; i < 32; i++) S[i] = S[i] * f + g_states[base + i];
    }
}

// ---------------- fused Y = Y_diag + Y_off (single write of g_y) ----------------
// Y_diag: (exp(Acum_i - Acum_j) * G[i,j] * [j<=i]) @ X
// Y_off:  (C[i,:]*exp(Acum_i)) @ prefix^T  -- exp folded into C staging
__global__ void __launch_bounds__(512) yfused_kernel()
{
    int h = blockIdx.x, c = blockIdx.y, b = blockIdx.z;
    __shared__ float Ss[16][256];
    __shared__ float Xs[16][128];
    __shared__ float Ac[CHUNKT];
    __shared__ float eAc[CHUNKT];
    int tid = threadIdx.x;
    if (tid < CHUNKT) {
        float a = g_Acum[(b * NHEADS + h) * SEQLEN + c * CHUNKT + tid];
        Ac[tid] = a;
        eAc[tid] = __expf(a);
    }
    __syncthreads();
    int brow = b * SEQLEN + c * CHUNKT;
    size_t gbase = (size_t)(b * NCHUNK + c) * CHUNKT * CHUNKT;
    size_t sbase = ((size_t)((b * NCHUNK + c) * NHEADS + h)) * (HEADDIM * DSTATE);
    int ti = tid >> 4, tp = tid & 15;
    float acc[8][8];
#pragma unroll
    for (int m = 0; m < 8; m++)
#pragma unroll
        for (int n = 0; n < 8; n++) acc[m][n] = 0.f;

    // ---- part 1: masked decay * G @ X ----
    for (int jt = 0; jt < CHUNKT; jt += 16) {
#pragma unroll
        for (int q = 0; q < 8; q++) {
            int idx = tid + q * 512;
            int jj = idx >> 8, i = idx & 255;
            int j = jt + jj;
            float v = 0.f;
            if (j <= i) v = __expf(Ac[i] - Ac[j]) * g_G[gbase + (size_t)i * 256 + j];
            Ss[jj][i] = v;
        }
#pragma unroll
        for (int q = 0; q < 4; q++) {
            int idx = tid + q * 512;
            int jj = idx >> 7, p = idx & 127;
            Xs[jj][p] = g_xdt[(size_t)(brow + jt + jj) * DINNER + h * HEADDIM + p];
        }
        __syncthreads();
#pragma unroll
        for (int k = 0; k < 16; k++) {
            float ra[8], rb[8];
#pragma unroll
            for (int m = 0; m < 8; m++) ra[m] = Ss[k][ti * 8 + m];
#pragma unroll
            for (int n = 0; n < 8; n++) rb[n] = Xs[k][tp * 8 + n];
#pragma unroll
            for (int m = 0; m < 8; m++)
#pragma unroll
                for (int n = 0; n < 8; n++) acc[m][n] = fmaf(ra[m], rb[n], acc[m][n]);
        }
        __syncthreads();
    }

    // ---- part 2: (C*exp(Acum)) @ prefix^T ----
    for (int kt = 0; kt < DSTATE; kt += 16) {
#pragma unroll
        for (int q = 0; q < 8; q++) {
            int idx = tid + q * 512;
            int nn = idx >> 8, i = idx & 255;
            Ss[nn][i] = g_Cv[(brow + i) * DSTATE + kt + nn] * eAc[i];
        }
#pragma unroll
        for (int q = 0; q < 4; q++) {
            int idx = tid + q * 512;
            int nn = idx >> 7, p = idx & 127;
            Xs[nn][p] = g_prefix[sbase + (size_t)p * DSTATE + kt + nn];
        }
        __syncthreads();
#pragma unroll
        for (int k = 0; k < 16; k++) {
            float ra[8], rb[8];
#pragma unroll
            for (int m = 0; m < 8; m++) ra[m] = Ss[k][ti * 8 + m];
#pragma unroll
            for (int n = 0; n < 8; n++) rb[n] = Xs[k][tp * 8 + n];
#pragma unroll
            for (int m = 0; m < 8; m++)
#pragma unroll
                for (int n = 0; n < 8; n++) acc[m][n] = fmaf(ra[m], rb[n], acc[m][n]);
        }
        __syncthreads();
    }

#pragma unroll
    for (int m = 0; m < 8; m++) {
        int i = ti * 8 + m;
#pragma unroll
        for (int n = 0; n < 8; n++)
            g_y[(size_t)(brow + i) * DINNER + h * HEADDIM + tp * 8 + n] = acc[m][n];
    }
}

// ---------------- gating (y * silu(z)) + LayerNorm; emits bf16 hi/lo ----------------
__global__ void __launch_bounds__(256) ln_kernel(const float* __restrict__ lnw, const float* __restrict__ lnb)
{
    int row = blockIdx.x;
    int tid = threadIdx.x;
    float g[16];
    float s = 0.f, s2 = 0.f;
#pragma unroll
    for (int q = 0; q < 16; q++) {
        int i = tid + q * 256;
        float y = g_y[(size_t)row * DINNER + i];
        float z = g_zxbcdt[(size_t)row * DINPROJ + i];
        float v = y * siluf(z);
        g[q] = v; s += v; s2 = fmaf(v, v, s2);
    }
    __shared__ float red[2][8];
#pragma unroll
    for (int off = 16; off > 0; off >>= 1) {
        s  += __shfl_xor_sync(0xffffffffu, s, off);
        s2 += __shfl_xor_sync(0xffffffffu, s2, off);
    }
    if ((tid & 31) == 0) { red[0][tid >> 5] = s; red[1][tid >> 5] = s2; }
    __syncthreads();
    if (tid == 0) {
        float a = 0.f, a2 = 0.f;
#pragma unroll
        for (int w = 0; w < 8; w++) { a += red[0][w]; a2 += red[1][w]; }
        red[0][0] = a; red[1][0] = a2;
    }
    __syncthreads();
    float mu  = red[0][0] * (1.f / DINNER);
    float var = red[1][0] * (1.f / DINNER) - mu * mu;
    float rstd = rsqrtf(var + LN_EPS);
#pragma unroll
    for (int q = 0; q < 16; q++) {
        int i = tid + q * 256;
        float v = (g[q] - mu) * rstd * lnw[i] + lnb[i];
        __nv_bfloat16 h = __float2bfloat16(v);
        g_ynh[(size_t)row * DINNER + i] = h;
        g_ynl[(size_t)row * DINNER + i] = __float2bfloat16(v - __bfloat162float(h));
    }
}

// ---------------- launch ----------------
extern "C" void kernel_launch(void* const* d_in, const int* in_sizes, int n_in,
                              void* d_out, int out_size)
{
    const float* u          = (const float*)d_in[0];
    const float* in_proj_w  = (const float*)d_in[1];
    const float* in_proj_b  = (const float*)d_in[2];
    const float* conv_w     = (const float*)d_in[3];
    const float* conv_b     = (const float*)d_in[4];
    const float* dt_bias    = (const float*)d_in[5];
    const float* A_log      = (const float*)d_in[6];
    const float* ln_w       = (const float*)d_in[7];
    const float* ln_b       = (const float*)d_in[8];
    const float* out_proj_w = (const float*)d_in[9];
    const float* out_proj_b = (const float*)d_in[10];
    float* out = (float*)d_out;

    float *zx, *gB, *gC, *gG;
    __nv_bfloat16 *uh, *ul, *w1h, *w1l, *ynh, *ynl, *w2h, *w2l;
    cudaGetSymbolAddress((void**)&zx,  g_zxbcdt);
    cudaGetSymbolAddress((void**)&gB,  g_Bv);
    cudaGetSymbolAddress((void**)&gC,  g_Cv);
    cudaGetSymbolAddress((void**)&gG,  g_G);
    cudaGetSymbolAddress((void**)&uh,  g_uh);
    cudaGetSymbolAddress((void**)&ul,  g_ul);
    cudaGetSymbolAddress((void**)&w1h, g_w1h);
    cudaGetSymbolAddress((void**)&w1l, g_w1l);
    cudaGetSymbolAddress((void**)&ynh, g_ynh);
    cudaGetSymbolAddress((void**)&ynl, g_ynl);
    cudaGetSymbolAddress((void**)&w2h, g_w2h);
    cudaGetSymbolAddress((void**)&w2l, g_w2l);

    cudaFuncSetAttribute(mma_gemm_nt, cudaFuncAttributeMaxDynamicSharedMemorySize, 3 * GST);

    // 0) fp32 -> bf16 hi/lo splits
    {
        long n1 = (long)NROWS * DMODEL;
        split_kernel<<<(unsigned)((n1 + 255) / 256), 256>>>(u, uh, ul, n1);
        long n2 = (long)DINPROJ * DMODEL;
        split_kernel<<<(unsigned)((n2 + 255) / 256), 256>>>(in_proj_w, w1h, w1l, n2);
        long n3 = (long)DMODEL * DINNER;
        split_kernel<<<(unsigned)((n3 + 255) / 256), 256>>>(out_proj_w, w2h, w2l, n3);
    }

    // 1) in_proj: M=8192, N=8352, K=2048
    mma_gemm_nt<<<dim3((DINPROJ + 127) / 128, NROWS / 128), 512, 3 * GST>>>(
        uh, ul, w1h, w1l, in_proj_b, zx, DINPROJ, DMODEL);

    // 2) dt softplus + dA
    dt_kernel<<<(NROWS * NHEADS) / 256, 256>>>(dt_bias, A_log);

    // 3) causal conv + silu + split (x*dt, B, C)
    {
        long total = (long)NROWS * CONVDIM;
        conv_kernel<<<(unsigned)((total + 255) / 256), 256>>>(conv_w, conv_b);
    }

    // 4) per-chunk cumsum of dA
    cumsum_kernel<<<dim3(NCHUNK, NHEADS, BATCH), CHUNKT>>>();

    // 5) G = C @ B^T per (b,chunk)
    sgemm_nt<<<dim3(2, 2, BATCH * NCHUNK), 256>>>(
        gC, gB, nullptr, gG, CHUNKT, DSTATE,
        (long)CHUNKT * DSTATE, (long)CHUNKT * DSTATE, (long)CHUNKT * CHUNKT);

    // 6) chunk-local states
    states_kernel<<<dim3(NHEADS, NCHUNK, BATCH), 256>>>();

    // 7) inter-chunk scan
    scan_kernel<<<BATCH * NHEADS, 256>>>();

    // 8) fused Y_diag + Y_off
    yfused_kernel<<<dim3(NHEADS, NCHUNK, BATCH), 512>>>();

    // 9) gate + layernorm (+ bf16 split of yn)
    ln_kernel<<<NROWS, 256>>>(ln_w, ln_b);

    // 10) out_proj: M=8192, N=2048, K=4096
    mma_gemm_nt<<<dim3(DMODEL / 128, NROWS / 128), 512, 3 * GST>>>(
        ynh, ynl, w2h, w2l, out_proj_b, out, DMODEL, DINNER);
}

// round 6
// speedup vs baseline: 2.6711x; 1.1415x over previous
#include <cuda_runtime.h>
#include <cuda_bf16.h>
#include <cstdint>
#include <math.h>

#define BATCH   2
#define SEQLEN  4096
#define DMODEL  2048
#define DINNER  4096
#define NHEADS  32
#define HEADDIM 128
#define DSTATE  64
#define NCHUNK  16
#define CHUNKT  256
#define CONVDIM 4224
#define DINPROJ 8352
#define NROWS   (BATCH*SEQLEN)
#define LN_EPS  1e-5f

// ---------------- scratch (device globals; no allocations allowed) ----------------
__device__ float g_zxbcdt[(size_t)NROWS * DINPROJ];
__device__ float g_xdt  [(size_t)NROWS * DINNER];
__device__ float g_Bv   [NROWS * DSTATE];
__device__ float g_Cv   [NROWS * DSTATE];
__device__ float g_dt   [NROWS * NHEADS];
__device__ float g_dA   [NROWS * NHEADS];
__device__ float g_Acum [BATCH * NHEADS * SEQLEN];
__device__ float g_G    [(size_t)BATCH * NCHUNK * CHUNKT * CHUNKT];
__device__ float g_states[(size_t)BATCH * NCHUNK * NHEADS * HEADDIM * DSTATE];
__device__ float g_prefix[(size_t)BATCH * NCHUNK * NHEADS * HEADDIM * DSTATE];
__device__ float g_y    [(size_t)NROWS * DINNER];

// bf16 split buffers
__device__ __nv_bfloat16 g_uh [(size_t)NROWS * DMODEL];
__device__ __nv_bfloat16 g_ul [(size_t)NROWS * DMODEL];
__device__ __nv_bfloat16 g_w1h[(size_t)DINPROJ * DMODEL];
__device__ __nv_bfloat16 g_w1l[(size_t)DINPROJ * DMODEL];
__device__ __nv_bfloat16 g_ynh[(size_t)NROWS * DINNER];
__device__ __nv_bfloat16 g_ynl[(size_t)NROWS * DINNER];
__device__ __nv_bfloat16 g_w2h[(size_t)DMODEL * DINNER];
__device__ __nv_bfloat16 g_w2l[(size_t)DMODEL * DINNER];
__device__ __nv_bfloat16 g_xh [(size_t)NROWS * DINNER];   // bf16 hi of xdt
__device__ __nv_bfloat16 g_xl [(size_t)NROWS * DINNER];   // bf16 lo of xdt

__device__ __forceinline__ float siluf(float x) { return x / (1.f + __expf(-x)); }

__device__ __forceinline__ uint32_t smem_u32(const void* p) {
    uint32_t a;
    asm("{ .reg .u64 t; cvta.to.shared.u64 t, %1; cvt.u32.u64 %0, t; }" : "=r"(a) : "l"(p));
    return a;
}

// pack two floats into bf16x2 hi; return hi, write lo
__device__ __forceinline__ uint32_t pack2(float a, float b, uint32_t& lo) {
    __nv_bfloat16 ha = __float2bfloat16(a), hb = __float2bfloat16(b);
    __nv_bfloat16 la = __float2bfloat16(a - __bfloat162float(ha));
    __nv_bfloat16 lb = __float2bfloat16(b - __bfloat162float(hb));
    lo = (uint32_t)__bfloat16_as_ushort(la) | ((uint32_t)__bfloat16_as_ushort(lb) << 16);
    return (uint32_t)__bfloat16_as_ushort(ha) | ((uint32_t)__bfloat16_as_ushort(hb) << 16);
}

// ================= split fp32 -> bf16 hi/lo =================
__global__ void split_kernel(const float* __restrict__ src,
                             __nv_bfloat16* __restrict__ hi,
                             __nv_bfloat16* __restrict__ lo, long n)
{
    long i = (long)blockIdx.x * blockDim.x + threadIdx.x;
    if (i >= n) return;
    float x = src[i];
    __nv_bfloat16 h = __float2bfloat16(x);
    hi[i] = h;
    lo[i] = __float2bfloat16(x - __bfloat162float(h));
}

// ================= tensor-core primitives =================
__device__ __forceinline__ void mma16816(float* c, const uint32_t* a, uint32_t b0, uint32_t b1)
{
    asm volatile(
        "mma.sync.aligned.m16n8k16.row.col.f32.bf16.bf16.f32 "
        "{%0,%1,%2,%3}, {%4,%5,%6,%7}, {%8,%9}, {%0,%1,%2,%3};"
        : "+f"(c[0]), "+f"(c[1]), "+f"(c[2]), "+f"(c[3])
        : "r"(a[0]), "r"(a[1]), "r"(a[2]), "r"(a[3]), "r"(b0), "r"(b1));
}
#define LDSM_X4(r0, r1, r2, r3, addr) \
    asm volatile("ldmatrix.sync.aligned.m8n8.x4.shared.b16 {%0,%1,%2,%3}, [%4];" \
                 : "=r"(r0), "=r"(r1), "=r"(r2), "=r"(r3) : "r"(addr))
#define LDSM_X4_T(r0, r1, r2, r3, addr) \
    asm volatile("ldmatrix.sync.aligned.m8n8.x4.trans.shared.b16 {%0,%1,%2,%3}, [%4];" \
                 : "=r"(r0), "=r"(r1), "=r"(r2), "=r"(r3) : "r"(addr))
#define CP16(dst, src, sz) \
    asm volatile("cp.async.cg.shared.global [%0], [%1], 16, %2;" \
                 :: "r"(dst), "l"(src), "r"(sz))
#define CP_COMMIT() asm volatile("cp.async.commit_group;" ::: "memory")
#define CP_WAIT1()  asm volatile("cp.async.wait_group 1;" ::: "memory")
#define CP_WAIT0()  asm volatile("cp.async.wait_group 0;" ::: "memory")

// ================= split-bf16 tensor-core GEMM: C = A*B^T + bias =================
#define GST 65536
__global__ void __launch_bounds__(512, 1)
mma_gemm_nt(const __nv_bfloat16* __restrict__ Ah, const __nv_bfloat16* __restrict__ Al,
            const __nv_bfloat16* __restrict__ Bh, const __nv_bfloat16* __restrict__ Bl,
            const float* __restrict__ bias, float* __restrict__ C, int N, int K)
{
    extern __shared__ char smem[];
    const uint32_t sb = smem_u32(smem);
    const int tid = threadIdx.x, lane = tid & 31, wid = tid >> 5;
    const int wr = wid >> 2, wc = wid & 3;
    const int mbase = blockIdx.y * 128;
    const int nbase = blockIdx.x * 128;

    const int r = tid >> 2, u0 = (tid & 3) * 2;
    const bool bval = (nbase + r) < N;
    const uint32_t bsz = bval ? 16u : 0u;
    const __nv_bfloat16* gAh = Ah + (size_t)(mbase + r) * K + u0 * 8;
    const __nv_bfloat16* gAl = Al + (size_t)(mbase + r) * K + u0 * 8;
    const __nv_bfloat16* gBh = Bh + (size_t)(bval ? nbase + r : 0) * K + u0 * 8;
    const __nv_bfloat16* gBl = Bl + (size_t)(bval ? nbase + r : 0) * K + u0 * 8;
    const uint32_t d0 = r * 128 + (( u0      ^ (r & 7)) * 16);
    const uint32_t d1 = r * 128 + (((u0 + 1) ^ (r & 7)) * 16);

    auto issue = [&](int st, int kt) {
        uint32_t s0 = sb + st * GST;
        CP16(s0 + d0,         gAh + kt,     16);
        CP16(s0 + d1,         gAh + kt + 8, 16);
        CP16(s0 + 16384 + d0, gAl + kt,     16);
        CP16(s0 + 16384 + d1, gAl + kt + 8, 16);
        CP16(s0 + 32768 + d0, gBh + kt,     bsz);
        CP16(s0 + 32768 + d1, gBh + kt + 8, bsz);
        CP16(s0 + 49152 + d0, gBl + kt,     bsz);
        CP16(s0 + 49152 + d1, gBl + kt + 8, bsz);
        CP_COMMIT();
    };

    float acc[2][4][4];
#pragma unroll
    for (int mt = 0; mt < 2; mt++)
#pragma unroll
        for (int nt = 0; nt < 4; nt++)
#pragma unroll
            for (int i = 0; i < 4; i++) acc[mt][nt][i] = 0.f;

    const int nk = K >> 6;
    issue(0, 0);
    issue(1, 64);

    const int g = lane >> 3, li = lane & 7;
    const int arow_lo = (g & 1) * 8 + li;
    const int ahalf   = g >> 1;
    const int brow_lo = (g >> 1) * 8 + li;
    const int bhalf   = g & 1;

    int stage = 0;
    for (int c = 0; c < nk; c++) {
        if (c + 1 < nk) CP_WAIT1(); else CP_WAIT0();
        __syncthreads();
        if (c + 2 < nk) {
            int st = stage + 2; if (st >= 3) st -= 3;
            issue(st, (c + 2) * 64);
        }
        const uint32_t s0 = sb + stage * GST;
#pragma unroll
        for (int s = 0; s < 4; s++) {
            uint32_t afh[2][4], afl[2][4];
#pragma unroll
            for (int mt = 0; mt < 2; mt++) {
                int row = wr * 32 + mt * 16 + arow_lo;
                uint32_t off = row * 128 + (((2 * s + ahalf) ^ (row & 7)) * 16);
                LDSM_X4(afh[mt][0], afh[mt][1], afh[mt][2], afh[mt][3], s0 + off);
                LDSM_X4(afl[mt][0], afl[mt][1], afl[mt][2], afl[mt][3], s0 + 16384 + off);
            }
#pragma unroll
            for (int ntp = 0; ntp < 2; ntp++) {
                int row = wc * 32 + ntp * 16 + brow_lo;
                uint32_t off = row * 128 + (((2 * s + bhalf) ^ (row & 7)) * 16);
                uint32_t bh0, bh1, bh2, bh3, bl0, bl1, bl2, bl3;
                LDSM_X4(bh0, bh1, bh2, bh3, s0 + 32768 + off);
                LDSM_X4(bl0, bl1, bl2, bl3, s0 + 49152 + off);
#pragma unroll
                for (int mt = 0; mt < 2; mt++) {
                    mma16816(acc[mt][2*ntp+0], afh[mt], bh0, bh1);
                    mma16816(acc[mt][2*ntp+0], afh[mt], bl0, bl1);
                    mma16816(acc[mt][2*ntp+0], afl[mt], bh0, bh1);
                    mma16816(acc[mt][2*ntp+1], afh[mt], bh2, bh3);
                    mma16816(acc[mt][2*ntp+1], afh[mt], bl2, bl3);
                    mma16816(acc[mt][2*ntp+1], afl[mt], bh2, bh3);
                }
            }
        }
        stage++; if (stage >= 3) stage -= 3;
    }

#pragma unroll
    for (int mt = 0; mt < 2; mt++) {
        int r0 = mbase + wr * 32 + mt * 16 + (lane >> 2);
#pragma unroll
        for (int nt = 0; nt < 4; nt++) {
            int col = nbase + wc * 32 + nt * 8 + (lane & 3) * 2;
            if (col < N) {
                float b0 = bias ? bias[col] : 0.f;
                float b1 = bias ? bias[col + 1] : 0.f;
                float2 v0 = make_float2(acc[mt][nt][0] + b0, acc[mt][nt][1] + b1);
                float2 v1 = make_float2(acc[mt][nt][2] + b0, acc[mt][nt][3] + b1);
                *(float2*)(C + (size_t)r0 * N + col)       = v0;
                *(float2*)(C + (size_t)(r0 + 8) * N + col) = v1;
            }
        }
    }
}

// ---------------- small fp32 NT GEMM (G = C @ B^T) ----------------
__global__ void __launch_bounds__(256)
sgemm_nt(const float* __restrict__ A, const float* __restrict__ B,
         const float* __restrict__ bias, float* __restrict__ C,
         int N, int K, long sA, long sB, long sC)
{
    __shared__ float As[16][128];
    __shared__ float Bs[16][128];
    const int tid  = threadIdx.x;
    const int tcol = tid & 15;
    const int trow = tid >> 4;
    const float* Ab = A + (size_t)blockIdx.z * sA + (size_t)blockIdx.y * 128 * K;
    const float* Bb = B + (size_t)blockIdx.z * sB + (size_t)blockIdx.x * 128 * K;
    const int nbase = blockIdx.x * 128;

    float acc[8][8];
#pragma unroll
    for (int m = 0; m < 8; m++)
#pragma unroll
        for (int n = 0; n < 8; n++) acc[m][n] = 0.f;

    const int lrow = tid >> 2;
    const int lcol = (tid & 3) * 4;

    for (int kt = 0; kt < K; kt += 16) {
#pragma unroll
        for (int it = 0; it < 2; it++) {
            int r = lrow + it * 64;
            float4 va = *(const float4*)(Ab + (size_t)r * K + kt + lcol);
            As[lcol+0][r] = va.x; As[lcol+1][r] = va.y;
            As[lcol+2][r] = va.z; As[lcol+3][r] = va.w;
            float4 vb;
            if (nbase + r < N) vb = *(const float4*)(Bb + (size_t)r * K + kt + lcol);
            else               vb = make_float4(0.f, 0.f, 0.f, 0.f);
            Bs[lcol+0][r] = vb.x; Bs[lcol+1][r] = vb.y;
            Bs[lcol+2][r] = vb.z; Bs[lcol+3][r] = vb.w;
        }
        __syncthreads();
#pragma unroll
        for (int k = 0; k < 16; k++) {
            float ra[8], rb[8];
#pragma unroll
            for (int m = 0; m < 8; m++) ra[m] = As[k][trow * 8 + m];
#pragma unroll
            for (int n = 0; n < 8; n++) rb[n] = Bs[k][tcol * 8 + n];
#pragma unroll
            for (int m = 0; m < 8; m++)
#pragma unroll
                for (int n = 0; n < 8; n++) acc[m][n] = fmaf(ra[m], rb[n], acc[m][n]);
        }
        __syncthreads();
    }
#pragma unroll
    for (int m = 0; m < 8; m++) {
        int row = blockIdx.y * 128 + trow * 8 + m;
#pragma unroll
        for (int n = 0; n < 8; n++) {
            int col = nbase + tcol * 8 + n;
            if (col < N) {
                float bv = bias ? bias[col] : 0.f;
                C[(size_t)blockIdx.z * sC + (size_t)row * N + col] = acc[m][n] + bv;
            }
        }
    }
}

// ---------------- dt: softplus(dt_raw + bias), dA = -exp(A_log)*dt ----------------
__global__ void dt_kernel(const float* __restrict__ dt_bias, const float* __restrict__ A_log)
{
    int idx = blockIdx.x * blockDim.x + threadIdx.x;
    if (idx >= NROWS * NHEADS) return;
    int h = idx & (NHEADS - 1);
    int r = idx >> 5;
    float v = g_zxbcdt[(size_t)r * DINPROJ + DINNER + CONVDIM + h] + dt_bias[h];
    float dt = (v > 20.f) ? v : log1pf(__expf(v));
    g_dt[idx] = dt;
    g_dA[idx] = -__expf(A_log[h]) * dt;
}

// ---------------- causal depthwise conv + SiLU; split x*dt (fp32 + bf16 hi/lo) / B / C ----
__global__ void conv_kernel(const float* __restrict__ w, const float* __restrict__ cb)
{
    long idx = (long)blockIdx.x * blockDim.x + threadIdx.x;
    if (idx >= (long)NROWS * CONVDIM) return;
    int c = (int)(idx % CONVDIM);
    int r = (int)(idx / CONVDIM);
    int l = r & (SEQLEN - 1);
    float acc = cb[c];
#pragma unroll
    for (int k = 0; k < 4; k++) {
        int lp = l - 3 + k;
        if (lp >= 0)
            acc = fmaf(w[c * 4 + k], g_zxbcdt[(size_t)(r - 3 + k) * DINPROJ + DINNER + c], acc);
    }
    float out = siluf(acc);
    if (c < DINNER) {
        float v = out * g_dt[r * NHEADS + (c >> 7)];
        size_t o = (size_t)r * DINNER + c;
        g_xdt[o] = v;
        __nv_bfloat16 h = __float2bfloat16(v);
        g_xh[o] = h;
        g_xl[o] = __float2bfloat16(v - __bfloat162float(h));
    } else if (c < DINNER + DSTATE) {
        g_Bv[r * DSTATE + (c - DINNER)] = out;
    } else {
        g_Cv[r * DSTATE + (c - DINNER - DSTATE)] = out;
    }
}

// ---------------- per-chunk inclusive cumsum of dA ----------------
__global__ void cumsum_kernel()
{
    int c = blockIdx.x, h = blockIdx.y, b = blockIdx.z;
    int t = threadIdx.x;
    __shared__ float s[CHUNKT];
    int row = b * SEQLEN + c * CHUNKT + t;
    s[t] = g_dA[row * NHEADS + h];
    __syncthreads();
#pragma unroll
    for (int off = 1; off < CHUNKT; off <<= 1) {
        float x = (t >= off) ? s[t - off] : 0.f;
        __syncthreads();
        s[t] += x;
        __syncthreads();
    }
    g_Acum[(b * NHEADS + h) * SEQLEN + c * CHUNKT + t] = s[t];
}

// ---------------- chunk-local states (FFMA) ----------------
__global__ void __launch_bounds__(256) states_kernel()
{
    int h = blockIdx.x, c = blockIdx.y, b = blockIdx.z;
    __shared__ float Xs[16][128];
    __shared__ float Bsc[16][64];
    __shared__ float Ac[CHUNKT];
    int tid = threadIdx.x;
    Ac[tid] = g_Acum[(b * NHEADS + h) * SEQLEN + c * CHUNKT + tid];
    __syncthreads();
    float Atot = Ac[CHUNKT - 1];
    int brow = b * SEQLEN + c * CHUNKT;
    int tp = tid >> 3, tn = tid & 7;
    float acc[4][8];
#pragma unroll
    for (int m = 0; m < 4; m++)
#pragma unroll
        for (int n = 0; n < 8; n++) acc[m][n] = 0.f;

    for (int lt = 0; lt < CHUNKT; lt += 16) {
#pragma unroll
        for (int q = 0; q < 8; q++) {
            int idx = tid + q * 256;
            int ll = idx >> 7, p = idx & 127;
            Xs[ll][p] = g_xdt[(size_t)(brow + lt + ll) * DINNER + h * HEADDIM + p];
        }
#pragma unroll
        for (int q = 0; q < 4; q++) {
            int idx = tid + q * 256;
            int ll = idx >> 6, n = idx & 63;
            Bsc[ll][n] = g_Bv[(brow + lt + ll) * DSTATE + n] * __expf(Atot - Ac[lt + ll]);
        }
        __syncthreads();
#pragma unroll
        for (int l = 0; l < 16; l++) {
            float ra[4], rb[8];
#pragma unroll
            for (int m = 0; m < 4; m++) ra[m] = Xs[l][tp * 4 + m];
#pragma unroll
            for (int n = 0; n < 8; n++) rb[n] = Bsc[l][tn * 8 + n];
#pragma unroll
            for (int m = 0; m < 4; m++)
#pragma unroll
                for (int n = 0; n < 8; n++) acc[m][n] = fmaf(ra[m], rb[n], acc[m][n]);
        }
        __syncthreads();
    }
    size_t base = ((size_t)((b * NCHUNK + c) * NHEADS + h)) * HEADDIM * DSTATE;
#pragma unroll
    for (int m = 0; m < 4; m++)
#pragma unroll
        for (int n = 0; n < 8; n++)
            g_states[base + (size_t)(tp * 4 + m) * DSTATE + tn * 8 + n] = acc[m][n];
}

// ---------------- inter-chunk state scan ----------------
__global__ void scan_kernel()
{
    int bh = blockIdx.x;
    int b = bh >> 5, h = bh & 31;
    int t = threadIdx.x;
    float S[32];
#pragma unroll
    for (int i = 0; i < 32; i++) S[i] = 0.f;
    for (int c = 0; c < NCHUNK; c++) {
        size_t base = ((size_t)((b * NCHUNK + c) * NHEADS + h)) * (HEADDIM * DSTATE) + (size_t)t * 32;
#pragma unroll
        for (int i = 0; i < 32; i++) g_prefix[base + i] = S[i];
        float f = __expf(g_Acum[(b * NHEADS + h) * SEQLEN + c * CHUNKT + CHUNKT - 1]);
#pragma unroll
        for (int i = 0; i < 32; i++) S[i] = S[i] * f + g_states[base + i];
    }
}

// ================= fused Y on tensor cores (split-bf16) =================
// Block (h,c,b): Y[256 i][128 p] = W @ X + Ce @ S^T
//   W[i][j] = [j<=i] exp(Ac[i]-Ac[j]) G[i][j]   (staged fp32->hi/lo, A operand)
//   X[j][p] bf16 hi/lo (k-major storage -> B via ldmatrix.trans)
//   Ce[i][n] = C[i][n]*exp(Ac[i]) (A operand), S[p][n] = prefix (B non-trans)
// smem: WH 0 (32K) | WL 32768 | XH 65536 (16K) | XL 81920 | Ac 98304 | eAc 99328
#define YSMEM 100352
__global__ void __launch_bounds__(512, 1) yfused_mma()
{
    extern __shared__ char ysm[];
    const uint32_t sb = smem_u32(ysm);
    float* Ac  = (float*)(ysm + 98304);
    float* eAc = (float*)(ysm + 99328);
    const int h = blockIdx.x, c = blockIdx.y, b = blockIdx.z;
    const int tid = threadIdx.x, lane = tid & 31, wid = tid >> 5;
    const int wr = wid >> 2, wc = wid & 3;     // warp tile 64(i) x 32(p)
    const int brow = b * SEQLEN + c * CHUNKT;
    const size_t gbase = (size_t)(b * NCHUNK + c) * CHUNKT * CHUNKT;
    const size_t sbase = ((size_t)((b * NCHUNK + c) * NHEADS + h)) * (HEADDIM * DSTATE);

    if (tid < CHUNKT) {
        float a = g_Acum[(b * NHEADS + h) * SEQLEN + c * CHUNKT + tid];
        Ac[tid] = a;
        eAc[tid] = __expf(a);
    }

    float acc[4][4][4];
#pragma unroll
    for (int mt = 0; mt < 4; mt++)
#pragma unroll
        for (int nt = 0; nt < 4; nt++)
#pragma unroll
            for (int i = 0; i < 4; i++) acc[mt][nt][i] = 0.f;

    const int g = lane >> 3, li = lane & 7;
    const int arow  = (g & 1) * 8 + li;   // A non-trans: row-lo
    const int ahalf = g >> 1;             // A non-trans: k-half
    const int bkt   = (g & 1) * 8 + li;   // B trans: k-row-lo
    const int bnt   = (g >> 1) * 8;       // B trans: n-col-half
    const int brw2  = (g >> 1) * 8 + li;  // B non-trans: n-row-lo
    const int bhf2  = g & 1;              // B non-trans: k-half

    // ---- part 1: W @ X over 4 j-tiles of 64 ----
    for (int jt = 0; jt < CHUNKT; jt += 64) {
        __syncthreads();   // prev compute done (and Ac ready for jt=0)
        // stage W (256 x 64) hi/lo
        for (int idx = tid; idx < 256 * 16; idx += 512) {
            int i = idx >> 4, u4 = idx & 15;
            float4 gv = *(const float4*)&g_G[gbase + (size_t)i * 256 + jt + u4 * 4];
            float ai = Ac[i];
            int j0 = jt + u4 * 4;
            float v0 = (j0 + 0 <= i) ? __expf(ai - Ac[j0 + 0]) * gv.x : 0.f;
            float v1 = (j0 + 1 <= i) ? __expf(ai - Ac[j0 + 1]) * gv.y : 0.f;
            float v2 = (j0 + 2 <= i) ? __expf(ai - Ac[j0 + 2]) * gv.z : 0.f;
            float v3 = (j0 + 3 <= i) ? __expf(ai - Ac[j0 + 3]) * gv.w : 0.f;
            uint32_t lo01, lo23;
            uint32_t hi01 = pack2(v0, v1, lo01);
            uint32_t hi23 = pack2(v2, v3, lo23);
            uint32_t base = i * 128 + (((u4 >> 1) ^ (i & 7)) * 16) + (u4 & 1) * 8;
            *(uint2*)(ysm + base)         = make_uint2(hi01, hi23);
            *(uint2*)(ysm + 32768 + base) = make_uint2(lo01, lo23);
        }
        // stage X rows jt..jt+63 (bf16, [j][p], 256B rows)
        for (int idx = tid; idx < 64 * 16; idx += 512) {
            int l = idx >> 4, u = idx & 15;
            size_t src = (size_t)(brow + jt + l) * DINNER + h * HEADDIM + u * 8;
            uint32_t dst = l * 256 + ((u ^ (l & 7)) * 16);
            *(uint4*)(ysm + 65536 + dst) = *(const uint4*)(g_xh + src);
            *(uint4*)(ysm + 81920 + dst) = *(const uint4*)(g_xl + src);
        }
        __syncthreads();
        if (wr * 64 + 63 >= jt) {
#pragma unroll
            for (int s = 0; s < 4; s++) {
                uint32_t afh[4][4], afl[4][4];
#pragma unroll
                for (int mt = 0; mt < 4; mt++) {
                    int row = wr * 64 + mt * 16 + arow;
                    uint32_t off = row * 128 + (((2 * s + ahalf) ^ (row & 7)) * 16);
                    LDSM_X4(afh[mt][0], afh[mt][1], afh[mt][2], afh[mt][3], sb + off);
                    LDSM_X4(afl[mt][0], afl[mt][1], afl[mt][2], afl[mt][3], sb + 32768 + off);
                }
#pragma unroll
                for (int ntp = 0; ntp < 2; ntp++) {
                    int krow = s * 16 + bkt;
                    int p = wc * 32 + ntp * 16 + bnt;
                    uint32_t off = krow * 256 + (((p >> 3) ^ (krow & 7)) * 16);
                    uint32_t bh0, bh1, bh2, bh3, bl0, bl1, bl2, bl3;
                    LDSM_X4_T(bh0, bh1, bh2, bh3, sb + 65536 + off);
                    LDSM_X4_T(bl0, bl1, bl2, bl3, sb + 81920 + off);
#pragma unroll
                    for (int mt = 0; mt < 4; mt++) {
                        mma16816(acc[mt][2*ntp+0], afh[mt], bh0, bh1);
                        mma16816(acc[mt][2*ntp+0], afh[mt], bl0, bl1);
                        mma16816(acc[mt][2*ntp+0], afl[mt], bh0, bh1);
                        mma16816(acc[mt][2*ntp+1], afh[mt], bh2, bh3);
                        mma16816(acc[mt][2*ntp+1], afh[mt], bl2, bl3);
                        mma16816(acc[mt][2*ntp+1], afl[mt], bh2, bh3);
                    }
                }
            }
        }
    }

    // ---- part 2: Ce @ S^T (K = 64) ----
    __syncthreads();
    for (int idx = tid; idx < 256 * 16; idx += 512) {
        int i = idx >> 4, u4 = idx & 15;
        float4 cv = *(const float4*)&g_Cv[(size_t)(brow + i) * 64 + u4 * 4];
        float e = eAc[i];
        uint32_t lo01, lo23;
        uint32_t hi01 = pack2(cv.x * e, cv.y * e, lo01);
        uint32_t hi23 = pack2(cv.z * e, cv.w * e, lo23);
        uint32_t base = i * 128 + (((u4 >> 1) ^ (i & 7)) * 16) + (u4 & 1) * 8;
        *(uint2*)(ysm + base)         = make_uint2(hi01, hi23);
        *(uint2*)(ysm + 32768 + base) = make_uint2(lo01, lo23);
    }
    for (int idx = tid; idx < 128 * 16; idx += 512) {
        int p = idx >> 4, u4 = idx & 15;
        float4 sv = *(const float4*)&g_prefix[sbase + (size_t)p * 64 + u4 * 4];
        uint32_t lo01, lo23;
        uint32_t hi01 = pack2(sv.x, sv.y, lo01);
        uint32_t hi23 = pack2(sv.z, sv.w, lo23);
        uint32_t base = p * 128 + (((u4 >> 1) ^ (p & 7)) * 16) + (u4 & 1) * 8;
        *(uint2*)(ysm + 65536 + base) = make_uint2(hi01, hi23);
        *(uint2*)(ysm + 81920 + base) = make_uint2(lo01, lo23);
    }
    __syncthreads();
#pragma unroll
    for (int s = 0; s < 4; s++) {
        uint32_t afh[4][4], afl[4][4];
#pragma unroll
        for (int mt = 0; mt < 4; mt++) {
            int row = wr * 64 + mt * 16 + arow;
            uint32_t off = row * 128 + (((2 * s + ahalf) ^ (row & 7)) * 16);
            LDSM_X4(afh[mt][0], afh[mt][1], afh[mt][2], afh[mt][3], sb + off);
            LDSM_X4(afl[mt][0], afl[mt][1], afl[mt][2], afl[mt][3], sb + 32768 + off);
        }
#pragma unroll
        for (int ntp = 0; ntp < 2; ntp++) {
            int row = wc * 32 + ntp * 16 + brw2;
            uint32_t off = row * 128 + (((2 * s + bhf2) ^ (row & 7)) * 16);
            uint32_t bh0, bh1, bh2, bh3, bl0, bl1, bl2, bl3;
            LDSM_X4(bh0, bh1, bh2, bh3, sb + 65536 + off);
            LDSM_X4(bl0, bl1, bl2, bl3, sb + 81920 + off);
#pragma unroll
            for (int mt = 0; mt < 4; mt++) {
                mma16816(acc[mt][2*ntp+0], afh[mt], bh0, bh1);
                mma16816(acc[mt][2*ntp+0], afh[mt], bl0, bl1);
                mma16816(acc[mt][2*ntp+0], afl[mt], bh0, bh1);
                mma16816(acc[mt][2*ntp+1], afh[mt], bh2, bh3);
                mma16816(acc[mt][2*ntp+1], afh[mt], bl2, bl3);
                mma16816(acc[mt][2*ntp+1], afl[mt], bh2, bh3);
            }
        }
    }

    // ---- epilogue ----
#pragma unroll
    for (int mt = 0; mt < 4; mt++) {
        int i0 = wr * 64 + mt * 16 + (lane >> 2);
#pragma unroll
        for (int nt = 0; nt < 4; nt++) {
            int col = h * HEADDIM + wc * 32 + nt * 8 + (lane & 3) * 2;
            *(float2*)(g_y + (size_t)(brow + i0) * DINNER + col) =
                make_float2(acc[mt][nt][0], acc[mt][nt][1]);
            *(float2*)(g_y + (size_t)(brow + i0 + 8) * DINNER + col) =
                make_float2(acc[mt][nt][2], acc[mt][nt][3]);
        }
    }
}

// ---------------- gating (y * silu(z)) + LayerNorm; emits bf16 hi/lo ----------------
__global__ void __launch_bounds__(256) ln_kernel(const float* __restrict__ lnw, const float* __restrict__ lnb)
{
    int row = blockIdx.x;
    int tid = threadIdx.x;
    float g[16];
    float s = 0.f, s2 = 0.f;
#pragma unroll
    for (int q = 0; q < 16; q++) {
        int i = tid + q * 256;
        float y = g_y[(size_t)row * DINNER + i];
        float z = g_zxbcdt[(size_t)row * DINPROJ + i];
        float v = y * siluf(z);
        g[q] = v; s += v; s2 = fmaf(v, v, s2);
    }
    __shared__ float red[2][8];
#pragma unroll
    for (int off = 16; off > 0; off >>= 1) {
        s  += __shfl_xor_sync(0xffffffffu, s, off);
        s2 += __shfl_xor_sync(0xffffffffu, s2, off);
    }
    if ((tid & 31) == 0) { red[0][tid >> 5] = s; red[1][tid >> 5] = s2; }
    __syncthreads();
    if (tid == 0) {
        float a = 0.f, a2 = 0.f;
#pragma unroll
        for (int w = 0; w < 8; w++) { a += red[0][w]; a2 += red[1][w]; }
        red[0][0] = a; red[1][0] = a2;
    }
    __syncthreads();
    float mu  = red[0][0] * (1.f / DINNER);
    float var = red[1][0] * (1.f / DINNER) - mu * mu;
    float rstd = rsqrtf(var + LN_EPS);
#pragma unroll
    for (int q = 0; q < 16; q++) {
        int i = tid + q * 256;
        float v = (g[q] - mu) * rstd * lnw[i] + lnb[i];
        __nv_bfloat16 h = __float2bfloat16(v);
        g_ynh[(size_t)row * DINNER + i] = h;
        g_ynl[(size_t)row * DINNER + i] = __float2bfloat16(v - __bfloat162float(h));
    }
}

// ---------------- launch ----------------
extern "C" void kernel_launch(void* const* d_in, const int* in_sizes, int n_in,
                              void* d_out, int out_size)
{
    const float* u          = (const float*)d_in[0];
    const float* in_proj_w  = (const float*)d_in[1];
    const float* in_proj_b  = (const float*)d_in[2];
    const float* conv_w     = (const float*)d_in[3];
    const float* conv_b     = (const float*)d_in[4];
    const float* dt_bias    = (const float*)d_in[5];
    const float* A_log      = (const float*)d_in[6];
    const float* ln_w       = (const float*)d_in[7];
    const float* ln_b       = (const float*)d_in[8];
    const float* out_proj_w = (const float*)d_in[9];
    const float* out_proj_b = (const float*)d_in[10];
    float* out = (float*)d_out;

    float *zx, *gB, *gC, *gG;
    __nv_bfloat16 *uh, *ul, *w1h, *w1l, *ynh, *ynl, *w2h, *w2l;
    cudaGetSymbolAddress((void**)&zx,  g_zxbcdt);
    cudaGetSymbolAddress((void**)&gB,  g_Bv);
    cudaGetSymbolAddress((void**)&gC,  g_Cv);
    cudaGetSymbolAddress((void**)&gG,  g_G);
    cudaGetSymbolAddress((void**)&uh,  g_uh);
    cudaGetSymbolAddress((void**)&ul,  g_ul);
    cudaGetSymbolAddress((void**)&w1h, g_w1h);
    cudaGetSymbolAddress((void**)&w1l, g_w1l);
    cudaGetSymbolAddress((void**)&ynh, g_ynh);
    cudaGetSymbolAddress((void**)&ynl, g_ynl);
    cudaGetSymbolAddress((void**)&w2h, g_w2h);
    cudaGetSymbolAddress((void**)&w2l, g_w2l);

    cudaFuncSetAttribute(mma_gemm_nt, cudaFuncAttributeMaxDynamicSharedMemorySize, 3 * GST);
    cudaFuncSetAttribute(yfused_mma, cudaFuncAttributeMaxDynamicSharedMemorySize, YSMEM);

    // 0) fp32 -> bf16 hi/lo splits
    {
        long n1 = (long)NROWS * DMODEL;
        split_kernel<<<(unsigned)((n1 + 255) / 256), 256>>>(u, uh, ul, n1);
        long n2 = (long)DINPROJ * DMODEL;
        split_kernel<<<(unsigned)((n2 + 255) / 256), 256>>>(in_proj_w, w1h, w1l, n2);
        long n3 = (long)DMODEL * DINNER;
        split_kernel<<<(unsigned)((n3 + 255) / 256), 256>>>(out_proj_w, w2h, w2l, n3);
    }

    // 1) in_proj: M=8192, N=8352, K=2048
    mma_gemm_nt<<<dim3((DINPROJ + 127) / 128, NROWS / 128), 512, 3 * GST>>>(
        uh, ul, w1h, w1l, in_proj_b, zx, DINPROJ, DMODEL);

    // 2) dt softplus + dA
    dt_kernel<<<(NROWS * NHEADS) / 256, 256>>>(dt_bias, A_log);

    // 3) causal conv + silu + split
    {
        long total = (long)NROWS * CONVDIM;
        conv_kernel<<<(unsigned)((total + 255) / 256), 256>>>(conv_w, conv_b);
    }

    // 4) per-chunk cumsum of dA
    cumsum_kernel<<<dim3(NCHUNK, NHEADS, BATCH), CHUNKT>>>();

    // 5) G = C @ B^T per (b,chunk)
    sgemm_nt<<<dim3(2, 2, BATCH * NCHUNK), 256>>>(
        gC, gB, nullptr, gG, CHUNKT, DSTATE,
        (long)CHUNKT * DSTATE, (long)CHUNKT * DSTATE, (long)CHUNKT * CHUNKT);

    // 6) chunk-local states
    states_kernel<<<dim3(NHEADS, NCHUNK, BATCH), 256>>>();

    // 7) inter-chunk scan
    scan_kernel<<<BATCH * NHEADS, 256>>>();

    // 8) fused Y on tensor cores
    yfused_mma<<<dim3(NHEADS, NCHUNK, BATCH), 512, YSMEM>>>();

    // 9) gate + layernorm (+ bf16 split of yn)
    ln_kernel<<<NROWS, 256>>>(ln_w, ln_b);

    // 10) out_proj: M=8192, N=2048, K=4096
    mma_gemm_nt<<<dim3(DMODEL / 128, NROWS / 128), 512, 3 * GST>>>(
        ynh, ynl, w2h, w2l, out_proj_b, out, DMODEL, DINNER);
}

// round 7
// speedup vs baseline: 3.3880x; 1.2684x over previous
#include <cuda_runtime.h>
#include <cuda_bf16.h>
#include <cuda_fp16.h>
#include <cstdint>
#include <math.h>

#define BATCH   2
#define SEQLEN  4096
#define DMODEL  2048
#define DINNER  4096
#define NHEADS  32
#define HEADDIM 128
#define DSTATE  64
#define NCHUNK  16
#define CHUNKT  256
#define CONVDIM 4224
#define DINPROJ 8352
#define NROWS   (BATCH*SEQLEN)
#define LN_EPS  1e-5f

// ---------------- scratch (device globals; no allocations allowed) ----------------
__device__ float g_zxbcdt[(size_t)NROWS * DINPROJ];
__device__ float g_xdt  [(size_t)NROWS * DINNER];
__device__ float g_Bv   [NROWS * DSTATE];
__device__ float g_Cv   [NROWS * DSTATE];
__device__ float g_dt   [NROWS * NHEADS];
__device__ float g_dA   [NROWS * NHEADS];
__device__ float g_Acum [BATCH * NHEADS * SEQLEN];
__device__ float g_G    [(size_t)BATCH * NCHUNK * CHUNKT * CHUNKT];
__device__ float g_states[(size_t)BATCH * NCHUNK * NHEADS * HEADDIM * DSTATE];
__device__ float g_prefix[(size_t)BATCH * NCHUNK * NHEADS * HEADDIM * DSTATE];
__device__ float g_y    [(size_t)NROWS * DINNER];

// fp16 buffers for dense GEMMs (activations exact hi/lo, weights rounded)
__device__ __half g_uh [(size_t)NROWS * DMODEL];
__device__ __half g_ul [(size_t)NROWS * DMODEL];
__device__ __half g_w1h[(size_t)DINPROJ * DMODEL];
__device__ __half g_ynh[(size_t)NROWS * DINNER];
__device__ __half g_ynl[(size_t)NROWS * DINNER];
__device__ __half g_w2h[(size_t)DMODEL * DINNER];
// bf16 hi/lo of xdt for yfused (3-term path)
__device__ __nv_bfloat16 g_xh [(size_t)NROWS * DINNER];
__device__ __nv_bfloat16 g_xl [(size_t)NROWS * DINNER];

__device__ __forceinline__ float siluf(float x) { return x / (1.f + __expf(-x)); }

__device__ __forceinline__ uint32_t smem_u32(const void* p) {
    uint32_t a;
    asm("{ .reg .u64 t; cvta.to.shared.u64 t, %1; cvt.u32.u64 %0, t; }" : "=r"(a) : "l"(p));
    return a;
}

// pack two floats into bf16x2 hi; return hi, write lo
__device__ __forceinline__ uint32_t pack2(float a, float b, uint32_t& lo) {
    __nv_bfloat16 ha = __float2bfloat16(a), hb = __float2bfloat16(b);
    __nv_bfloat16 la = __float2bfloat16(a - __bfloat162float(ha));
    __nv_bfloat16 lb = __float2bfloat16(b - __bfloat162float(hb));
    lo = (uint32_t)__bfloat16_as_ushort(la) | ((uint32_t)__bfloat16_as_ushort(lb) << 16);
    return (uint32_t)__bfloat16_as_ushort(ha) | ((uint32_t)__bfloat16_as_ushort(hb) << 16);
}

// ================= split kernels =================
__global__ void split_f16(const float* __restrict__ src,
                          __half* __restrict__ hi, __half* __restrict__ lo, long n)
{
    long i = (long)blockIdx.x * blockDim.x + threadIdx.x;
    if (i >= n) return;
    float x = src[i];
    __half h = __float2half_rn(x);
    hi[i] = h;
    lo[i] = __float2half_rn(x - __half2float(h));
}
__global__ void round_f16(const float* __restrict__ src, __half* __restrict__ dst, long n)
{
    long i = (long)blockIdx.x * blockDim.x + threadIdx.x;
    if (i >= n) return;
    dst[i] = __float2half_rn(src[i]);
}

// ================= tensor-core primitives =================
__device__ __forceinline__ void mma16816bf(float* c, const uint32_t* a, uint32_t b0, uint32_t b1)
{
    asm volatile(
        "mma.sync.aligned.m16n8k16.row.col.f32.bf16.bf16.f32 "
        "{%0,%1,%2,%3}, {%4,%5,%6,%7}, {%8,%9}, {%0,%1,%2,%3};"
        : "+f"(c[0]), "+f"(c[1]), "+f"(c[2]), "+f"(c[3])
        : "r"(a[0]), "r"(a[1]), "r"(a[2]), "r"(a[3]), "r"(b0), "r"(b1));
}
__device__ __forceinline__ void mma16816h(float* c, const uint32_t* a, uint32_t b0, uint32_t b1)
{
    asm volatile(
        "mma.sync.aligned.m16n8k16.row.col.f32.f16.f16.f32 "
        "{%0,%1,%2,%3}, {%4,%5,%6,%7}, {%8,%9}, {%0,%1,%2,%3};"
        : "+f"(c[0]), "+f"(c[1]), "+f"(c[2]), "+f"(c[3])
        : "r"(a[0]), "r"(a[1]), "r"(a[2]), "r"(a[3]), "r"(b0), "r"(b1));
}
#define LDSM_X4(r0, r1, r2, r3, addr) \
    asm volatile("ldmatrix.sync.aligned.m8n8.x4.shared.b16 {%0,%1,%2,%3}, [%4];" \
                 : "=r"(r0), "=r"(r1), "=r"(r2), "=r"(r3) : "r"(addr))
#define LDSM_X4_T(r0, r1, r2, r3, addr) \
    asm volatile("ldmatrix.sync.aligned.m8n8.x4.trans.shared.b16 {%0,%1,%2,%3}, [%4];" \
                 : "=r"(r0), "=r"(r1), "=r"(r2), "=r"(r3) : "r"(addr))
#define CP16(dst, src, sz) \
    asm volatile("cp.async.cg.shared.global [%0], [%1], 16, %2;" \
                 :: "r"(dst), "l"(src), "r"(sz))
#define CP_COMMIT() asm volatile("cp.async.commit_group;" ::: "memory")
#define CP_WAIT1()  asm volatile("cp.async.wait_group 1;" ::: "memory")
#define CP_WAIT0()  asm volatile("cp.async.wait_group 0;" ::: "memory")

// ================= fp16 2-MMA GEMM: C = (Ah+Al)*Bh^T + bias =================
// BM=128, BN=128, BK=64, 512 threads (16 warps, 32x32), 3-stage cp.async pipeline.
// A exact fp16 hi/lo (rows M, mult of 128); B rounded fp16 (rows N, guarded).
#define GST 49152
__global__ void __launch_bounds__(512, 1)
mma_gemm_nt(const __half* __restrict__ Ah, const __half* __restrict__ Al,
            const __half* __restrict__ Bh,
            const float* __restrict__ bias, float* __restrict__ C, int N, int K)
{
    extern __shared__ char smem[];
    const uint32_t sb = smem_u32(smem);
    const int tid = threadIdx.x, lane = tid & 31, wid = tid >> 5;
    const int wr = wid >> 2, wc = wid & 3;
    const int mbase = blockIdx.y * 128;
    const int nbase = blockIdx.x * 128;

    const int r = tid >> 2, u0 = (tid & 3) * 2;
    const bool bval = (nbase + r) < N;
    const uint32_t bsz = bval ? 16u : 0u;
    const __half* gAh = Ah + (size_t)(mbase + r) * K + u0 * 8;
    const __half* gAl = Al + (size_t)(mbase + r) * K + u0 * 8;
    const __half* gBh = Bh + (size_t)(bval ? nbase + r : 0) * K + u0 * 8;
    const uint32_t d0 = r * 128 + (( u0      ^ (r & 7)) * 16);
    const uint32_t d1 = r * 128 + (((u0 + 1) ^ (r & 7)) * 16);

    auto issue = [&](int st, int kt) {
        uint32_t s0 = sb + st * GST;
        CP16(s0 + d0,         gAh + kt,     16);
        CP16(s0 + d1,         gAh + kt + 8, 16);
        CP16(s0 + 16384 + d0, gAl + kt,     16);
        CP16(s0 + 16384 + d1, gAl + kt + 8, 16);
        CP16(s0 + 32768 + d0, gBh + kt,     bsz);
        CP16(s0 + 32768 + d1, gBh + kt + 8, bsz);
        CP_COMMIT();
    };

    float acc[2][4][4];
#pragma unroll
    for (int mt = 0; mt < 2; mt++)
#pragma unroll
        for (int nt = 0; nt < 4; nt++)
#pragma unroll
            for (int i = 0; i < 4; i++) acc[mt][nt][i] = 0.f;

    const int nk = K >> 6;
    issue(0, 0);
    issue(1, 64);

    const int g = lane >> 3, li = lane & 7;
    const int arow_lo = (g & 1) * 8 + li;
    const int ahalf   = g >> 1;
    const int brow_lo = (g >> 1) * 8 + li;
    const int bhalf   = g & 1;

    int stage = 0;
    for (int c = 0; c < nk; c++) {
        if (c + 1 < nk) CP_WAIT1(); else CP_WAIT0();
        __syncthreads();
        if (c + 2 < nk) {
            int st = stage + 2; if (st >= 3) st -= 3;
            issue(st, (c + 2) * 64);
        }
        const uint32_t s0 = sb + stage * GST;
#pragma unroll
        for (int s = 0; s < 4; s++) {
            uint32_t afh[2][4], afl[2][4];
#pragma unroll
            for (int mt = 0; mt < 2; mt++) {
                int row = wr * 32 + mt * 16 + arow_lo;
                uint32_t off = row * 128 + (((2 * s + ahalf) ^ (row & 7)) * 16);
                LDSM_X4(afh[mt][0], afh[mt][1], afh[mt][2], afh[mt][3], s0 + off);
                LDSM_X4(afl[mt][0], afl[mt][1], afl[mt][2], afl[mt][3], s0 + 16384 + off);
            }
#pragma unroll
            for (int ntp = 0; ntp < 2; ntp++) {
                int row = wc * 32 + ntp * 16 + brow_lo;
                uint32_t off = row * 128 + (((2 * s + bhalf) ^ (row & 7)) * 16);
                uint32_t bh0, bh1, bh2, bh3;
                LDSM_X4(bh0, bh1, bh2, bh3, s0 + 32768 + off);
#pragma unroll
                for (int mt = 0; mt < 2; mt++) {
                    mma16816h(acc[mt][2*ntp+0], afh[mt], bh0, bh1);
                    mma16816h(acc[mt][2*ntp+0], afl[mt], bh0, bh1);
                    mma16816h(acc[mt][2*ntp+1], afh[mt], bh2, bh3);
                    mma16816h(acc[mt][2*ntp+1], afl[mt], bh2, bh3);
                }
            }
        }
        stage++; if (stage >= 3) stage -= 3;
    }

#pragma unroll
    for (int mt = 0; mt < 2; mt++) {
        int r0 = mbase + wr * 32 + mt * 16 + (lane >> 2);
#pragma unroll
        for (int nt = 0; nt < 4; nt++) {
            int col = nbase + wc * 32 + nt * 8 + (lane & 3) * 2;
            if (col < N) {
                float b0 = bias ? bias[col] : 0.f;
                float b1 = bias ? bias[col + 1] : 0.f;
                float2 v0 = make_float2(acc[mt][nt][0] + b0, acc[mt][nt][1] + b1);
                float2 v1 = make_float2(acc[mt][nt][2] + b0, acc[mt][nt][3] + b1);
                *(float2*)(C + (size_t)r0 * N + col)       = v0;
                *(float2*)(C + (size_t)(r0 + 8) * N + col) = v1;
            }
        }
    }
}

// ---------------- small fp32 NT GEMM (G = C @ B^T) ----------------
__global__ void __launch_bounds__(256)
sgemm_nt(const float* __restrict__ A, const float* __restrict__ B,
         const float* __restrict__ bias, float* __restrict__ C,
         int N, int K, long sA, long sB, long sC)
{
    __shared__ float As[16][128];
    __shared__ float Bs[16][128];
    const int tid  = threadIdx.x;
    const int tcol = tid & 15;
    const int trow = tid >> 4;
    const float* Ab = A + (size_t)blockIdx.z * sA + (size_t)blockIdx.y * 128 * K;
    const float* Bb = B + (size_t)blockIdx.z * sB + (size_t)blockIdx.x * 128 * K;
    const int nbase = blockIdx.x * 128;

    float acc[8][8];
#pragma unroll
    for (int m = 0; m < 8; m++)
#pragma unroll
        for (int n = 0; n < 8; n++) acc[m][n] = 0.f;

    const int lrow = tid >> 2;
    const int lcol = (tid & 3) * 4;

    for (int kt = 0; kt < K; kt += 16) {
#pragma unroll
        for (int it = 0; it < 2; it++) {
            int r = lrow + it * 64;
            float4 va = *(const float4*)(Ab + (size_t)r * K + kt + lcol);
            As[lcol+0][r] = va.x; As[lcol+1][r] = va.y;
            As[lcol+2][r] = va.z; As[lcol+3][r] = va.w;
            float4 vb;
            if (nbase + r < N) vb = *(const float4*)(Bb + (size_t)r * K + kt + lcol);
            else               vb = make_float4(0.f, 0.f, 0.f, 0.f);
            Bs[lcol+0][r] = vb.x; Bs[lcol+1][r] = vb.y;
            Bs[lcol+2][r] = vb.z; Bs[lcol+3][r] = vb.w;
        }
        __syncthreads();
#pragma unroll
        for (int k = 0; k < 16; k++) {
            float ra[8], rb[8];
#pragma unroll
            for (int m = 0; m < 8; m++) ra[m] = As[k][trow * 8 + m];
#pragma unroll
            for (int n = 0; n < 8; n++) rb[n] = Bs[k][tcol * 8 + n];
#pragma unroll
            for (int m = 0; m < 8; m++)
#pragma unroll
                for (int n = 0; n < 8; n++) acc[m][n] = fmaf(ra[m], rb[n], acc[m][n]);
        }
        __syncthreads();
    }
#pragma unroll
    for (int m = 0; m < 8; m++) {
        int row = blockIdx.y * 128 + trow * 8 + m;
#pragma unroll
        for (int n = 0; n < 8; n++) {
            int col = nbase + tcol * 8 + n;
            if (col < N) {
                float bv = bias ? bias[col] : 0.f;
                C[(size_t)blockIdx.z * sC + (size_t)row * N + col] = acc[m][n] + bv;
            }
        }
    }
}

// ---------------- dt: softplus(dt_raw + bias), dA = -exp(A_log)*dt ----------------
__global__ void dt_kernel(const float* __restrict__ dt_bias, const float* __restrict__ A_log)
{
    int idx = blockIdx.x * blockDim.x + threadIdx.x;
    if (idx >= NROWS * NHEADS) return;
    int h = idx & (NHEADS - 1);
    int r = idx >> 5;
    float v = g_zxbcdt[(size_t)r * DINPROJ + DINNER + CONVDIM + h] + dt_bias[h];
    float dt = (v > 20.f) ? v : log1pf(__expf(v));
    g_dt[idx] = dt;
    g_dA[idx] = -__expf(A_log[h]) * dt;
}

// ---------------- causal depthwise conv + SiLU; split x*dt / B / C ----------------
__global__ void conv_kernel(const float* __restrict__ w, const float* __restrict__ cb)
{
    long idx = (long)blockIdx.x * blockDim.x + threadIdx.x;
    if (idx >= (long)NROWS * CONVDIM) return;
    int c = (int)(idx % CONVDIM);
    int r = (int)(idx / CONVDIM);
    int l = r & (SEQLEN - 1);
    float acc = cb[c];
#pragma unroll
    for (int k = 0; k < 4; k++) {
        int lp = l - 3 + k;
        if (lp >= 0)
            acc = fmaf(w[c * 4 + k], g_zxbcdt[(size_t)(r - 3 + k) * DINPROJ + DINNER + c], acc);
    }
    float out = siluf(acc);
    if (c < DINNER) {
        float v = out * g_dt[r * NHEADS + (c >> 7)];
        size_t o = (size_t)r * DINNER + c;
        g_xdt[o] = v;
        __nv_bfloat16 h = __float2bfloat16(v);
        g_xh[o] = h;
        g_xl[o] = __float2bfloat16(v - __bfloat162float(h));
    } else if (c < DINNER + DSTATE) {
        g_Bv[r * DSTATE + (c - DINNER)] = out;
    } else {
        g_Cv[r * DSTATE + (c - DINNER - DSTATE)] = out;
    }
}

// ---------------- per-chunk inclusive cumsum of dA ----------------
__global__ void cumsum_kernel()
{
    int c = blockIdx.x, h = blockIdx.y, b = blockIdx.z;
    int t = threadIdx.x;
    __shared__ float s[CHUNKT];
    int row = b * SEQLEN + c * CHUNKT + t;
    s[t] = g_dA[row * NHEADS + h];
    __syncthreads();
#pragma unroll
    for (int off = 1; off < CHUNKT; off <<= 1) {
        float x = (t >= off) ? s[t - off] : 0.f;
        __syncthreads();
        s[t] += x;
        __syncthreads();
    }
    g_Acum[(b * NHEADS + h) * SEQLEN + c * CHUNKT + t] = s[t];
}

// ---------------- chunk-local states (FFMA) ----------------
__global__ void __launch_bounds__(256) states_kernel()
{
    int h = blockIdx.x, c = blockIdx.y, b = blockIdx.z;
    __shared__ float Xs[16][128];
    __shared__ float Bsc[16][64];
    __shared__ float Ac[CHUNKT];
    int tid = threadIdx.x;
    Ac[tid] = g_Acum[(b * NHEADS + h) * SEQLEN + c * CHUNKT + tid];
    __syncthreads();
    float Atot = Ac[CHUNKT - 1];
    int brow = b * SEQLEN + c * CHUNKT;
    int tp = tid >> 3, tn = tid & 7;
    float acc[4][8];
#pragma unroll
    for (int m = 0; m < 4; m++)
#pragma unroll
        for (int n = 0; n < 8; n++) acc[m][n] = 0.f;

    for (int lt = 0; lt < CHUNKT; lt += 16) {
#pragma unroll
        for (int q = 0; q < 8; q++) {
            int idx = tid + q * 256;
            int ll = idx >> 7, p = idx & 127;
            Xs[ll][p] = g_xdt[(size_t)(brow + lt + ll) * DINNER + h * HEADDIM + p];
        }
#pragma unroll
        for (int q = 0; q < 4; q++) {
            int idx = tid + q * 256;
            int ll = idx >> 6, n = idx & 63;
            Bsc[ll][n] = g_Bv[(brow + lt + ll) * DSTATE + n] * __expf(Atot - Ac[lt + ll]);
        }
        __syncthreads();
#pragma unroll
        for (int l = 0; l < 16; l++) {
            float ra[4], rb[8];
#pragma unroll
            for (int m = 0; m < 4; m++) ra[m] = Xs[l][tp * 4 + m];
#pragma unroll
            for (int n = 0; n < 8; n++) rb[n] = Bsc[l][tn * 8 + n];
#pragma unroll
            for (int m = 0; m < 4; m++)
#pragma unroll
                for (int n = 0; n < 8; n++) acc[m][n] = fmaf(ra[m], rb[n], acc[m][n]);
        }
        __syncthreads();
    }
    size_t base = ((size_t)((b * NCHUNK + c) * NHEADS + h)) * HEADDIM * DSTATE;
#pragma unroll
    for (int m = 0; m < 4; m++)
#pragma unroll
        for (int n = 0; n < 8; n++)
            g_states[base + (size_t)(tp * 4 + m) * DSTATE + tn * 8 + n] = acc[m][n];
}

// ---------------- inter-chunk state scan ----------------
__global__ void scan_kernel()
{
    int bh = blockIdx.x;
    int b = bh >> 5, h = bh & 31;
    int t = threadIdx.x;
    float S[32];
#pragma unroll
    for (int i = 0; i < 32; i++) S[i] = 0.f;
    for (int c = 0; c < NCHUNK; c++) {
        size_t base = ((size_t)((b * NCHUNK + c) * NHEADS + h)) * (HEADDIM * DSTATE) + (size_t)t * 32;
#pragma unroll
        for (int i = 0; i < 32; i++) g_prefix[base + i] = S[i];
        float f = __expf(g_Acum[(b * NHEADS + h) * SEQLEN + c * CHUNKT + CHUNKT - 1]);
#pragma unroll
        for (int i = 0; i < 32; i++) S[i] = S[i] * f + g_states[base + i];
    }
}

// ================= fused Y on tensor cores (split-bf16, 3-term) =================
#define YSMEM 100352
__global__ void __launch_bounds__(512, 1) yfused_mma()
{
    extern __shared__ char ysm[];
    const uint32_t sb = smem_u32(ysm);
    float* Ac  = (float*)(ysm + 98304);
    float* eAc = (float*)(ysm + 99328);
    const int h = blockIdx.x, c = blockIdx.y, b = blockIdx.z;
    const int tid = threadIdx.x, lane = tid & 31, wid = tid >> 5;
    const int wr = wid >> 2, wc = wid & 3;
    const int brow = b * SEQLEN + c * CHUNKT;
    const size_t gbase = (size_t)(b * NCHUNK + c) * CHUNKT * CHUNKT;
    const size_t sbase = ((size_t)((b * NCHUNK + c) * NHEADS + h)) * (HEADDIM * DSTATE);

    if (tid < CHUNKT) {
        float a = g_Acum[(b * NHEADS + h) * SEQLEN + c * CHUNKT + tid];
        Ac[tid] = a;
        eAc[tid] = __expf(a);
    }

    float acc[4][4][4];
#pragma unroll
    for (int mt = 0; mt < 4; mt++)
#pragma unroll
        for (int nt = 0; nt < 4; nt++)
#pragma unroll
            for (int i = 0; i < 4; i++) acc[mt][nt][i] = 0.f;

    const int g = lane >> 3, li = lane & 7;
    const int arow  = (g & 1) * 8 + li;
    const int ahalf = g >> 1;
    const int bkt   = (g & 1) * 8 + li;
    const int bnt   = (g >> 1) * 8;
    const int brw2  = (g >> 1) * 8 + li;
    const int bhf2  = g & 1;

    for (int jt = 0; jt < CHUNKT; jt += 64) {
        __syncthreads();
        for (int idx = tid; idx < 256 * 16; idx += 512) {
            int i = idx >> 4, u4 = idx & 15;
            float4 gv = *(const float4*)&g_G[gbase + (size_t)i * 256 + jt + u4 * 4];
            float ai = Ac[i];
            int j0 = jt + u4 * 4;
            float v0 = (j0 + 0 <= i) ? __expf(ai - Ac[j0 + 0]) * gv.x : 0.f;
            float v1 = (j0 + 1 <= i) ? __expf(ai - Ac[j0 + 1]) * gv.y : 0.f;
            float v2 = (j0 + 2 <= i) ? __expf(ai - Ac[j0 + 2]) * gv.z : 0.f;
            float v3 = (j0 + 3 <= i) ? __expf(ai - Ac[j0 + 3]) * gv.w : 0.f;
            uint32_t lo01, lo23;
            uint32_t hi01 = pack2(v0, v1, lo01);
            uint32_t hi23 = pack2(v2, v3, lo23);
            uint32_t base = i * 128 + (((u4 >> 1) ^ (i & 7)) * 16) + (u4 & 1) * 8;
            *(uint2*)(ysm + base)         = make_uint2(hi01, hi23);
            *(uint2*)(ysm + 32768 + base) = make_uint2(lo01, lo23);
        }
        for (int idx = tid; idx < 64 * 16; idx += 512) {
            int l = idx >> 4, u = idx & 15;
            size_t src = (size_t)(brow + jt + l) * DINNER + h * HEADDIM + u * 8;
            uint32_t dst = l * 256 + ((u ^ (l & 7)) * 16);
            *(uint4*)(ysm + 65536 + dst) = *(const uint4*)(g_xh + src);
            *(uint4*)(ysm + 81920 + dst) = *(const uint4*)(g_xl + src);
        }
        __syncthreads();
        if (wr * 64 + 63 >= jt) {
#pragma unroll
            for (int s = 0; s < 4; s++) {
                uint32_t afh[4][4], afl[4][4];
#pragma unroll
                for (int mt = 0; mt < 4; mt++) {
                    int row = wr * 64 + mt * 16 + arow;
                    uint32_t off = row * 128 + (((2 * s + ahalf) ^ (row & 7)) * 16);
                    LDSM_X4(afh[mt][0], afh[mt][1], afh[mt][2], afh[mt][3], sb + off);
                    LDSM_X4(afl[mt][0], afl[mt][1], afl[mt][2], afl[mt][3], sb + 32768 + off);
                }
#pragma unroll
                for (int ntp = 0; ntp < 2; ntp++) {
                    int krow = s * 16 + bkt;
                    int p = wc * 32 + ntp * 16 + bnt;
                    uint32_t off = krow * 256 + (((p >> 3) ^ (krow & 7)) * 16);
                    uint32_t bh0, bh1, bh2, bh3, bl0, bl1, bl2, bl3;
                    LDSM_X4_T(bh0, bh1, bh2, bh3, sb + 65536 + off);
                    LDSM_X4_T(bl0, bl1, bl2, bl3, sb + 81920 + off);
#pragma unroll
                    for (int mt = 0; mt < 4; mt++) {
                        mma16816bf(acc[mt][2*ntp+0], afh[mt], bh0, bh1);
                        mma16816bf(acc[mt][2*ntp+0], afh[mt], bl0, bl1);
                        mma16816bf(acc[mt][2*ntp+0], afl[mt], bh0, bh1);
                        mma16816bf(acc[mt][2*ntp+1], afh[mt], bh2, bh3);
                        mma16816bf(acc[mt][2*ntp+1], afh[mt], bl2, bl3);
                        mma16816bf(acc[mt][2*ntp+1], afl[mt], bh2, bh3);
                    }
                }
            }
        }
    }

    __syncthreads();
    for (int idx = tid; idx < 256 * 16; idx += 512) {
        int i = idx >> 4, u4 = idx & 15;
        float4 cv = *(const float4*)&g_Cv[(size_t)(brow + i) * 64 + u4 * 4];
        float e = eAc[i];
        uint32_t lo01, lo23;
        uint32_t hi01 = pack2(cv.x * e, cv.y * e, lo01);
        uint32_t hi23 = pack2(cv.z * e, cv.w * e, lo23);
        uint32_t base = i * 128 + (((u4 >> 1) ^ (i & 7)) * 16) + (u4 & 1) * 8;
        *(uint2*)(ysm + base)         = make_uint2(hi01, hi23);
        *(uint2*)(ysm + 32768 + base) = make_uint2(lo01, lo23);
    }
    for (int idx = tid; idx < 128 * 16; idx += 512) {
        int p = idx >> 4, u4 = idx & 15;
        float4 sv = *(const float4*)&g_prefix[sbase + (size_t)p * 64 + u4 * 4];
        uint32_t lo01, lo23;
        uint32_t hi01 = pack2(sv.x, sv.y, lo01);
        uint32_t hi23 = pack2(sv.z, sv.w, lo23);
        uint32_t base = p * 128 + (((u4 >> 1) ^ (p & 7)) * 16) + (u4 & 1) * 8;
        *(uint2*)(ysm + 65536 + base) = make_uint2(hi01, hi23);
        *(uint2*)(ysm + 81920 + base) = make_uint2(lo01, lo23);
    }
    __syncthreads();
#pragma unroll
    for (int s = 0; s < 4; s++) {
        uint32_t afh[4][4], afl[4][4];
#pragma unroll
        for (int mt = 0; mt < 4; mt++) {
            int row = wr * 64 + mt * 16 + arow;
            uint32_t off = row * 128 + (((2 * s + ahalf) ^ (row & 7)) * 16);
            LDSM_X4(afh[mt][0], afh[mt][1], afh[mt][2], afh[mt][3], sb + off);
            LDSM_X4(afl[mt][0], afl[mt][1], afl[mt][2], afl[mt][3], sb + 32768 + off);
        }
#pragma unroll
        for (int ntp = 0; ntp < 2; ntp++) {
            int row = wc * 32 + ntp * 16 + brw2;
            uint32_t off = row * 128 + (((2 * s + bhf2) ^ (row & 7)) * 16);
            uint32_t bh0, bh1, bh2, bh3, bl0, bl1, bl2, bl3;
            LDSM_X4(bh0, bh1, bh2, bh3, sb + 65536 + off);
            LDSM_X4(bl0, bl1, bl2, bl3, sb + 81920 + off);
#pragma unroll
            for (int mt = 0; mt < 4; mt++) {
                mma16816bf(acc[mt][2*ntp+0], afh[mt], bh0, bh1);
                mma16816bf(acc[mt][2*ntp+0], afh[mt], bl0, bl1);
                mma16816bf(acc[mt][2*ntp+0], afl[mt], bh0, bh1);
                mma16816bf(acc[mt][2*ntp+1], afh[mt], bh2, bh3);
                mma16816bf(acc[mt][2*ntp+1], afh[mt], bl2, bl3);
                mma16816bf(acc[mt][2*ntp+1], afl[mt], bh2, bh3);
            }
        }
    }

#pragma unroll
    for (int mt = 0; mt < 4; mt++) {
        int i0 = wr * 64 + mt * 16 + (lane >> 2);
#pragma unroll
        for (int nt = 0; nt < 4; nt++) {
            int col = h * HEADDIM + wc * 32 + nt * 8 + (lane & 3) * 2;
            *(float2*)(g_y + (size_t)(brow + i0) * DINNER + col) =
                make_float2(acc[mt][nt][0], acc[mt][nt][1]);
            *(float2*)(g_y + (size_t)(brow + i0 + 8) * DINNER + col) =
                make_float2(acc[mt][nt][2], acc[mt][nt][3]);
        }
    }
}

// ---------------- gating (y * silu(z)) + LayerNorm; emits fp16 hi/lo ----------------
__global__ void __launch_bounds__(256) ln_kernel(const float* __restrict__ lnw, const float* __restrict__ lnb)
{
    int row = blockIdx.x;
    int tid = threadIdx.x;
    float g[16];
    float s = 0.f, s2 = 0.f;
#pragma unroll
    for (int q = 0; q < 16; q++) {
        int i = tid + q * 256;
        float y = g_y[(size_t)row * DINNER + i];
        float z = g_zxbcdt[(size_t)row * DINPROJ + i];
        float v = y * siluf(z);
        g[q] = v; s += v; s2 = fmaf(v, v, s2);
    }
    __shared__ float red[2][8];
#pragma unroll
    for (int off = 16; off > 0; off >>= 1) {
        s  += __shfl_xor_sync(0xffffffffu, s, off);
        s2 += __shfl_xor_sync(0xffffffffu, s2, off);
    }
    if ((tid & 31) == 0) { red[0][tid >> 5] = s; red[1][tid >> 5] = s2; }
    __syncthreads();
    if (tid == 0) {
        float a = 0.f, a2 = 0.f;
#pragma unroll
        for (int w = 0; w < 8; w++) { a += red[0][w]; a2 += red[1][w]; }
        red[0][0] = a; red[1][0] = a2;
    }
    __syncthreads();
    float mu  = red[0][0] * (1.f / DINNER);
    float var = red[1][0] * (1.f / DINNER) - mu * mu;
    float rstd = rsqrtf(var + LN_EPS);
#pragma unroll
    for (int q = 0; q < 16; q++) {
        int i = tid + q * 256;
        float v = (g[q] - mu) * rstd * lnw[i] + lnb[i];
        __half hh = __float2half_rn(v);
        g_ynh[(size_t)row * DINNER + i] = hh;
        g_ynl[(size_t)row * DINNER + i] = __float2half_rn(v - __half2float(hh));
    }
}

// ---------------- launch ----------------
extern "C" void kernel_launch(void* const* d_in, const int* in_sizes, int n_in,
                              void* d_out, int out_size)
{
    const float* u          = (const float*)d_in[0];
    const float* in_proj_w  = (const float*)d_in[1];
    const float* in_proj_b  = (const float*)d_in[2];
    const float* conv_w     = (const float*)d_in[3];
    const float* conv_b     = (const float*)d_in[4];
    const float* dt_bias    = (const float*)d_in[5];
    const float* A_log      = (const float*)d_in[6];
    const float* ln_w       = (const float*)d_in[7];
    const float* ln_b       = (const float*)d_in[8];
    const float* out_proj_w = (const float*)d_in[9];
    const float* out_proj_b = (const float*)d_in[10];
    float* out = (float*)d_out;

    float *zx, *gB, *gC, *gG;
    __half *uh, *ul, *w1h, *ynh, *ynl, *w2h;
    cudaGetSymbolAddress((void**)&zx,  g_zxbcdt);
    cudaGetSymbolAddress((void**)&gB,  g_Bv);
    cudaGetSymbolAddress((void**)&gC,  g_Cv);
    cudaGetSymbolAddress((void**)&gG,  g_G);
    cudaGetSymbolAddress((void**)&uh,  g_uh);
    cudaGetSymbolAddress((void**)&ul,  g_ul);
    cudaGetSymbolAddress((void**)&w1h, g_w1h);
    cudaGetSymbolAddress((void**)&ynh, g_ynh);
    cudaGetSymbolAddress((void**)&ynl, g_ynl);
    cudaGetSymbolAddress((void**)&w2h, g_w2h);

    cudaFuncSetAttribute(mma_gemm_nt, cudaFuncAttributeMaxDynamicSharedMemorySize, 3 * GST);
    cudaFuncSetAttribute(yfused_mma, cudaFuncAttributeMaxDynamicSharedMemorySize, YSMEM);

    // 0) fp32 -> fp16 conversions
    {
        long n1 = (long)NROWS * DMODEL;
        split_f16<<<(unsigned)((n1 + 255) / 256), 256>>>(u, uh, ul, n1);
        long n2 = (long)DINPROJ * DMODEL;
        round_f16<<<(unsigned)((n2 + 255) / 256), 256>>>(in_proj_w, w1h, n2);
        long n3 = (long)DMODEL * DINNER;
        round_f16<<<(unsigned)((n3 + 255) / 256), 256>>>(out_proj_w, w2h, n3);
    }

    // 1) in_proj: M=8192, N=8352, K=2048
    mma_gemm_nt<<<dim3((DINPROJ + 127) / 128, NROWS / 128), 512, 3 * GST>>>(
        uh, ul, w1h, in_proj_b, zx, DINPROJ, DMODEL);

    // 2) dt softplus + dA
    dt_kernel<<<(NROWS * NHEADS) / 256, 256>>>(dt_bias, A_log);

    // 3) causal conv + silu + split
    {
        long total = (long)NROWS * CONVDIM;
        conv_kernel<<<(unsigned)((total + 255) / 256), 256>>>(conv_w, conv_b);
    }

    // 4) per-chunk cumsum of dA
    cumsum_kernel<<<dim3(NCHUNK, NHEADS, BATCH), CHUNKT>>>();

    // 5) G = C @ B^T per (b,chunk)
    sgemm_nt<<<dim3(2, 2, BATCH * NCHUNK), 256>>>(
        gC, gB, nullptr, gG, CHUNKT, DSTATE,
        (long)CHUNKT * DSTATE, (long)CHUNKT * DSTATE, (long)CHUNKT * CHUNKT);

    // 6) chunk-local states
    states_kernel<<<dim3(NHEADS, NCHUNK, BATCH), 256>>>();

    // 7) inter-chunk scan
    scan_kernel<<<BATCH * NHEADS, 256>>>();

    // 8) fused Y on tensor cores
    yfused_mma<<<dim3(NHEADS, NCHUNK, BATCH), 512, YSMEM>>>();

    // 9) gate + layernorm (+ fp16 split of yn)
    ln_kernel<<<NROWS, 256>>>(ln_w, ln_b);

    // 10) out_proj: M=8192, N=2048, K=4096
    mma_gemm_nt<<<dim3(DMODEL / 128, NROWS / 128), 512, 3 * GST>>>(
        ynh, ynl, w2h, out_proj_b, out, DMODEL, DINNER);
}

// round 8
// speedup vs baseline: 3.5045x; 1.0344x over previous
#include <cuda_runtime.h>
#include <cuda_bf16.h>
#include <cuda_fp16.h>
#include <cstdint>
#include <math.h>

#define BATCH   2
#define SEQLEN  4096
#define DMODEL  2048
#define DINNER  4096
#define NHEADS  32
#define HEADDIM 128
#define DSTATE  64
#define NCHUNK  16
#define CHUNKT  256
#define CONVDIM 4224
#define DINPROJ 8352
#define NROWS   (BATCH*SEQLEN)
#define LN_EPS  1e-5f

// ---------------- scratch (device globals; no allocations allowed) ----------------
__device__ float g_zxbcdt[(size_t)NROWS * DINPROJ];
__device__ float g_xdt  [(size_t)NROWS * DINNER];
__device__ float g_Bv   [NROWS * DSTATE];
__device__ float g_Cv   [NROWS * DSTATE];
__device__ float g_dt   [NROWS * NHEADS];
__device__ float g_dA   [NROWS * NHEADS];
__device__ float g_Acum [BATCH * NHEADS * SEQLEN];
__device__ float g_G    [(size_t)BATCH * NCHUNK * CHUNKT * CHUNKT];
__device__ float g_states[(size_t)BATCH * NCHUNK * NHEADS * HEADDIM * DSTATE];
__device__ float g_prefix[(size_t)BATCH * NCHUNK * NHEADS * HEADDIM * DSTATE];
__device__ float g_y    [(size_t)NROWS * DINNER];

// fp16 buffers (activations exact hi/lo, weights rounded)
__device__ __half g_uh [(size_t)NROWS * DMODEL];
__device__ __half g_ul [(size_t)NROWS * DMODEL];
__device__ __half g_w1h[(size_t)DINPROJ * DMODEL];
__device__ __half g_ynh[(size_t)NROWS * DINNER];
__device__ __half g_ynl[(size_t)NROWS * DINNER];
__device__ __half g_w2h[(size_t)DMODEL * DINNER];
__device__ __half g_xf16[(size_t)NROWS * DINNER];   // rounded fp16 of xdt

__device__ __forceinline__ float siluf(float x) { return x / (1.f + __expf(-x)); }

__device__ __forceinline__ uint32_t smem_u32(const void* p) {
    uint32_t a;
    asm("{ .reg .u64 t; cvta.to.shared.u64 t, %1; cvt.u32.u64 %0, t; }" : "=r"(a) : "l"(p));
    return a;
}

// pack two floats into fp16x2 hi; return hi, write lo (exact 2-term split)
__device__ __forceinline__ uint32_t pack2h(float a, float b, uint32_t& lo) {
    __half ha = __float2half_rn(a), hb = __float2half_rn(b);
    __half la = __float2half_rn(a - __half2float(ha));
    __half lb = __float2half_rn(b - __half2float(hb));
    lo = (uint32_t)__half_as_ushort(la) | ((uint32_t)__half_as_ushort(lb) << 16);
    return (uint32_t)__half_as_ushort(ha) | ((uint32_t)__half_as_ushort(hb) << 16);
}
__device__ __forceinline__ uint32_t rnd2h(float a, float b) {
    return (uint32_t)__half_as_ushort(__float2half_rn(a)) |
           ((uint32_t)__half_as_ushort(__float2half_rn(b)) << 16);
}

// ================= split kernels =================
__global__ void split_f16(const float* __restrict__ src,
                          __half* __restrict__ hi, __half* __restrict__ lo, long n)
{
    long i = (long)blockIdx.x * blockDim.x + threadIdx.x;
    if (i >= n) return;
    float x = src[i];
    __half h = __float2half_rn(x);
    hi[i] = h;
    lo[i] = __float2half_rn(x - __half2float(h));
}
__global__ void round_f16(const float* __restrict__ src, __half* __restrict__ dst, long n)
{
    long i = (long)blockIdx.x * blockDim.x + threadIdx.x;
    if (i >= n) return;
    dst[i] = __float2half_rn(src[i]);
}

// ================= tensor-core primitives =================
__device__ __forceinline__ void mma16816h(float* c, const uint32_t* a, uint32_t b0, uint32_t b1)
{
    asm volatile(
        "mma.sync.aligned.m16n8k16.row.col.f32.f16.f16.f32 "
        "{%0,%1,%2,%3}, {%4,%5,%6,%7}, {%8,%9}, {%0,%1,%2,%3};"
        : "+f"(c[0]), "+f"(c[1]), "+f"(c[2]), "+f"(c[3])
        : "r"(a[0]), "r"(a[1]), "r"(a[2]), "r"(a[3]), "r"(b0), "r"(b1));
}
#define LDSM_X4(r0, r1, r2, r3, addr) \
    asm volatile("ldmatrix.sync.aligned.m8n8.x4.shared.b16 {%0,%1,%2,%3}, [%4];" \
                 : "=r"(r0), "=r"(r1), "=r"(r2), "=r"(r3) : "r"(addr))
#define LDSM_X4_T(r0, r1, r2, r3, addr) \
    asm volatile("ldmatrix.sync.aligned.m8n8.x4.trans.shared.b16 {%0,%1,%2,%3}, [%4];" \
                 : "=r"(r0), "=r"(r1), "=r"(r2), "=r"(r3) : "r"(addr))
#define CP16(dst, src, sz) \
    asm volatile("cp.async.cg.shared.global [%0], [%1], 16, %2;" \
                 :: "r"(dst), "l"(src), "r"(sz))
#define CP_COMMIT() asm volatile("cp.async.commit_group;" ::: "memory")
#define CP_WAIT1()  asm volatile("cp.async.wait_group 1;" ::: "memory")
#define CP_WAIT0()  asm volatile("cp.async.wait_group 0;" ::: "memory")

// ================= fp16 2-MMA GEMM: C = (Ah+Al)*Bh^T + bias =================
// BM=128, BN=256, BK=64, 512 threads (16 warps, 32x64 warp tiles).
// 3-stage cp.async pipeline. A exact fp16 hi/lo (M mult of 128); B rounded fp16.
#define GST 65536
__global__ void __launch_bounds__(512, 1)
mma_gemm_nt(const __half* __restrict__ Ah, const __half* __restrict__ Al,
            const __half* __restrict__ Bh,
            const float* __restrict__ bias, float* __restrict__ C, int N, int K)
{
    extern __shared__ char smem[];
    const uint32_t sb = smem_u32(smem);
    const int tid = threadIdx.x, lane = tid & 31, wid = tid >> 5;
    const int wr = wid >> 2, wc = wid & 3;        // 4x4 warps, each 32(m) x 64(n)
    const int mbase = blockIdx.y * 128;
    const int nbase = blockIdx.x * 256;

    // A loader: 4 thr/row, 2 units; B loader: 2 thr/row, 4 units
    const int ra = tid >> 2, ua0 = (tid & 3) * 2;
    const int rb = tid >> 1, ub0 = (tid & 1) * 4;
    const bool bval = (nbase + rb) < N;
    const uint32_t bsz = bval ? 16u : 0u;
    const __half* gAh = Ah + (size_t)(mbase + ra) * K + ua0 * 8;
    const __half* gAl = Al + (size_t)(mbase + ra) * K + ua0 * 8;
    const __half* gBh = Bh + (size_t)(bval ? nbase + rb : 0) * K + ub0 * 8;
    const uint32_t dA0 = ra * 128 + (( ua0      ^ (ra & 7)) * 16);
    const uint32_t dA1 = ra * 128 + (((ua0 + 1) ^ (ra & 7)) * 16);
    uint32_t dB[4];
#pragma unroll
    for (int j = 0; j < 4; j++) dB[j] = rb * 128 + (((ub0 + j) ^ (rb & 7)) * 16);

    auto issue = [&](int st, int kt) {
        uint32_t s0 = sb + st * GST;
        CP16(s0 + dA0,         gAh + kt,     16);
        CP16(s0 + dA1,         gAh + kt + 8, 16);
        CP16(s0 + 16384 + dA0, gAl + kt,     16);
        CP16(s0 + 16384 + dA1, gAl + kt + 8, 16);
#pragma unroll
        for (int j = 0; j < 4; j++)
            CP16(s0 + 32768 + dB[j], gBh + kt + j * 8, bsz);
        CP_COMMIT();
    };

    float acc[2][8][4];
#pragma unroll
    for (int mt = 0; mt < 2; mt++)
#pragma unroll
        for (int nt = 0; nt < 8; nt++)
#pragma unroll
            for (int i = 0; i < 4; i++) acc[mt][nt][i] = 0.f;

    const int nk = K >> 6;
    issue(0, 0);
    issue(1, 64);

    const int g = lane >> 3, li = lane & 7;
    const int arow_lo = (g & 1) * 8 + li;
    const int ahalf   = g >> 1;
    const int brow_lo = (g >> 1) * 8 + li;
    const int bhalf   = g & 1;

    int stage = 0;
    for (int c = 0; c < nk; c++) {
        if (c + 1 < nk) CP_WAIT1(); else CP_WAIT0();
        __syncthreads();
        if (c + 2 < nk) {
            int st = stage + 2; if (st >= 3) st -= 3;
            issue(st, (c + 2) * 64);
        }
        const uint32_t s0 = sb + stage * GST;
#pragma unroll
        for (int s = 0; s < 4; s++) {
            uint32_t afh[2][4], afl[2][4];
#pragma unroll
            for (int mt = 0; mt < 2; mt++) {
                int row = wr * 32 + mt * 16 + arow_lo;
                uint32_t off = row * 128 + (((2 * s + ahalf) ^ (row & 7)) * 16);
                LDSM_X4(afh[mt][0], afh[mt][1], afh[mt][2], afh[mt][3], s0 + off);
                LDSM_X4(afl[mt][0], afl[mt][1], afl[mt][2], afl[mt][3], s0 + 16384 + off);
            }
#pragma unroll
            for (int ntp = 0; ntp < 4; ntp++) {
                int row = wc * 64 + ntp * 16 + brow_lo;
                uint32_t off = row * 128 + (((2 * s + bhalf) ^ (row & 7)) * 16);
                uint32_t b0, b1, b2, b3;
                LDSM_X4(b0, b1, b2, b3, s0 + 32768 + off);
#pragma unroll
                for (int mt = 0; mt < 2; mt++) {
                    mma16816h(acc[mt][2*ntp+0], afh[mt], b0, b1);
                    mma16816h(acc[mt][2*ntp+0], afl[mt], b0, b1);
                    mma16816h(acc[mt][2*ntp+1], afh[mt], b2, b3);
                    mma16816h(acc[mt][2*ntp+1], afl[mt], b2, b3);
                }
            }
        }
        stage++; if (stage >= 3) stage -= 3;
    }

#pragma unroll
    for (int mt = 0; mt < 2; mt++) {
        int r0 = mbase + wr * 32 + mt * 16 + (lane >> 2);
#pragma unroll
        for (int nt = 0; nt < 8; nt++) {
            int col = nbase + wc * 64 + nt * 8 + (lane & 3) * 2;
            if (col < N) {
                float b0 = bias ? bias[col] : 0.f;
                float b1 = bias ? bias[col + 1] : 0.f;
                float2 v0 = make_float2(acc[mt][nt][0] + b0, acc[mt][nt][1] + b1);
                float2 v1 = make_float2(acc[mt][nt][2] + b0, acc[mt][nt][3] + b1);
                *(float2*)(C + (size_t)r0 * N + col)       = v0;
                *(float2*)(C + (size_t)(r0 + 8) * N + col) = v1;
            }
        }
    }
}

// ---------------- small fp32 NT GEMM (G = C @ B^T) ----------------
__global__ void __launch_bounds__(256)
sgemm_nt(const float* __restrict__ A, const float* __restrict__ B,
         const float* __restrict__ bias, float* __restrict__ C,
         int N, int K, long sA, long sB, long sC)
{
    __shared__ float As[16][128];
    __shared__ float Bs[16][128];
    const int tid  = threadIdx.x;
    const int tcol = tid & 15;
    const int trow = tid >> 4;
    const float* Ab = A + (size_t)blockIdx.z * sA + (size_t)blockIdx.y * 128 * K;
    const float* Bb = B + (size_t)blockIdx.z * sB + (size_t)blockIdx.x * 128 * K;
    const int nbase = blockIdx.x * 128;

    float acc[8][8];
#pragma unroll
    for (int m = 0; m < 8; m++)
#pragma unroll
        for (int n = 0; n < 8; n++) acc[m][n] = 0.f;

    const int lrow = tid >> 2;
    const int lcol = (tid & 3) * 4;

    for (int kt = 0; kt < K; kt += 16) {
#pragma unroll
        for (int it = 0; it < 2; it++) {
            int r = lrow + it * 64;
            float4 va = *(const float4*)(Ab + (size_t)r * K + kt + lcol);
            As[lcol+0][r] = va.x; As[lcol+1][r] = va.y;
            As[lcol+2][r] = va.z; As[lcol+3][r] = va.w;
            float4 vb;
            if (nbase + r < N) vb = *(const float4*)(Bb + (size_t)r * K + kt + lcol);
            else               vb = make_float4(0.f, 0.f, 0.f, 0.f);
            Bs[lcol+0][r] = vb.x; Bs[lcol+1][r] = vb.y;
            Bs[lcol+2][r] = vb.z; Bs[lcol+3][r] = vb.w;
        }
        __syncthreads();
#pragma unroll
        for (int k = 0; k < 16; k++) {
            float ra[8], rb[8];
#pragma unroll
            for (int m = 0; m < 8; m++) ra[m] = As[k][trow * 8 + m];
#pragma unroll
            for (int n = 0; n < 8; n++) rb[n] = Bs[k][tcol * 8 + n];
#pragma unroll
            for (int m = 0; m < 8; m++)
#pragma unroll
                for (int n = 0; n < 8; n++) acc[m][n] = fmaf(ra[m], rb[n], acc[m][n]);
        }
        __syncthreads();
    }
#pragma unroll
    for (int m = 0; m < 8; m++) {
        int row = blockIdx.y * 128 + trow * 8 + m;
#pragma unroll
        for (int n = 0; n < 8; n++) {
            int col = nbase + tcol * 8 + n;
            if (col < N) {
                float bv = bias ? bias[col] : 0.f;
                C[(size_t)blockIdx.z * sC + (size_t)row * N + col] = acc[m][n] + bv;
            }
        }
    }
}

// ---------------- dt: softplus(dt_raw + bias), dA = -exp(A_log)*dt ----------------
__global__ void dt_kernel(const float* __restrict__ dt_bias, const float* __restrict__ A_log)
{
    int idx = blockIdx.x * blockDim.x + threadIdx.x;
    if (idx >= NROWS * NHEADS) return;
    int h = idx & (NHEADS - 1);
    int r = idx >> 5;
    float v = g_zxbcdt[(size_t)r * DINPROJ + DINNER + CONVDIM + h] + dt_bias[h];
    float dt = (v > 20.f) ? v : log1pf(__expf(v));
    g_dt[idx] = dt;
    g_dA[idx] = -__expf(A_log[h]) * dt;
}

// ---------------- causal depthwise conv + SiLU; split x*dt / B / C ----------------
__global__ void conv_kernel(const float* __restrict__ w, const float* __restrict__ cb)
{
    long idx = (long)blockIdx.x * blockDim.x + threadIdx.x;
    if (idx >= (long)NROWS * CONVDIM) return;
    int c = (int)(idx % CONVDIM);
    int r = (int)(idx / CONVDIM);
    int l = r & (SEQLEN - 1);
    float acc = cb[c];
#pragma unroll
    for (int k = 0; k < 4; k++) {
        int lp = l - 3 + k;
        if (lp >= 0)
            acc = fmaf(w[c * 4 + k], g_zxbcdt[(size_t)(r - 3 + k) * DINPROJ + DINNER + c], acc);
    }
    float out = siluf(acc);
    if (c < DINNER) {
        float v = out * g_dt[r * NHEADS + (c >> 7)];
        size_t o = (size_t)r * DINNER + c;
        g_xdt[o] = v;
        g_xf16[o] = __float2half_rn(v);
    } else if (c < DINNER + DSTATE) {
        g_Bv[r * DSTATE + (c - DINNER)] = out;
    } else {
        g_Cv[r * DSTATE + (c - DINNER - DSTATE)] = out;
    }
}

// ---------------- per-chunk inclusive cumsum of dA ----------------
__global__ void cumsum_kernel()
{
    int c = blockIdx.x, h = blockIdx.y, b = blockIdx.z;
    int t = threadIdx.x;
    __shared__ float s[CHUNKT];
    int row = b * SEQLEN + c * CHUNKT + t;
    s[t] = g_dA[row * NHEADS + h];
    __syncthreads();
#pragma unroll
    for (int off = 1; off < CHUNKT; off <<= 1) {
        float x = (t >= off) ? s[t - off] : 0.f;
        __syncthreads();
        s[t] += x;
        __syncthreads();
    }
    g_Acum[(b * NHEADS + h) * SEQLEN + c * CHUNKT + t] = s[t];
}

// ---------------- chunk-local states (FFMA) ----------------
__global__ void __launch_bounds__(256) states_kernel()
{
    int h = blockIdx.x, c = blockIdx.y, b = blockIdx.z;
    __shared__ float Xs[16][128];
    __shared__ float Bsc[16][64];
    __shared__ float Ac[CHUNKT];
    int tid = threadIdx.x;
    Ac[tid] = g_Acum[(b * NHEADS + h) * SEQLEN + c * CHUNKT + tid];
    __syncthreads();
    float Atot = Ac[CHUNKT - 1];
    int brow = b * SEQLEN + c * CHUNKT;
    int tp = tid >> 3, tn = tid & 7;
    float acc[4][8];
#pragma unroll
    for (int m = 0; m < 4; m++)
#pragma unroll
        for (int n = 0; n < 8; n++) acc[m][n] = 0.f;

    for (int lt = 0; lt < CHUNKT; lt += 16) {
#pragma unroll
        for (int q = 0; q < 8; q++) {
            int idx = tid + q * 256;
            int ll = idx >> 7, p = idx & 127;
            Xs[ll][p] = g_xdt[(size_t)(brow + lt + ll) * DINNER + h * HEADDIM + p];
        }
#pragma unroll
        for (int q = 0; q < 4; q++) {
            int idx = tid + q * 256;
            int ll = idx >> 6, n = idx & 63;
            Bsc[ll][n] = g_Bv[(brow + lt + ll) * DSTATE + n] * __expf(Atot - Ac[lt + ll]);
        }
        __syncthreads();
#pragma unroll
        for (int l = 0; l < 16; l++) {
            float ra[4], rb[8];
#pragma unroll
            for (int m = 0; m < 4; m++) ra[m] = Xs[l][tp * 4 + m];
#pragma unroll
            for (int n = 0; n < 8; n++) rb[n] = Bsc[l][tn * 8 + n];
#pragma unroll
            for (int m = 0; m < 4; m++)
#pragma unroll
                for (int n = 0; n < 8; n++) acc[m][n] = fmaf(ra[m], rb[n], acc[m][n]);
        }
        __syncthreads();
    }
    size_t base = ((size_t)((b * NCHUNK + c) * NHEADS + h)) * HEADDIM * DSTATE;
#pragma unroll
    for (int m = 0; m < 4; m++)
#pragma unroll
        for (int n = 0; n < 8; n++)
            g_states[base + (size_t)(tp * 4 + m) * DSTATE + tn * 8 + n] = acc[m][n];
}

// ---------------- inter-chunk state scan ----------------
__global__ void scan_kernel()
{
    int bh = blockIdx.x;
    int b = bh >> 5, h = bh & 31;
    int t = threadIdx.x;
    float S[32];
#pragma unroll
    for (int i = 0; i < 32; i++) S[i] = 0.f;
    for (int c = 0; c < NCHUNK; c++) {
        size_t base = ((size_t)((b * NCHUNK + c) * NHEADS + h)) * (HEADDIM * DSTATE) + (size_t)t * 32;
#pragma unroll
        for (int i = 0; i < 32; i++) g_prefix[base + i] = S[i];
        float f = __expf(g_Acum[(b * NHEADS + h) * SEQLEN + c * CHUNKT + CHUNKT - 1]);
#pragma unroll
        for (int i = 0; i < 32; i++) S[i] = S[i] * f + g_states[base + i];
    }
}

// ================= fused Y on tensor cores (fp16 2-term) =================
// Block (h,c,b): Y[256 i][128 p] = W @ X + Ce @ S^T
//   W (and Ce) exact fp16 hi/lo (A operand); X (and S) rounded fp16 (B operand).
// smem: WH 0 (32K) | WL 32768 (32K) | X/S 65536 (16K) | Ac 81920 | eAc 82944
#define YSMEM 84992
__global__ void __launch_bounds__(512, 1) yfused_mma()
{
    extern __shared__ char ysm[];
    const uint32_t sb = smem_u32(ysm);
    float* Ac  = (float*)(ysm + 81920);
    float* eAc = (float*)(ysm + 82944);
    const int h = blockIdx.x, c = blockIdx.y, b = blockIdx.z;
    const int tid = threadIdx.x, lane = tid & 31, wid = tid >> 5;
    const int wr = wid >> 2, wc = wid & 3;     // warp tile 64(i) x 32(p)
    const int brow = b * SEQLEN + c * CHUNKT;
    const size_t gbase = (size_t)(b * NCHUNK + c) * CHUNKT * CHUNKT;
    const size_t sbase = ((size_t)((b * NCHUNK + c) * NHEADS + h)) * (HEADDIM * DSTATE);

    if (tid < CHUNKT) {
        float a = g_Acum[(b * NHEADS + h) * SEQLEN + c * CHUNKT + tid];
        Ac[tid] = a;
        eAc[tid] = __expf(a);
    }

    float acc[4][4][4];
#pragma unroll
    for (int mt = 0; mt < 4; mt++)
#pragma unroll
        for (int nt = 0; nt < 4; nt++)
#pragma unroll
            for (int i = 0; i < 4; i++) acc[mt][nt][i] = 0.f;

    const int g = lane >> 3, li = lane & 7;
    const int arow  = (g & 1) * 8 + li;
    const int ahalf = g >> 1;
    const int bkt   = (g & 1) * 8 + li;   // B trans: k-row-lo
    const int bnt   = (g >> 1) * 8;       // B trans: n-col-half
    const int brw2  = (g >> 1) * 8 + li;  // B non-trans: n-row-lo
    const int bhf2  = g & 1;

    // ---- part 1: W @ X over 4 j-tiles of 64 ----
    for (int jt = 0; jt < CHUNKT; jt += 64) {
        __syncthreads();
        // stage W (256 x 64) fp16 hi/lo
        for (int idx = tid; idx < 256 * 16; idx += 512) {
            int i = idx >> 4, u4 = idx & 15;
            float4 gv = *(const float4*)&g_G[gbase + (size_t)i * 256 + jt + u4 * 4];
            float ai = Ac[i];
            int j0 = jt + u4 * 4;
            float v0 = (j0 + 0 <= i) ? __expf(ai - Ac[j0 + 0]) * gv.x : 0.f;
            float v1 = (j0 + 1 <= i) ? __expf(ai - Ac[j0 + 1]) * gv.y : 0.f;
            float v2 = (j0 + 2 <= i) ? __expf(ai - Ac[j0 + 2]) * gv.z : 0.f;
            float v3 = (j0 + 3 <= i) ? __expf(ai - Ac[j0 + 3]) * gv.w : 0.f;
            uint32_t lo01, lo23;
            uint32_t hi01 = pack2h(v0, v1, lo01);
            uint32_t hi23 = pack2h(v2, v3, lo23);
            uint32_t base = i * 128 + (((u4 >> 1) ^ (i & 7)) * 16) + (u4 & 1) * 8;
            *(uint2*)(ysm + base)         = make_uint2(hi01, hi23);
            *(uint2*)(ysm + 32768 + base) = make_uint2(lo01, lo23);
        }
        // stage X rows jt..jt+63 ([j][p] fp16, 256B rows)
        for (int idx = tid; idx < 64 * 16; idx += 512) {
            int l = idx >> 4, u = idx & 15;
            size_t src = (size_t)(brow + jt + l) * DINNER + h * HEADDIM + u * 8;
            uint32_t dst = l * 256 + ((u ^ (l & 7)) * 16);
            *(uint4*)(ysm + 65536 + dst) = *(const uint4*)(g_xf16 + src);
        }
        __syncthreads();
        if (wr * 64 + 63 >= jt) {
#pragma unroll
            for (int s = 0; s < 4; s++) {
                uint32_t afh[4][4], afl[4][4];
#pragma unroll
                for (int mt = 0; mt < 4; mt++) {
                    int row = wr * 64 + mt * 16 + arow;
                    uint32_t off = row * 128 + (((2 * s + ahalf) ^ (row & 7)) * 16);
                    LDSM_X4(afh[mt][0], afh[mt][1], afh[mt][2], afh[mt][3], sb + off);
                    LDSM_X4(afl[mt][0], afl[mt][1], afl[mt][2], afl[mt][3], sb + 32768 + off);
                }
#pragma unroll
                for (int ntp = 0; ntp < 2; ntp++) {
                    int krow = s * 16 + bkt;
                    int p = wc * 32 + ntp * 16 + bnt;
                    uint32_t off = krow * 256 + (((p >> 3) ^ (krow & 7)) * 16);
                    uint32_t b0, b1, b2, b3;
                    LDSM_X4_T(b0, b1, b2, b3, sb + 65536 + off);
#pragma unroll
                    for (int mt = 0; mt < 4; mt++) {
                        mma16816h(acc[mt][2*ntp+0], afh[mt], b0, b1);
                        mma16816h(acc[mt][2*ntp+0], afl[mt], b0, b1);
                        mma16816h(acc[mt][2*ntp+1], afh[mt], b2, b3);
                        mma16816h(acc[mt][2*ntp+1], afl[mt], b2, b3);
                    }
                }
            }
        }
    }

    // ---- part 2: Ce @ S^T (K = 64) ----
    __syncthreads();
    for (int idx = tid; idx < 256 * 16; idx += 512) {
        int i = idx >> 4, u4 = idx & 15;
        float4 cv = *(const float4*)&g_Cv[(size_t)(brow + i) * 64 + u4 * 4];
        float e = eAc[i];
        uint32_t lo01, lo23;
        uint32_t hi01 = pack2h(cv.x * e, cv.y * e, lo01);
        uint32_t hi23 = pack2h(cv.z * e, cv.w * e, lo23);
        uint32_t base = i * 128 + (((u4 >> 1) ^ (i & 7)) * 16) + (u4 & 1) * 8;
        *(uint2*)(ysm + base)         = make_uint2(hi01, hi23);
        *(uint2*)(ysm + 32768 + base) = make_uint2(lo01, lo23);
    }
    for (int idx = tid; idx < 128 * 16; idx += 512) {
        int p = idx >> 4, u4 = idx & 15;
        float4 sv = *(const float4*)&g_prefix[sbase + (size_t)p * 64 + u4 * 4];
        uint32_t h01 = rnd2h(sv.x, sv.y);
        uint32_t h23 = rnd2h(sv.z, sv.w);
        uint32_t base = p * 128 + (((u4 >> 1) ^ (p & 7)) * 16) + (u4 & 1) * 8;
        *(uint2*)(ysm + 65536 + base) = make_uint2(h01, h23);
    }
    __syncthreads();
#pragma unroll
    for (int s = 0; s < 4; s++) {
        uint32_t afh[4][4], afl[4][4];
#pragma unroll
        for (int mt = 0; mt < 4; mt++) {
            int row = wr * 64 + mt * 16 + arow;
            uint32_t off = row * 128 + (((2 * s + ahalf) ^ (row & 7)) * 16);
            LDSM_X4(afh[mt][0], afh[mt][1], afh[mt][2], afh[mt][3], sb + off);
            LDSM_X4(afl[mt][0], afl[mt][1], afl[mt][2], afl[mt][3], sb + 32768 + off);
        }
#pragma unroll
        for (int ntp = 0; ntp < 2; ntp++) {
            int row = wc * 32 + ntp * 16 + brw2;
            uint32_t off = row * 128 + (((2 * s + bhf2) ^ (row & 7)) * 16);
            uint32_t b0, b1, b2, b3;
            LDSM_X4(b0, b1, b2, b3, sb + 65536 + off);
#pragma unroll
            for (int mt = 0; mt < 4; mt++) {
                mma16816h(acc[mt][2*ntp+0], afh[mt], b0, b1);
                mma16816h(acc[mt][2*ntp+0], afl[mt], b0, b1);
                mma16816h(acc[mt][2*ntp+1], afh[mt], b2, b3);
                mma16816h(acc[mt][2*ntp+1], afl[mt], b2, b3);
            }
        }
    }

    // ---- epilogue ----
#pragma unroll
    for (int mt = 0; mt < 4; mt++) {
        int i0 = wr * 64 + mt * 16 + (lane >> 2);
#pragma unroll
        for (int nt = 0; nt < 4; nt++) {
            int col = h * HEADDIM + wc * 32 + nt * 8 + (lane & 3) * 2;
            *(float2*)(g_y + (size_t)(brow + i0) * DINNER + col) =
                make_float2(acc[mt][nt][0], acc[mt][nt][1]);
            *(float2*)(g_y + (size_t)(brow + i0 + 8) * DINNER + col) =
                make_float2(acc[mt][nt][2], acc[mt][nt][3]);
        }
    }
}

// ---------------- gating (y * silu(z)) + LayerNorm; emits fp16 hi/lo ----------------
__global__ void __launch_bounds__(256) ln_kernel(const float* __restrict__ lnw, const float* __restrict__ lnb)
{
    int row = blockIdx.x;
    int tid = threadIdx.x;
    float g[16];
    float s = 0.f, s2 = 0.f;
#pragma unroll
    for (int q = 0; q < 16; q++) {
        int i = tid + q * 256;
        float y = g_y[(size_t)row * DINNER + i];
        float z = g_zxbcdt[(size_t)row * DINPROJ + i];
        float v = y * siluf(z);
        g[q] = v; s += v; s2 = fmaf(v, v, s2);
    }
    __shared__ float red[2][8];
#pragma unroll
    for (int off = 16; off > 0; off >>= 1) {
        s  += __shfl_xor_sync(0xffffffffu, s, off);
        s2 += __shfl_xor_sync(0xffffffffu, s2, off);
    }
    if ((tid & 31) == 0) { red[0][tid >> 5] = s; red[1][tid >> 5] = s2; }
    __syncthreads();
    if (tid == 0) {
        float a = 0.f, a2 = 0.f;
#pragma unroll
        for (int w = 0; w < 8; w++) { a += red[0][w]; a2 += red[1][w]; }
        red[0][0] = a; red[1][0] = a2;
    }
    __syncthreads();
    float mu  = red[0][0] * (1.f / DINNER);
    float var = red[1][0] * (1.f / DINNER) - mu * mu;
    float rstd = rsqrtf(var + LN_EPS);
#pragma unroll
    for (int q = 0; q < 16; q++) {
        int i = tid + q * 256;
        float v = (g[q] - mu) * rstd * lnw[i] + lnb[i];
        __half hh = __float2half_rn(v);
        g_ynh[(size_t)row * DINNER + i] = hh;
        g_ynl[(size_t)row * DINNER + i] = __float2half_rn(v - __half2float(hh));
    }
}

// ---------------- launch ----------------
extern "C" void kernel_launch(void* const* d_in, const int* in_sizes, int n_in,
                              void* d_out, int out_size)
{
    const float* u          = (const float*)d_in[0];
    const float* in_proj_w  = (const float*)d_in[1];
    const float* in_proj_b  = (const float*)d_in[2];
    const float* conv_w     = (const float*)d_in[3];
    const float* conv_b     = (const float*)d_in[4];
    const float* dt_bias    = (const float*)d_in[5];
    const float* A_log      = (const float*)d_in[6];
    const float* ln_w       = (const float*)d_in[7];
    const float* ln_b       = (const float*)d_in[8];
    const float* out_proj_w = (const float*)d_in[9];
    const float* out_proj_b = (const float*)d_in[10];
    float* out = (float*)d_out;

    float *zx, *gB, *gC, *gG;
    __half *uh, *ul, *w1h, *ynh, *ynl, *w2h;
    cudaGetSymbolAddress((void**)&zx,  g_zxbcdt);
    cudaGetSymbolAddress((void**)&gB,  g_Bv);
    cudaGetSymbolAddress((void**)&gC,  g_Cv);
    cudaGetSymbolAddress((void**)&gG,  g_G);
    cudaGetSymbolAddress((void**)&uh,  g_uh);
    cudaGetSymbolAddress((void**)&ul,  g_ul);
    cudaGetSymbolAddress((void**)&w1h, g_w1h);
    cudaGetSymbolAddress((void**)&ynh, g_ynh);
    cudaGetSymbolAddress((void**)&ynl, g_ynl);
    cudaGetSymbolAddress((void**)&w2h, g_w2h);

    cudaFuncSetAttribute(mma_gemm_nt, cudaFuncAttributeMaxDynamicSharedMemorySize, 3 * GST);
    cudaFuncSetAttribute(yfused_mma, cudaFuncAttributeMaxDynamicSharedMemorySize, YSMEM);

    // 0) fp32 -> fp16 conversions
    {
        long n1 = (long)NROWS * DMODEL;
        split_f16<<<(unsigned)((n1 + 255) / 256), 256>>>(u, uh, ul, n1);
        long n2 = (long)DINPROJ * DMODEL;
        round_f16<<<(unsigned)((n2 + 255) / 256), 256>>>(in_proj_w, w1h, n2);
        long n3 = (long)DMODEL * DINNER;
        round_f16<<<(unsigned)((n3 + 255) / 256), 256>>>(out_proj_w, w2h, n3);
    }

    // 1) in_proj: M=8192, N=8352, K=2048
    mma_gemm_nt<<<dim3((DINPROJ + 255) / 256, NROWS / 128), 512, 3 * GST>>>(
        uh, ul, w1h, in_proj_b, zx, DINPROJ, DMODEL);

    // 2) dt softplus + dA
    dt_kernel<<<(NROWS * NHEADS) / 256, 256>>>(dt_bias, A_log);

    // 3) causal conv + silu + split
    {
        long total = (long)NROWS * CONVDIM;
        conv_kernel<<<(unsigned)((total + 255) / 256), 256>>>(conv_w, conv_b);
    }

    // 4) per-chunk cumsum of dA
    cumsum_kernel<<<dim3(NCHUNK, NHEADS, BATCH), CHUNKT>>>();

    // 5) G = C @ B^T per (b,chunk)
    sgemm_nt<<<dim3(2, 2, BATCH * NCHUNK), 256>>>(
        gC, gB, nullptr, gG, CHUNKT, DSTATE,
        (long)CHUNKT * DSTATE, (long)CHUNKT * DSTATE, (long)CHUNKT * CHUNKT);

    // 6) chunk-local states
    states_kernel<<<dim3(NHEADS, NCHUNK, BATCH), 256>>>();

    // 7) inter-chunk scan
    scan_kernel<<<BATCH * NHEADS, 256>>>();

    // 8) fused Y on tensor cores
    yfused_mma<<<dim3(NHEADS, NCHUNK, BATCH), 512, YSMEM>>>();

    // 9) gate + layernorm (+ fp16 split of yn)
    ln_kernel<<<NROWS, 256>>>(ln_w, ln_b);

    // 10) out_proj: M=8192, N=2048, K=4096
    mma_gemm_nt<<<dim3(DMODEL / 256, NROWS / 128), 512, 3 * GST>>>(
        ynh, ynl, w2h, out_proj_b, out, DMODEL, DINNER);
}